// round 2
// baseline (speedup 1.0000x reference)
#include <cuda_runtime.h>
#include <math.h>
#include <stdint.h>

// ---------------------------------------------------------------------------
// Problem constants
// ---------------------------------------------------------------------------
#define NP 4096
#define KN 80
#define DM 128
#define FFD 512

static constexpr size_t SZ_ND  = (size_t)NP * DM;            // 524288
static constexpr size_t SZ_A1  = (size_t)NP * 8192;          // per-stream A
static constexpr size_t OFF_A    = 0;
static constexpr size_t OFF_S    = OFF_A + 2 * SZ_A1;
static constexpr size_t SZ_S     = (size_t)4 * NP * NP;
static constexpr size_t OFF_PE   = OFF_S + SZ_S;
static constexpr size_t OFF_CONV = OFF_PE + SZ_ND;
static constexpr size_t OFF_F0   = OFF_CONV + SZ_ND;         // 2 buffers
static constexpr size_t OFF_H    = OFF_F0 + 2 * SZ_ND;
static constexpr size_t OFF_Q    = OFF_H + SZ_ND;
static constexpr size_t OFF_K    = OFF_Q + SZ_ND;
static constexpr size_t OFF_V    = OFF_K + SZ_ND;
static constexpr size_t OFF_O    = OFF_V + SZ_ND;
static constexpr size_t OFF_T    = OFF_O + SZ_ND;
static constexpr size_t OFF_F1   = OFF_T + SZ_ND;
static constexpr size_t OFF_FF   = OFF_F1 + SZ_ND;           // NP*512
static constexpr size_t OFF_OUT  = OFF_FF + (size_t)NP * FFD; // 2 buffers
static constexpr size_t OFF_ST   = OFF_OUT + 2 * SZ_ND;      // stats (512)
static constexpr size_t SCRATCH_TOTAL = OFF_ST + 512;

__device__ float g_scratch[SCRATCH_TOTAL];

// ---------------------------------------------------------------------------
// pos[:,0] mean / std(ddof=1)  -> st[0]=mean, st[1]=1/(std+1e-8)
// ---------------------------------------------------------------------------
__global__ void k_pos_stats(const float* __restrict__ pos, float* __restrict__ st) {
    __shared__ double ss[256], sq[256];
    int t = threadIdx.x;
    double a = 0.0, b = 0.0;
    for (int i = t; i < NP; i += 256) {
        double v = (double)pos[3 * i];
        a += v; b += v * v;
    }
    ss[t] = a; sq[t] = b;
    __syncthreads();
    for (int o = 128; o > 0; o >>= 1) {
        if (t < o) { ss[t] += ss[t + o]; sq[t] += sq[t + o]; }
        __syncthreads();
    }
    if (t == 0) {
        double mean = ss[0] / NP;
        double var  = (sq[0] - ss[0] * ss[0] / NP) / (NP - 1);
        double sd   = sqrt(var);
        st[0] = (float)mean;
        st[1] = (float)(1.0 / (sd + 1e-8));
    }
}

// ---------------------------------------------------------------------------
// sinusoidal positional encoding from standardized pos[:,0]
// ---------------------------------------------------------------------------
__global__ void k_posenc(const float* __restrict__ pos, const float* __restrict__ st,
                         float* __restrict__ pe) {
    int n = blockIdx.x;
    int j = threadIdx.x;               // 0..63
    float px  = (pos[3 * n] - st[0]) * st[1];
    float dv  = expf((float)(2 * j) * (-9.210340371976184f / 128.0f)); // -ln(1e4)/D
    float ang = px * dv;
    float s, c;
    sincosf(ang, &s, &c);
    pe[(size_t)n * DM + 2 * j]     = s;
    pe[(size_t)n * DM + 2 * j + 1] = c;
}

// ---------------------------------------------------------------------------
// Build A[n, 64, 128]: scatter win * trilinear weights * feat[nbr].
// One block per point, 128 threads (one per channel). grid.y picks x vs y.
// mask is derived as (idx != n).
// ---------------------------------------------------------------------------
__global__ void k_buildA(const float* __restrict__ fx, const float* __restrict__ fy,
                         const float* __restrict__ pos, const int* __restrict__ idx,
                         float* __restrict__ Abuf) {
    __shared__ float sA[64 * 128];     // 32 KB, column-private per thread
    int n = blockIdx.x;
    const float* feat = blockIdx.y ? fy : fx;
    float* Aout = Abuf + (size_t)blockIdx.y * SZ_A1 + (size_t)n * 8192;
    int c = threadIdx.x;

#pragma unroll
    for (int g = 0; g < 64; ++g) sA[g * 128 + c] = 0.0f;

    const float RAD  = 0.22499999403953552f * 0.5f;  // float32(1.5*6*0.025)/2
    const float invR = 1.0f / RAD;
    float p0 = pos[3 * n], p1 = pos[3 * n + 1], p2 = pos[3 * n + 2];

    for (int k = 0; k < KN; k++) {
        int nb = idx[n * KN + k];
        if (nb == n) continue;                       // mask == (idx != n)
        float rx = (pos[3 * nb]     - p0) * invR;
        float ry = (pos[3 * nb + 1] - p1) * invR;
        float rz = (pos[3 * nb + 2] - p2) * invR;
        float r2 = rx * rx + ry * ry + rz * rz;
        float w1 = 1.0f - r2;
        float win = fminf(fmaxf(w1 * w1 * w1, 0.0f), 1.0f);
        if (win <= 0.0f) continue;
        float nrm  = sqrtf(fmaxf(r2, 1e-12f));
        float linf = fmaxf(fmaxf(fabsf(rx), fabsf(ry)), fabsf(rz));
        linf = fmaxf(linf, 1e-9f);
        float sc = nrm / linf;
        float gx = fminf(fmaxf((rx * sc + 1.0f) * 1.5f, 0.0f), 3.0f);
        float gy = fminf(fmaxf((ry * sc + 1.0f) * 1.5f, 0.0f), 3.0f);
        float gz = fminf(fmaxf((rz * sc + 1.0f) * 1.5f, 0.0f), 3.0f);
        float f0x = fminf(floorf(gx), 2.0f);
        float f0y = fminf(floorf(gy), 2.0f);
        float f0z = fminf(floorf(gz), 2.0f);
        float tx = gx - f0x, ty = gy - f0y, tz = gz - f0z;
        int ix = (int)f0x, iy = (int)f0y, iz = (int)f0z;
        int base = ix * 16 + iy * 4 + iz;
        float f = feat[(size_t)nb * DM + c];
        float wx[2] = {1.0f - tx, tx};
        float wy[2] = {1.0f - ty, ty};
        float wz[2] = {1.0f - tz, tz};
#pragma unroll
        for (int dx = 0; dx < 2; dx++)
#pragma unroll
            for (int dy = 0; dy < 2; dy++)
#pragma unroll
                for (int dz = 0; dz < 2; dz++) {
                    int cell = base + dx * 16 + dy * 4 + dz;
                    sA[cell * 128 + c] += win * wx[dx] * wy[dy] * wz[dz] * f;
                }
    }
#pragma unroll 8
    for (int g = 0; g < 64; ++g)
        Aout[(size_t)g * 128 + c] = sA[g * 128 + c];
}

// ---------------------------------------------------------------------------
// Generic tiled fp32 GEMM: C = act(alpha * A @ op(B) + bias)
//   A: M x K  row-major (lda),  TRANSB=0: B is K x N (ldb); TRANSB=1: B is N x K
//   64x64 block tile, BK=16, 256 threads, 4x4 micro-tile. batched via blockIdx.z.
//   M must be a multiple of 64, K of 16, N of 4 (cols guarded vs BN=64).
// ---------------------------------------------------------------------------
template <int TRANSB, int ACT>
__global__ __launch_bounds__(256)
void k_gemm(const float* __restrict__ A, int lda, long long strideA,
            const float* __restrict__ B, int ldb, long long strideB,
            float* __restrict__ C, int ldc, long long strideC,
            const float* __restrict__ bias,
            int M, int N, int K, float alpha) {
    __shared__ float shA[16][64];
    __shared__ float shB[16][64];
    A += (size_t)blockIdx.z * strideA;
    B += (size_t)blockIdx.z * strideB;
    C += (size_t)blockIdx.z * strideC;

    int n0 = blockIdx.x * 64;
    int m0 = blockIdx.y * 64;
    int t  = threadIdx.x;
    int tx = t & 15, ty = t >> 4;

    float acc[4][4];
#pragma unroll
    for (int i = 0; i < 4; i++)
#pragma unroll
        for (int j = 0; j < 4; j++) acc[i][j] = 0.0f;

    int ar  = t >> 2;
    int akq = (t & 3) * 4;

    for (int k0 = 0; k0 < K; k0 += 16) {
        // A tile (transposed into smem)
        float4 av = *reinterpret_cast<const float4*>(
            A + (size_t)(m0 + ar) * lda + k0 + akq);
        shA[akq + 0][ar] = av.x; shA[akq + 1][ar] = av.y;
        shA[akq + 2][ar] = av.z; shA[akq + 3][ar] = av.w;

        if (TRANSB == 0) {
            int kk = t >> 4, nq = (t & 15) * 4;
            float4 bv = make_float4(0.f, 0.f, 0.f, 0.f);
            if (n0 + nq < N)
                bv = *reinterpret_cast<const float4*>(
                    B + (size_t)(k0 + kk) * ldb + n0 + nq);
            *reinterpret_cast<float4*>(&shB[kk][nq]) = bv;
        } else {
            int nn = t >> 2, kq = (t & 3) * 4;
            float4 bv = make_float4(0.f, 0.f, 0.f, 0.f);
            if (n0 + nn < N)
                bv = *reinterpret_cast<const float4*>(
                    B + (size_t)(n0 + nn) * ldb + k0 + kq);
            shB[kq + 0][nn] = bv.x; shB[kq + 1][nn] = bv.y;
            shB[kq + 2][nn] = bv.z; shB[kq + 3][nn] = bv.w;
        }
        __syncthreads();

#pragma unroll
        for (int kk = 0; kk < 16; kk++) {
            float4 a = *reinterpret_cast<const float4*>(&shA[kk][ty * 4]);
            float4 b = *reinterpret_cast<const float4*>(&shB[kk][tx * 4]);
            float ai[4] = {a.x, a.y, a.z, a.w};
            float bj[4] = {b.x, b.y, b.z, b.w};
#pragma unroll
            for (int i = 0; i < 4; i++)
#pragma unroll
                for (int j = 0; j < 4; j++) acc[i][j] += ai[i] * bj[j];
        }
        __syncthreads();
    }

    int col = n0 + tx * 4;
    if (col < N) {
        float b0 = bias ? bias[col + 0] : 0.0f;
        float b1 = bias ? bias[col + 1] : 0.0f;
        float b2 = bias ? bias[col + 2] : 0.0f;
        float b3 = bias ? bias[col + 3] : 0.0f;
#pragma unroll
        for (int i = 0; i < 4; i++) {
            int row = m0 + ty * 4 + i;
            float4 o;
            o.x = acc[i][0] * alpha + b0;
            o.y = acc[i][1] * alpha + b1;
            o.z = acc[i][2] * alpha + b2;
            o.w = acc[i][3] * alpha + b3;
            if (ACT) {
                o.x = fmaxf(o.x, 0.f); o.y = fmaxf(o.y, 0.f);
                o.z = fmaxf(o.z, 0.f); o.w = fmaxf(o.w, 0.f);
            }
            *reinterpret_cast<float4*>(C + (size_t)row * ldc + col) = o;
        }
    }
}

// ---------------------------------------------------------------------------
// Per-channel batchnorm stats over N rows: st[c]=mean, st[128+c]=rstd
// ---------------------------------------------------------------------------
__global__ void k_bn_stats(const float* __restrict__ h, float* __restrict__ st) {
    __shared__ float ss[256], sq[256];
    int c = blockIdx.x, t = threadIdx.x;
    float a = 0.f, b = 0.f;
    for (int n = t; n < NP; n += 256) {
        float v = h[(size_t)n * DM + c];
        a += v; b += v * v;
    }
    ss[t] = a; sq[t] = b;
    __syncthreads();
    for (int o = 128; o > 0; o >>= 1) {
        if (t < o) { ss[t] += ss[t + o]; sq[t] += sq[t + o]; }
        __syncthreads();
    }
    if (t == 0) {
        float mean = ss[0] / NP;
        float var  = sq[0] / NP - mean * mean;
        st[c]       = mean;
        st[128 + c] = rsqrtf(var + 1e-5f);
    }
}

// bn apply + relu; also h = feat0 + pe
__global__ void k_bn_apply(const float* __restrict__ conv, const float* __restrict__ st,
                           const float* __restrict__ g, const float* __restrict__ b,
                           const float* __restrict__ pe,
                           float* __restrict__ feat0, float* __restrict__ h) {
    int i = blockIdx.x * 256 + threadIdx.x;
    int c = i & 127;
    float v = (conv[i] - st[c]) * st[128 + c] * g[c] + b[c];
    v = fmaxf(v, 0.0f);
    feat0[i] = v;
    h[i] = v + pe[i];
}

// ---------------------------------------------------------------------------
// Row softmax over 4096 (one block per (row, head)), smem-resident row
// ---------------------------------------------------------------------------
__global__ void k_softmax(float* __restrict__ S) {
    __shared__ float buf[NP];
    __shared__ float red[256];
    int row = blockIdx.x, head = blockIdx.y, t = threadIdx.x;
    float* r = S + ((size_t)head * NP + row) * NP;
    float mx = -1e30f;
    for (int i = t; i < NP; i += 256) {
        float v = r[i];
        buf[i] = v;
        mx = fmaxf(mx, v);
    }
    red[t] = mx;
    __syncthreads();
    for (int o = 128; o > 0; o >>= 1) {
        if (t < o) red[t] = fmaxf(red[t], red[t + o]);
        __syncthreads();
    }
    float M = red[0];
    __syncthreads();
    float s = 0.f;
    for (int i = t; i < NP; i += 256) {
        float e = __expf(buf[i] - M);
        buf[i] = e;
        s += e;
    }
    red[t] = s;
    __syncthreads();
    for (int o = 128; o > 0; o >>= 1) {
        if (t < o) red[t] += red[t + o];
        __syncthreads();
    }
    float inv = 1.0f / red[0];
    for (int i = t; i < NP; i += 256) r[i] = buf[i] * inv;
}

// ---------------------------------------------------------------------------
// LayerNorm(a + b) * g + beta  (one block of 128 threads per row)
// ---------------------------------------------------------------------------
__global__ void k_ln(const float* __restrict__ a, const float* __restrict__ b,
                     const float* __restrict__ g, const float* __restrict__ beta,
                     float* __restrict__ out) {
    int r = blockIdx.x, t = threadIdx.x;
    float v = a[(size_t)r * DM + t] + b[(size_t)r * DM + t];
    float s = v, q = v * v;
#pragma unroll
    for (int o = 16; o > 0; o >>= 1) {
        s += __shfl_xor_sync(0xffffffffu, s, o);
        q += __shfl_xor_sync(0xffffffffu, q, o);
    }
    __shared__ float ws[4], wq[4];
    int w = t >> 5, lane = t & 31;
    if (lane == 0) { ws[w] = s; wq[w] = q; }
    __syncthreads();
    if (t == 0) {
        float S_ = ws[0] + ws[1] + ws[2] + ws[3];
        float Q_ = wq[0] + wq[1] + wq[2] + wq[3];
        float mean = S_ / 128.0f;
        float var  = Q_ / 128.0f - mean * mean;
        ws[0] = mean;
        wq[0] = rsqrtf(var + 1e-5f);
    }
    __syncthreads();
    out[(size_t)r * DM + t] = (v - ws[0]) * wq[0] * g[t] + beta[t];
}

// out = 2*x*sig(xf+yf) + 2*y*(1 - sig(xf+yf))
__global__ void k_combine(const float* __restrict__ x, const float* __restrict__ y,
                          const float* __restrict__ xf, const float* __restrict__ yf,
                          float* __restrict__ out) {
    int i = blockIdx.x * 256 + threadIdx.x;
    float z = xf[i] + yf[i];
    float s = 1.0f / (1.0f + expf(-z));
    out[i] = 2.0f * x[i] * s + 2.0f * y[i] * (1.0f - s);
}

// ---------------------------------------------------------------------------
// Launch
// ---------------------------------------------------------------------------
extern "C" void kernel_launch(void* const* d_in, const int* in_sizes, int n_in,
                              void* d_out, int out_size) {
    const float* x    = (const float*)d_in[0];
    const float* y    = (const float*)d_in[1];
    const float* pos  = (const float*)d_in[2];
    const int*   idx  = (const int*)d_in[3];
    // d_in[4] = nbr_mask (bool) — derived as idx != self, unused
    const float* Wx   = (const float*)d_in[5];
    const float* bx   = (const float*)d_in[6];
    const float* bnxg = (const float*)d_in[7];
    const float* bnxb = (const float*)d_in[8];
    const float* Wy   = (const float*)d_in[9];
    const float* by   = (const float*)d_in[10];
    const float* bnyg = (const float*)d_in[11];
    const float* bnyb = (const float*)d_in[12];
    const float* Wq   = (const float*)d_in[13];
    const float* bq   = (const float*)d_in[14];
    const float* Wk   = (const float*)d_in[15];
    const float* bk   = (const float*)d_in[16];
    const float* Wv   = (const float*)d_in[17];
    const float* bv   = (const float*)d_in[18];
    const float* Wo   = (const float*)d_in[19];
    const float* bo   = (const float*)d_in[20];
    const float* ln1g = (const float*)d_in[21];
    const float* ln1b = (const float*)d_in[22];
    const float* W1   = (const float*)d_in[23];
    const float* b1   = (const float*)d_in[24];
    const float* W2   = (const float*)d_in[25];
    const float* b2   = (const float*)d_in[26];
    const float* ln2g = (const float*)d_in[27];
    const float* ln2b = (const float*)d_in[28];
    float* out = (float*)d_out;

    float* base = nullptr;
    cudaGetSymbolAddress((void**)&base, g_scratch);

    float* A    = base + OFF_A;
    float* S    = base + OFF_S;
    float* pe   = base + OFF_PE;
    float* conv = base + OFF_CONV;
    float* f0   = base + OFF_F0;
    float* h    = base + OFF_H;
    float* q    = base + OFF_Q;
    float* kb   = base + OFF_K;
    float* v    = base + OFF_V;
    float* o    = base + OFF_O;
    float* tmp  = base + OFF_T;
    float* f1   = base + OFF_F1;
    float* ff   = base + OFF_FF;
    float* fo   = base + OFF_OUT;
    float* st   = base + OFF_ST;

    k_pos_stats<<<1, 256>>>(pos, st + 256);
    k_posenc<<<NP, 64>>>(pos, st + 256, pe);
    k_buildA<<<dim3(NP, 2), 128>>>(x, y, pos, idx, A);

    const float* Wc[2] = {Wx, Wy};
    const float* bc[2] = {bx, by};
    const float* bg[2] = {bnxg, bnyg};
    const float* bb[2] = {bnxb, bnyb};
    const float alphaS = 0.17677669529663687f;  // 1/sqrt(32)
    const long long sS = (long long)NP * NP;

    for (int s = 0; s < 2; s++) {
        float* fs = f0 + (size_t)s * SZ_ND;
        float* fout = fo + (size_t)s * SZ_ND;

        // cconv GEMM: A (4096 x 8192) @ Wf (8192 x 128) + bias
        k_gemm<0, 0><<<dim3(2, 64, 1), 256>>>(A + (size_t)s * SZ_A1, 8192, 0,
                                              Wc[s], 128, 0,
                                              conv, 128, 0, bc[s],
                                              NP, 128, 8192, 1.0f);
        k_bn_stats<<<128, 256>>>(conv, st);
        k_bn_apply<<<(NP * DM) / 256, 256>>>(conv, st, bg[s], bb[s], pe, fs, h);

        // QKV
        k_gemm<1, 0><<<dim3(2, 64, 1), 256>>>(h, 128, 0, Wq, 128, 0, q, 128, 0,
                                              bq, NP, 128, 128, 1.0f);
        k_gemm<1, 0><<<dim3(2, 64, 1), 256>>>(h, 128, 0, Wk, 128, 0, kb, 128, 0,
                                              bk, NP, 128, 128, 1.0f);
        k_gemm<1, 0><<<dim3(2, 64, 1), 256>>>(h, 128, 0, Wv, 128, 0, v, 128, 0,
                                              bv, NP, 128, 128, 1.0f);
        // S = (Q Kt) / sqrt(hd), batched over 4 heads
        k_gemm<1, 0><<<dim3(64, 64, 4), 256>>>(q, 128, 32, kb, 128, 32,
                                               S, NP, sS, nullptr,
                                               NP, NP, 32, alphaS);
        k_softmax<<<dim3(NP, 4), 256>>>(S);
        // O = P V, batched over heads
        k_gemm<0, 0><<<dim3(1, 64, 4), 256>>>(S, NP, sS, v, 128, 32,
                                              o, 128, 32, nullptr,
                                              NP, 32, NP, 1.0f);
        // Wo + residual + LN1
        k_gemm<1, 0><<<dim3(2, 64, 1), 256>>>(o, 128, 0, Wo, 128, 0, tmp, 128, 0,
                                              bo, NP, 128, 128, 1.0f);
        k_ln<<<NP, 128>>>(fs, tmp, ln1g, ln1b, f1);
        // FFN
        k_gemm<1, 1><<<dim3(8, 64, 1), 256>>>(f1, 128, 0, W1, 128, 0, ff, FFD, 0,
                                              b1, NP, FFD, 128, 1.0f);
        k_gemm<1, 0><<<dim3(2, 64, 1), 256>>>(ff, FFD, 0, W2, FFD, 0, tmp, 128, 0,
                                              b2, NP, 128, FFD, 1.0f);
        k_ln<<<NP, 128>>>(f1, tmp, ln2g, ln2b, fout);
    }

    k_combine<<<(NP * DM) / 256, 256>>>(x, y, fo, fo + SZ_ND, out);
}

// round 3
// speedup vs baseline: 1.6078x; 1.6078x over previous
#include <cuda_runtime.h>
#include <math.h>
#include <stdint.h>

// ---------------------------------------------------------------------------
// Problem constants
// ---------------------------------------------------------------------------
#define NP 4096
#define KN 80
#define DM 128
#define FFD 512

static constexpr size_t SZ_ND  = (size_t)NP * DM;              // 524288
static constexpr size_t SZ_A1  = (size_t)NP * 8192;            // per-stream A
static constexpr size_t SZ_S   = (size_t)4 * NP * NP;          // 4 heads
static constexpr size_t SZ_QKV = (size_t)NP * 384;

static constexpr size_t OFF_A    = 0;
static constexpr size_t OFF_S    = OFF_A + 2 * SZ_A1;
static constexpr size_t OFF_PE   = OFF_S + SZ_S;
static constexpr size_t OFF_CONV = OFF_PE + SZ_ND;
static constexpr size_t OFF_F0   = OFF_CONV + SZ_ND;           // 2 buffers
static constexpr size_t OFF_H    = OFF_F0 + 2 * SZ_ND;
static constexpr size_t OFF_QKV  = OFF_H + SZ_ND;
static constexpr size_t OFF_O    = OFF_QKV + SZ_QKV;
static constexpr size_t OFF_T    = OFF_O + SZ_ND;
static constexpr size_t OFF_F1   = OFF_T + SZ_ND;
static constexpr size_t OFF_FF   = OFF_F1 + SZ_ND;             // NP*512
static constexpr size_t OFF_OUT  = OFF_FF + (size_t)NP * FFD;  // 2 buffers
static constexpr size_t OFF_PART = OFF_OUT + 2 * SZ_ND;        // 4 split-K partials
static constexpr size_t OFF_WQKV = OFF_PART + 4 * SZ_ND;       // 384*128 + 512
static constexpr size_t OFF_ST   = OFF_WQKV + 384 * 128 + 512;
static constexpr size_t SCRATCH_TOTAL = OFF_ST + 512;

__device__ float g_scratch[SCRATCH_TOTAL];

// ---------------------------------------------------------------------------
// helpers
// ---------------------------------------------------------------------------
__device__ __forceinline__ uint32_t f2tf32(float x) {
    float r;
    asm("cvt.rna.tf32.f32 %0, %1;" : "=f"(r) : "f"(x));
    return __float_as_uint(r);
}

__device__ __forceinline__ void mma_tf32(float c[4],
                                         uint32_t a0, uint32_t a1, uint32_t a2, uint32_t a3,
                                         uint32_t b0, uint32_t b1) {
    asm volatile(
        "mma.sync.aligned.m16n8k8.row.col.f32.tf32.tf32.f32 "
        "{%0,%1,%2,%3}, {%4,%5,%6,%7}, {%8,%9}, {%0,%1,%2,%3};\n"
        : "+f"(c[0]), "+f"(c[1]), "+f"(c[2]), "+f"(c[3])
        : "r"(a0), "r"(a1), "r"(a2), "r"(a3), "r"(b0), "r"(b1));
}

// ---------------------------------------------------------------------------
// Generic tf32 tensor-core GEMM: C = act(alpha * A @ op(B) + bias)
//   A: M x K row-major. TRANSB=0: B is K x N; TRANSB=1: B is N x K.
//   CTA tile BM x BN, BK = 32 (4 x k8 mma steps). Warp tile WM x WN.
//   Requires: M % BM == 0, N % BN == 0 per launch, K % 32 == 0.
//   batched via blockIdx.z with element strides.
// ---------------------------------------------------------------------------
template <int BM, int BN, int WM, int WN, int TRANSB, int ACT>
__global__ __launch_bounds__((BM / WM) * (BN / WN) * 32)
void k_mma(const float* __restrict__ A, int lda, long long strideA,
           const float* __restrict__ B, int ldb, long long strideB,
           float* __restrict__ C, int ldc, long long strideC,
           const float* __restrict__ bias,
           int M, int N, int K, float alpha) {
    constexpr int MI = WM / 16;
    constexpr int NI = WN / 8;
    constexpr int NWARP = (BM / WM) * (BN / WN);
    constexpr int NT = NWARP * 32;
    constexpr int LD = 36;  // 32 + 4 pad: conflict-free frag loads, 16B-aligned rows

    __shared__ uint32_t sA[BM * LD];
    __shared__ uint32_t sB[BN * LD];

    A += (size_t)blockIdx.z * strideA;
    B += (size_t)blockIdx.z * strideB;
    C += (size_t)blockIdx.z * strideC;

    const int n0 = blockIdx.x * BN;
    const int m0 = blockIdx.y * BM;
    const int tid = threadIdx.x;
    const int w = tid >> 5, lane = tid & 31;
    const int grp = lane >> 2, qid = lane & 3;
    const int wm = w % (BM / WM), wn = w / (BM / WM);

    float acc[MI][NI][4];
#pragma unroll
    for (int i = 0; i < MI; i++)
#pragma unroll
        for (int j = 0; j < NI; j++)
#pragma unroll
            for (int q = 0; q < 4; q++) acc[i][j][q] = 0.0f;

    for (int k0 = 0; k0 < K; k0 += 32) {
        // --- A tile: BM x 32, row-major in smem ---
#pragma unroll
        for (int i = tid; i < BM * 8; i += NT) {
            int r = i >> 3, c = (i & 7) * 4;
            float4 v = *reinterpret_cast<const float4*>(
                A + (size_t)(m0 + r) * lda + k0 + c);
            sA[r * LD + c + 0] = f2tf32(v.x);
            sA[r * LD + c + 1] = f2tf32(v.y);
            sA[r * LD + c + 2] = f2tf32(v.z);
            sA[r * LD + c + 3] = f2tf32(v.w);
        }
        // --- B tile -> Bt (n-major, k cols) ---
        if (TRANSB == 1) {
#pragma unroll
            for (int i = tid; i < BN * 8; i += NT) {
                int r = i >> 3, c = (i & 7) * 4;
                float4 v = *reinterpret_cast<const float4*>(
                    B + (size_t)(n0 + r) * ldb + k0 + c);
                sB[r * LD + c + 0] = f2tf32(v.x);
                sB[r * LD + c + 1] = f2tf32(v.y);
                sB[r * LD + c + 2] = f2tf32(v.z);
                sB[r * LD + c + 3] = f2tf32(v.w);
            }
        } else {
#pragma unroll
            for (int i = tid; i < 32 * (BN / 4); i += NT) {
                int kr = i / (BN / 4);
                int n4 = (i % (BN / 4)) * 4;
                float4 v = *reinterpret_cast<const float4*>(
                    B + (size_t)(k0 + kr) * ldb + n0 + n4);
                sB[(n4 + 0) * LD + kr] = f2tf32(v.x);
                sB[(n4 + 1) * LD + kr] = f2tf32(v.y);
                sB[(n4 + 2) * LD + kr] = f2tf32(v.z);
                sB[(n4 + 3) * LD + kr] = f2tf32(v.w);
            }
        }
        __syncthreads();

#pragma unroll
        for (int ks = 0; ks < 4; ks++) {
            const int kk = ks * 8;
            uint32_t af[MI][4], bf[NI][2];
#pragma unroll
            for (int mi = 0; mi < MI; mi++) {
                int r = wm * WM + mi * 16 + grp;
                af[mi][0] = sA[r * LD + kk + qid];
                af[mi][1] = sA[(r + 8) * LD + kk + qid];
                af[mi][2] = sA[r * LD + kk + qid + 4];
                af[mi][3] = sA[(r + 8) * LD + kk + qid + 4];
            }
#pragma unroll
            for (int ni = 0; ni < NI; ni++) {
                int c = wn * WN + ni * 8 + grp;
                bf[ni][0] = sB[c * LD + kk + qid];
                bf[ni][1] = sB[c * LD + kk + qid + 4];
            }
#pragma unroll
            for (int mi = 0; mi < MI; mi++)
#pragma unroll
                for (int ni = 0; ni < NI; ni++)
                    mma_tf32(acc[mi][ni], af[mi][0], af[mi][1], af[mi][2], af[mi][3],
                             bf[ni][0], bf[ni][1]);
        }
        __syncthreads();
    }

    // --- epilogue ---
#pragma unroll
    for (int mi = 0; mi < MI; mi++) {
#pragma unroll
        for (int ni = 0; ni < NI; ni++) {
            int r = m0 + wm * WM + mi * 16 + grp;
            int c = n0 + wn * WN + ni * 8 + qid * 2;
            float b0 = 0.f, b1 = 0.f;
            if (bias) { b0 = bias[c]; b1 = bias[c + 1]; }
            float v0 = acc[mi][ni][0] * alpha + b0;
            float v1 = acc[mi][ni][1] * alpha + b1;
            float v2 = acc[mi][ni][2] * alpha + b0;
            float v3 = acc[mi][ni][3] * alpha + b1;
            if (ACT) {
                v0 = fmaxf(v0, 0.f); v1 = fmaxf(v1, 0.f);
                v2 = fmaxf(v2, 0.f); v3 = fmaxf(v3, 0.f);
            }
            *reinterpret_cast<float2*>(C + (size_t)r * ldc + c) = make_float2(v0, v1);
            *reinterpret_cast<float2*>(C + (size_t)(r + 8) * ldc + c) = make_float2(v2, v3);
        }
    }
}

// ---------------------------------------------------------------------------
// pos[:,0] mean / std(ddof=1)
// ---------------------------------------------------------------------------
__global__ void k_pos_stats(const float* __restrict__ pos, float* __restrict__ st) {
    __shared__ double ss[256], sq[256];
    int t = threadIdx.x;
    double a = 0.0, b = 0.0;
    for (int i = t; i < NP; i += 256) {
        double v = (double)pos[3 * i];
        a += v; b += v * v;
    }
    ss[t] = a; sq[t] = b;
    __syncthreads();
    for (int o = 128; o > 0; o >>= 1) {
        if (t < o) { ss[t] += ss[t + o]; sq[t] += sq[t + o]; }
        __syncthreads();
    }
    if (t == 0) {
        double mean = ss[0] / NP;
        double var  = (sq[0] - ss[0] * ss[0] / NP) / (NP - 1);
        st[0] = (float)mean;
        st[1] = (float)(1.0 / (sqrt(var) + 1e-8));
    }
}

__global__ void k_posenc(const float* __restrict__ pos, const float* __restrict__ st,
                         float* __restrict__ pe) {
    int n = blockIdx.x;
    int j = threadIdx.x;               // 0..63
    float px  = (pos[3 * n] - st[0]) * st[1];
    float dv  = expf((float)(2 * j) * (-9.210340371976184f / 128.0f));
    float ang = px * dv;
    float s, c;
    sincosf(ang, &s, &c);
    pe[(size_t)n * DM + 2 * j]     = s;
    pe[(size_t)n * DM + 2 * j + 1] = c;
}

// ---------------------------------------------------------------------------
// Build A[n, 64, 128] (mask derived as idx != n)
// ---------------------------------------------------------------------------
__global__ void k_buildA(const float* __restrict__ fx, const float* __restrict__ fy,
                         const float* __restrict__ pos, const int* __restrict__ idx,
                         float* __restrict__ Abuf) {
    __shared__ float sA[64 * 128];
    int n = blockIdx.x;
    const float* feat = blockIdx.y ? fy : fx;
    float* Aout = Abuf + (size_t)blockIdx.y * SZ_A1 + (size_t)n * 8192;
    int c = threadIdx.x;

#pragma unroll
    for (int g = 0; g < 64; ++g) sA[g * 128 + c] = 0.0f;

    const float RAD  = 0.22499999403953552f * 0.5f;
    const float invR = 1.0f / RAD;
    float p0 = pos[3 * n], p1 = pos[3 * n + 1], p2 = pos[3 * n + 2];

    for (int k = 0; k < KN; k++) {
        int nb = idx[n * KN + k];
        if (nb == n) continue;
        float rx = (pos[3 * nb]     - p0) * invR;
        float ry = (pos[3 * nb + 1] - p1) * invR;
        float rz = (pos[3 * nb + 2] - p2) * invR;
        float r2 = rx * rx + ry * ry + rz * rz;
        float w1 = 1.0f - r2;
        float win = fminf(fmaxf(w1 * w1 * w1, 0.0f), 1.0f);
        if (win <= 0.0f) continue;
        float nrm  = sqrtf(fmaxf(r2, 1e-12f));
        float linf = fmaxf(fmaxf(fabsf(rx), fabsf(ry)), fabsf(rz));
        linf = fmaxf(linf, 1e-9f);
        float sc = nrm / linf;
        float gx = fminf(fmaxf((rx * sc + 1.0f) * 1.5f, 0.0f), 3.0f);
        float gy = fminf(fmaxf((ry * sc + 1.0f) * 1.5f, 0.0f), 3.0f);
        float gz = fminf(fmaxf((rz * sc + 1.0f) * 1.5f, 0.0f), 3.0f);
        float f0x = fminf(floorf(gx), 2.0f);
        float f0y = fminf(floorf(gy), 2.0f);
        float f0z = fminf(floorf(gz), 2.0f);
        float tx = gx - f0x, ty = gy - f0y, tz = gz - f0z;
        int base = (int)f0x * 16 + (int)f0y * 4 + (int)f0z;
        float f = feat[(size_t)nb * DM + c];
        float wx[2] = {1.0f - tx, tx};
        float wy[2] = {1.0f - ty, ty};
        float wz[2] = {1.0f - tz, tz};
#pragma unroll
        for (int dx = 0; dx < 2; dx++)
#pragma unroll
            for (int dy = 0; dy < 2; dy++)
#pragma unroll
                for (int dz = 0; dz < 2; dz++) {
                    int cell = base + dx * 16 + dy * 4 + dz;
                    sA[cell * 128 + c] += win * wx[dx] * wy[dy] * wz[dz] * f;
                }
    }
#pragma unroll 8
    for (int g = 0; g < 64; ++g)
        Aout[(size_t)g * 128 + c] = sA[g * 128 + c];
}

// split-K reduce: conv = sum of 4 partials + bias
__global__ void k_reduce4(const float* __restrict__ part, const float* __restrict__ bias,
                          float* __restrict__ out) {
    int i = blockIdx.x * 256 + threadIdx.x;
    float v = part[i] + part[i + SZ_ND] + part[i + 2 * SZ_ND] + part[i + 3 * SZ_ND];
    out[i] = v + bias[i & 127];
}

// pack Wq/Wk/Wv -> [384,128], biases -> [384]
__global__ void k_pack_qkv(const float* __restrict__ Wq, const float* __restrict__ Wk,
                           const float* __restrict__ Wv, const float* __restrict__ bq,
                           const float* __restrict__ bk, const float* __restrict__ bv,
                           float* __restrict__ W, float* __restrict__ b) {
    int i = blockIdx.x * 256 + threadIdx.x;
    if (i < 16384) W[i] = Wq[i];
    else if (i < 32768) W[i] = Wk[i - 16384];
    else if (i < 49152) W[i] = Wv[i - 32768];
    if (i < 128) b[i] = bq[i];
    else if (i < 256) b[i] = bk[i - 128];
    else if (i < 384) b[i] = bv[i - 256];
}

// ---------------------------------------------------------------------------
// batchnorm
// ---------------------------------------------------------------------------
__global__ void k_bn_stats(const float* __restrict__ h, float* __restrict__ st) {
    __shared__ float ss[256], sq[256];
    int c = blockIdx.x, t = threadIdx.x;
    float a = 0.f, b = 0.f;
    for (int n = t; n < NP; n += 256) {
        float v = h[(size_t)n * DM + c];
        a += v; b += v * v;
    }
    ss[t] = a; sq[t] = b;
    __syncthreads();
    for (int o = 128; o > 0; o >>= 1) {
        if (t < o) { ss[t] += ss[t + o]; sq[t] += sq[t + o]; }
        __syncthreads();
    }
    if (t == 0) {
        float mean = ss[0] / NP;
        float var  = sq[0] / NP - mean * mean;
        st[c]       = mean;
        st[128 + c] = rsqrtf(var + 1e-5f);
    }
}

__global__ void k_bn_apply(const float* __restrict__ conv, const float* __restrict__ st,
                           const float* __restrict__ g, const float* __restrict__ b,
                           const float* __restrict__ pe,
                           float* __restrict__ feat0, float* __restrict__ h) {
    int i = blockIdx.x * 256 + threadIdx.x;
    int c = i & 127;
    float v = (conv[i] - st[c]) * st[128 + c] * g[c] + b[c];
    v = fmaxf(v, 0.0f);
    feat0[i] = v;
    h[i] = v + pe[i];
}

// ---------------------------------------------------------------------------
// Row softmax over 4096
// ---------------------------------------------------------------------------
__global__ void k_softmax(float* __restrict__ S) {
    __shared__ float buf[NP];
    __shared__ float red[256];
    int row = blockIdx.x, head = blockIdx.y, t = threadIdx.x;
    float* r = S + ((size_t)head * NP + row) * NP;
    float mx = -1e30f;
    for (int i = t; i < NP; i += 256) {
        float v = r[i];
        buf[i] = v;
        mx = fmaxf(mx, v);
    }
    red[t] = mx;
    __syncthreads();
    for (int o = 128; o > 0; o >>= 1) {
        if (t < o) red[t] = fmaxf(red[t], red[t + o]);
        __syncthreads();
    }
    float M = red[0];
    __syncthreads();
    float s = 0.f;
    for (int i = t; i < NP; i += 256) {
        float e = __expf(buf[i] - M);
        buf[i] = e;
        s += e;
    }
    red[t] = s;
    __syncthreads();
    for (int o = 128; o > 0; o >>= 1) {
        if (t < o) red[t] += red[t + o];
        __syncthreads();
    }
    float inv = 1.0f / red[0];
    for (int i = t; i < NP; i += 256) r[i] = buf[i] * inv;
}

// ---------------------------------------------------------------------------
// LayerNorm(a + b) * g + beta
// ---------------------------------------------------------------------------
__global__ void k_ln(const float* __restrict__ a, const float* __restrict__ b,
                     const float* __restrict__ g, const float* __restrict__ beta,
                     float* __restrict__ out) {
    int r = blockIdx.x, t = threadIdx.x;
    float v = a[(size_t)r * DM + t] + b[(size_t)r * DM + t];
    float s = v, q = v * v;
#pragma unroll
    for (int o = 16; o > 0; o >>= 1) {
        s += __shfl_xor_sync(0xffffffffu, s, o);
        q += __shfl_xor_sync(0xffffffffu, q, o);
    }
    __shared__ float ws[4], wq[4];
    int w = t >> 5, lane = t & 31;
    if (lane == 0) { ws[w] = s; wq[w] = q; }
    __syncthreads();
    if (t == 0) {
        float S_ = ws[0] + ws[1] + ws[2] + ws[3];
        float Q_ = wq[0] + wq[1] + wq[2] + wq[3];
        float mean = S_ / 128.0f;
        float var  = Q_ / 128.0f - mean * mean;
        ws[0] = mean;
        wq[0] = rsqrtf(var + 1e-5f);
    }
    __syncthreads();
    out[(size_t)r * DM + t] = (v - ws[0]) * wq[0] * g[t] + beta[t];
}

__global__ void k_combine(const float* __restrict__ x, const float* __restrict__ y,
                          const float* __restrict__ xf, const float* __restrict__ yf,
                          float* __restrict__ out) {
    int i = blockIdx.x * 256 + threadIdx.x;
    float z = xf[i] + yf[i];
    float s = 1.0f / (1.0f + expf(-z));
    out[i] = 2.0f * x[i] * s + 2.0f * y[i] * (1.0f - s);
}

// ---------------------------------------------------------------------------
// Launch
// ---------------------------------------------------------------------------
extern "C" void kernel_launch(void* const* d_in, const int* in_sizes, int n_in,
                              void* d_out, int out_size) {
    const float* x    = (const float*)d_in[0];
    const float* y    = (const float*)d_in[1];
    const float* pos  = (const float*)d_in[2];
    const int*   idx  = (const int*)d_in[3];
    const float* Wx   = (const float*)d_in[5];
    const float* bx   = (const float*)d_in[6];
    const float* bnxg = (const float*)d_in[7];
    const float* bnxb = (const float*)d_in[8];
    const float* Wy   = (const float*)d_in[9];
    const float* by   = (const float*)d_in[10];
    const float* bnyg = (const float*)d_in[11];
    const float* bnyb = (const float*)d_in[12];
    const float* Wq   = (const float*)d_in[13];
    const float* bq   = (const float*)d_in[14];
    const float* Wk   = (const float*)d_in[15];
    const float* bk   = (const float*)d_in[16];
    const float* Wv   = (const float*)d_in[17];
    const float* bv   = (const float*)d_in[18];
    const float* Wo   = (const float*)d_in[19];
    const float* bo   = (const float*)d_in[20];
    const float* ln1g = (const float*)d_in[21];
    const float* ln1b = (const float*)d_in[22];
    const float* W1   = (const float*)d_in[23];
    const float* b1   = (const float*)d_in[24];
    const float* W2   = (const float*)d_in[25];
    const float* b2   = (const float*)d_in[26];
    const float* ln2g = (const float*)d_in[27];
    const float* ln2b = (const float*)d_in[28];
    float* out = (float*)d_out;

    float* base = nullptr;
    cudaGetSymbolAddress((void**)&base, g_scratch);

    float* A    = base + OFF_A;
    float* S    = base + OFF_S;
    float* pe   = base + OFF_PE;
    float* conv = base + OFF_CONV;
    float* f0   = base + OFF_F0;
    float* h    = base + OFF_H;
    float* qkv  = base + OFF_QKV;
    float* o    = base + OFF_O;
    float* tmp  = base + OFF_T;
    float* f1   = base + OFF_F1;
    float* ff   = base + OFF_FF;
    float* fo   = base + OFF_OUT;
    float* part = base + OFF_PART;
    float* Wqkv = base + OFF_WQKV;
    float* bqkv = base + OFF_WQKV + 384 * 128;
    float* st   = base + OFF_ST;

    k_pos_stats<<<1, 256>>>(pos, st + 256);
    k_posenc<<<NP, 64>>>(pos, st + 256, pe);
    k_buildA<<<dim3(NP, 2), 128>>>(x, y, pos, idx, A);
    k_pack_qkv<<<192, 256>>>(Wq, Wk, Wv, bq, bk, bv, Wqkv, bqkv);

    const float* Wc[2] = {Wx, Wy};
    const float* bc[2] = {bx, by};
    const float* bg[2] = {bnxg, bnyg};
    const float* bb[2] = {bnxb, bnyb};
    const float alphaS = 0.17677669529663687f;  // 1/sqrt(32)
    const long long sS = (long long)NP * NP;

    for (int s = 0; s < 2; s++) {
        float* fs   = f0 + (size_t)s * SZ_ND;
        float* fout = fo + (size_t)s * SZ_ND;

        // conv GEMM, split-K=4: partials over K-slices of 2048
        k_mma<128, 128, 64, 32, 0, 0><<<dim3(1, 32, 4), 256>>>(
            A + (size_t)s * SZ_A1, 8192, 2048,
            Wc[s], 128, 2048LL * 128,
            part, 128, (long long)SZ_ND, nullptr,
            NP, 128, 2048, 1.0f);
        k_reduce4<<<(NP * DM) / 256, 256>>>(part, bc[s], conv);
        k_bn_stats<<<128, 256>>>(conv, st);
        k_bn_apply<<<(NP * DM) / 256, 256>>>(conv, st, bg[s], bb[s], pe, fs, h);

        // fused QKV: h (4096x128) @ Wqkv^T (384x128) -> qkv (4096x384)
        k_mma<128, 128, 64, 32, 1, 0><<<dim3(3, 32, 1), 256>>>(
            h, 128, 0, Wqkv, 128, 0, qkv, 384, 0, bqkv,
            NP, 384, 128, 1.0f);

        // S = Q K^T / sqrt(hd), batched over heads (z)
        k_mma<128, 128, 64, 32, 1, 0><<<dim3(32, 32, 4), 256>>>(
            qkv, 384, 32, qkv + 128, 384, 32,
            S, NP, sS, nullptr, NP, NP, 32, alphaS);
        k_softmax<<<dim3(NP, 4), 256>>>(S);

        // O = P V, per head
        k_mma<128, 32, 32, 32, 0, 0><<<dim3(1, 32, 4), 128>>>(
            S, NP, sS, qkv + 256, 384, 32,
            o, 128, 32, nullptr, NP, 32, NP, 1.0f);

        // Wo + residual + LN1
        k_mma<128, 128, 64, 32, 1, 0><<<dim3(1, 32, 1), 256>>>(
            o, 128, 0, Wo, 128, 0, tmp, 128, 0, bo, NP, 128, 128, 1.0f);
        k_ln<<<NP, 128>>>(fs, tmp, ln1g, ln1b, f1);

        // FFN
        k_mma<128, 128, 64, 32, 1, 1><<<dim3(4, 32, 1), 256>>>(
            f1, 128, 0, W1, 128, 0, ff, FFD, 0, b1, NP, FFD, 128, 1.0f);
        k_mma<128, 128, 64, 32, 1, 0><<<dim3(1, 32, 1), 256>>>(
            ff, FFD, 0, W2, FFD, 0, tmp, 128, 0, b2, NP, 128, FFD, 1.0f);
        k_ln<<<NP, 128>>>(f1, tmp, ln2g, ln2b, fout);
    }

    k_combine<<<(NP * DM) / 256, 256>>>(x, y, fo, fo + SZ_ND, out);
}

// round 4
// speedup vs baseline: 3.5072x; 2.1814x over previous
#include <cuda_runtime.h>
#include <math.h>
#include <stdint.h>

// ---------------------------------------------------------------------------
// Problem constants
// ---------------------------------------------------------------------------
#define NP 4096
#define KN 80
#define DM 128
#define FFD 512

static constexpr size_t SZ_ND  = (size_t)NP * DM;              // 524288
static constexpr size_t SZ_A1  = (size_t)NP * 8192;            // per-stream A
static constexpr size_t SZ_QKV = (size_t)NP * 384;

static constexpr size_t OFF_A    = 0;
static constexpr size_t OFF_PE   = OFF_A + 2 * SZ_A1;
static constexpr size_t OFF_CONV = OFF_PE + SZ_ND;
static constexpr size_t OFF_F0   = OFF_CONV + 2 * SZ_ND;
static constexpr size_t OFF_H    = OFF_F0 + 2 * SZ_ND;
static constexpr size_t OFF_QKV  = OFF_H + 2 * SZ_ND;
static constexpr size_t OFF_O    = OFF_QKV + 2 * SZ_QKV;
static constexpr size_t OFF_T    = OFF_O + 2 * SZ_ND;
static constexpr size_t OFF_F1   = OFF_T + 2 * SZ_ND;
static constexpr size_t OFF_FF   = OFF_F1 + 2 * SZ_ND;         // 2*NP*512
static constexpr size_t OFF_OUT  = OFF_FF + 2 * (size_t)NP * FFD;
static constexpr size_t OFF_PART = OFF_OUT + 2 * SZ_ND;        // 16 partials
static constexpr size_t OFF_WQKV = OFF_PART + 16 * SZ_ND;      // 384*128 + 512
static constexpr size_t OFF_ST   = OFF_WQKV + 384 * 128 + 512;
static constexpr size_t SCRATCH_TOTAL = OFF_ST + 1024;

__device__ float g_scratch[SCRATCH_TOTAL];

// ---------------------------------------------------------------------------
// helpers
// ---------------------------------------------------------------------------
__device__ __forceinline__ uint32_t f2tf32(float x) {
    float r;
    asm("cvt.rna.tf32.f32 %0, %1;" : "=f"(r) : "f"(x));
    return __float_as_uint(r);
}

__device__ __forceinline__ void mma_tf32(float c[4],
                                         uint32_t a0, uint32_t a1, uint32_t a2, uint32_t a3,
                                         uint32_t b0, uint32_t b1) {
    asm volatile(
        "mma.sync.aligned.m16n8k8.row.col.f32.tf32.tf32.f32 "
        "{%0,%1,%2,%3}, {%4,%5,%6,%7}, {%8,%9}, {%0,%1,%2,%3};\n"
        : "+f"(c[0]), "+f"(c[1]), "+f"(c[2]), "+f"(c[3])
        : "r"(a0), "r"(a1), "r"(a2), "r"(a3), "r"(b0), "r"(b1));
}

// ---------------------------------------------------------------------------
// Generic tf32 tensor-core GEMM (same as round-3, validated)
// ---------------------------------------------------------------------------
template <int BM, int BN, int WM, int WN, int TRANSB, int ACT>
__global__ __launch_bounds__((BM / WM) * (BN / WN) * 32)
void k_mma(const float* __restrict__ A, int lda, long long strideA,
           const float* __restrict__ B, int ldb, long long strideB,
           float* __restrict__ C, int ldc, long long strideC,
           const float* __restrict__ bias,
           int M, int N, int K, float alpha) {
    constexpr int MI = WM / 16;
    constexpr int NI = WN / 8;
    constexpr int NWARP = (BM / WM) * (BN / WN);
    constexpr int NT = NWARP * 32;
    constexpr int LD = 36;

    __shared__ uint32_t sA[BM * LD];
    __shared__ uint32_t sB[BN * LD];

    A += (size_t)blockIdx.z * strideA;
    B += (size_t)blockIdx.z * strideB;
    C += (size_t)blockIdx.z * strideC;

    const int n0 = blockIdx.x * BN;
    const int m0 = blockIdx.y * BM;
    const int tid = threadIdx.x;
    const int w = tid >> 5, lane = tid & 31;
    const int grp = lane >> 2, qid = lane & 3;
    const int wm = w % (BM / WM), wn = w / (BM / WM);

    float acc[MI][NI][4];
#pragma unroll
    for (int i = 0; i < MI; i++)
#pragma unroll
        for (int j = 0; j < NI; j++)
#pragma unroll
            for (int q = 0; q < 4; q++) acc[i][j][q] = 0.0f;

    for (int k0 = 0; k0 < K; k0 += 32) {
#pragma unroll
        for (int i = tid; i < BM * 8; i += NT) {
            int r = i >> 3, c = (i & 7) * 4;
            float4 v = *reinterpret_cast<const float4*>(
                A + (size_t)(m0 + r) * lda + k0 + c);
            sA[r * LD + c + 0] = f2tf32(v.x);
            sA[r * LD + c + 1] = f2tf32(v.y);
            sA[r * LD + c + 2] = f2tf32(v.z);
            sA[r * LD + c + 3] = f2tf32(v.w);
        }
        if (TRANSB == 1) {
#pragma unroll
            for (int i = tid; i < BN * 8; i += NT) {
                int r = i >> 3, c = (i & 7) * 4;
                float4 v = *reinterpret_cast<const float4*>(
                    B + (size_t)(n0 + r) * ldb + k0 + c);
                sB[r * LD + c + 0] = f2tf32(v.x);
                sB[r * LD + c + 1] = f2tf32(v.y);
                sB[r * LD + c + 2] = f2tf32(v.z);
                sB[r * LD + c + 3] = f2tf32(v.w);
            }
        } else {
#pragma unroll
            for (int i = tid; i < 32 * (BN / 4); i += NT) {
                int kr = i / (BN / 4);
                int n4 = (i % (BN / 4)) * 4;
                float4 v = *reinterpret_cast<const float4*>(
                    B + (size_t)(k0 + kr) * ldb + n0 + n4);
                sB[(n4 + 0) * LD + kr] = f2tf32(v.x);
                sB[(n4 + 1) * LD + kr] = f2tf32(v.y);
                sB[(n4 + 2) * LD + kr] = f2tf32(v.z);
                sB[(n4 + 3) * LD + kr] = f2tf32(v.w);
            }
        }
        __syncthreads();

#pragma unroll
        for (int ks = 0; ks < 4; ks++) {
            const int kk = ks * 8;
            uint32_t af[MI][4], bf[NI][2];
#pragma unroll
            for (int mi = 0; mi < MI; mi++) {
                int r = wm * WM + mi * 16 + grp;
                af[mi][0] = sA[r * LD + kk + qid];
                af[mi][1] = sA[(r + 8) * LD + kk + qid];
                af[mi][2] = sA[r * LD + kk + qid + 4];
                af[mi][3] = sA[(r + 8) * LD + kk + qid + 4];
            }
#pragma unroll
            for (int ni = 0; ni < NI; ni++) {
                int c = wn * WN + ni * 8 + grp;
                bf[ni][0] = sB[c * LD + kk + qid];
                bf[ni][1] = sB[c * LD + kk + qid + 4];
            }
#pragma unroll
            for (int mi = 0; mi < MI; mi++)
#pragma unroll
                for (int ni = 0; ni < NI; ni++)
                    mma_tf32(acc[mi][ni], af[mi][0], af[mi][1], af[mi][2], af[mi][3],
                             bf[ni][0], bf[ni][1]);
        }
        __syncthreads();
    }

#pragma unroll
    for (int mi = 0; mi < MI; mi++) {
#pragma unroll
        for (int ni = 0; ni < NI; ni++) {
            int r = m0 + wm * WM + mi * 16 + grp;
            int c = n0 + wn * WN + ni * 8 + qid * 2;
            float b0 = 0.f, b1 = 0.f;
            if (bias) { b0 = bias[c]; b1 = bias[c + 1]; }
            float v0 = acc[mi][ni][0] * alpha + b0;
            float v1 = acc[mi][ni][1] * alpha + b1;
            float v2 = acc[mi][ni][2] * alpha + b0;
            float v3 = acc[mi][ni][3] * alpha + b1;
            if (ACT) {
                v0 = fmaxf(v0, 0.f); v1 = fmaxf(v1, 0.f);
                v2 = fmaxf(v2, 0.f); v3 = fmaxf(v3, 0.f);
            }
            *reinterpret_cast<float2*>(C + (size_t)r * ldc + c) = make_float2(v0, v1);
            *reinterpret_cast<float2*>(C + (size_t)(r + 8) * ldc + c) = make_float2(v2, v3);
        }
    }
}

// ---------------------------------------------------------------------------
// Flash attention: 4 heads, hd=32, N=4096.  grid (qblock=32, head=4, stream=2)
// Br=Bc=128, 8 warps. Q tile resident; online softmax; P staged via smem.
// ---------------------------------------------------------------------------
static constexpr int FLASH_SMEM = (128 * 36 + 128 * 36 + 32 * 132 + 128 * 132) * 4;

__global__ __launch_bounds__(256)
void k_flash(const float* __restrict__ qkvbuf, float* __restrict__ obuf, float alpha) {
    constexpr int LDQ = 36, LDV = 132, LDP = 132;
    extern __shared__ uint32_t sm[];
    uint32_t* sQ = sm;                  // 128 x 36
    uint32_t* sK = sQ + 128 * LDQ;      // 128 x 36
    uint32_t* sV = sK + 128 * LDQ;      // 32  x 132 (transposed: [col][key])
    uint32_t* sP = sV + 32 * LDV;       // 128 x 132

    const int qb = blockIdx.x, head = blockIdx.y, str = blockIdx.z;
    const float* Qg = qkvbuf + (size_t)str * SZ_QKV + head * 32;
    const float* Kg = Qg + 128;
    const float* Vg = Qg + 256;

    const int tid = threadIdx.x;
    const int w = tid >> 5, lane = tid & 31;
    const int grp = lane >> 2, qid = lane & 3;

    // Q tile, pre-scaled by alpha
    for (int i = tid; i < 1024; i += 256) {
        int r = i >> 3, c = (i & 7) * 4;
        float4 v = *reinterpret_cast<const float4*>(
            Qg + (size_t)(qb * 128 + r) * 384 + c);
        sQ[r * LDQ + c + 0] = f2tf32(v.x * alpha);
        sQ[r * LDQ + c + 1] = f2tf32(v.y * alpha);
        sQ[r * LDQ + c + 2] = f2tf32(v.z * alpha);
        sQ[r * LDQ + c + 3] = f2tf32(v.w * alpha);
    }

    float acc[4][4];
#pragma unroll
    for (int ni = 0; ni < 4; ni++)
#pragma unroll
        for (int q = 0; q < 4; q++) acc[ni][q] = 0.0f;
    float m0 = -1e30f, m1 = -1e30f, l0 = 0.0f, l1 = 0.0f;

    const int pr0 = (w * 16 + grp) * LDP;
    const int pr1 = (w * 16 + grp + 8) * LDP;

    for (int kt = 0; kt < 32; kt++) {
        __syncthreads();
        for (int i = tid; i < 1024; i += 256) {
            int r = i >> 3, c = (i & 7) * 4;
            float4 kv = *reinterpret_cast<const float4*>(
                Kg + (size_t)(kt * 128 + r) * 384 + c);
            sK[r * LDQ + c + 0] = f2tf32(kv.x);
            sK[r * LDQ + c + 1] = f2tf32(kv.y);
            sK[r * LDQ + c + 2] = f2tf32(kv.z);
            sK[r * LDQ + c + 3] = f2tf32(kv.w);
            float4 vv = *reinterpret_cast<const float4*>(
                Vg + (size_t)(kt * 128 + r) * 384 + c);
            sV[(c + 0) * LDV + r] = f2tf32(vv.x);
            sV[(c + 1) * LDV + r] = f2tf32(vv.y);
            sV[(c + 2) * LDV + r] = f2tf32(vv.z);
            sV[(c + 3) * LDV + r] = f2tf32(vv.w);
        }
        __syncthreads();

        // ---- S = (alpha Q) K^T : warp owns rows w*16..w*16+15, 128 cols ----
        float s[16][4];
#pragma unroll
        for (int ni = 0; ni < 16; ni++)
#pragma unroll
            for (int q = 0; q < 4; q++) s[ni][q] = 0.0f;

#pragma unroll
        for (int ks = 0; ks < 4; ks++) {
            const int kk = ks * 8;
            const int r0 = w * 16 + grp;
            uint32_t a0 = sQ[r0 * LDQ + kk + qid];
            uint32_t a1 = sQ[(r0 + 8) * LDQ + kk + qid];
            uint32_t a2 = sQ[r0 * LDQ + kk + qid + 4];
            uint32_t a3 = sQ[(r0 + 8) * LDQ + kk + qid + 4];
#pragma unroll
            for (int ni = 0; ni < 16; ni++) {
                uint32_t b0 = sK[(ni * 8 + grp) * LDQ + kk + qid];
                uint32_t b1 = sK[(ni * 8 + grp) * LDQ + kk + qid + 4];
                mma_tf32(s[ni], a0, a1, a2, a3, b0, b1);
            }
        }

        // ---- online softmax ----
        float rm0 = -1e30f, rm1 = -1e30f;
#pragma unroll
        for (int ni = 0; ni < 16; ni++) {
            rm0 = fmaxf(rm0, fmaxf(s[ni][0], s[ni][1]));
            rm1 = fmaxf(rm1, fmaxf(s[ni][2], s[ni][3]));
        }
        rm0 = fmaxf(rm0, __shfl_xor_sync(0xffffffffu, rm0, 1));
        rm0 = fmaxf(rm0, __shfl_xor_sync(0xffffffffu, rm0, 2));
        rm1 = fmaxf(rm1, __shfl_xor_sync(0xffffffffu, rm1, 1));
        rm1 = fmaxf(rm1, __shfl_xor_sync(0xffffffffu, rm1, 2));

        float mn0 = fmaxf(m0, rm0), mn1 = fmaxf(m1, rm1);
        float c0 = __expf(m0 - mn0), c1 = __expf(m1 - mn1);
        float rs0 = 0.0f, rs1 = 0.0f;
#pragma unroll
        for (int ni = 0; ni < 16; ni++) {
            float p00 = __expf(s[ni][0] - mn0);
            float p01 = __expf(s[ni][1] - mn0);
            float p10 = __expf(s[ni][2] - mn1);
            float p11 = __expf(s[ni][3] - mn1);
            rs0 += p00 + p01;
            rs1 += p10 + p11;
            int col = ni * 8 + qid * 2;
            *reinterpret_cast<uint2*>(&sP[pr0 + col]) =
                make_uint2(f2tf32(p00), f2tf32(p01));
            *reinterpret_cast<uint2*>(&sP[pr1 + col]) =
                make_uint2(f2tf32(p10), f2tf32(p11));
        }
        rs0 += __shfl_xor_sync(0xffffffffu, rs0, 1);
        rs0 += __shfl_xor_sync(0xffffffffu, rs0, 2);
        rs1 += __shfl_xor_sync(0xffffffffu, rs1, 1);
        rs1 += __shfl_xor_sync(0xffffffffu, rs1, 2);

        l0 = l0 * c0 + rs0;
        l1 = l1 * c1 + rs1;
        m0 = mn0; m1 = mn1;
#pragma unroll
        for (int ni = 0; ni < 4; ni++) {
            acc[ni][0] *= c0; acc[ni][1] *= c0;
            acc[ni][2] *= c1; acc[ni][3] *= c1;
        }
        __syncwarp();

        // ---- O += P V  (A = warp's own rows of sP, B = sV) ----
#pragma unroll
        for (int ks = 0; ks < 16; ks++) {
            const int kk = ks * 8;
            uint32_t a0 = sP[pr0 + kk + qid];
            uint32_t a1 = sP[pr1 + kk + qid];
            uint32_t a2 = sP[pr0 + kk + qid + 4];
            uint32_t a3 = sP[pr1 + kk + qid + 4];
#pragma unroll
            for (int ni = 0; ni < 4; ni++) {
                uint32_t b0 = sV[(ni * 8 + grp) * LDV + kk + qid];
                uint32_t b1 = sV[(ni * 8 + grp) * LDV + kk + qid + 4];
                mma_tf32(acc[ni], a0, a1, a2, a3, b0, b1);
            }
        }
    }

    float i0 = 1.0f / l0, i1 = 1.0f / l1;
    float* O = obuf + (size_t)str * SZ_ND;
    int r0 = qb * 128 + w * 16 + grp;
#pragma unroll
    for (int ni = 0; ni < 4; ni++) {
        int col = head * 32 + ni * 8 + qid * 2;
        *reinterpret_cast<float2*>(O + (size_t)r0 * DM + col) =
            make_float2(acc[ni][0] * i0, acc[ni][1] * i0);
        *reinterpret_cast<float2*>(O + (size_t)(r0 + 8) * DM + col) =
            make_float2(acc[ni][2] * i1, acc[ni][3] * i1);
    }
}

// ---------------------------------------------------------------------------
// pos stats / positional encoding
// ---------------------------------------------------------------------------
__global__ void k_pos_stats(const float* __restrict__ pos, float* __restrict__ st) {
    __shared__ double ss[256], sq[256];
    int t = threadIdx.x;
    double a = 0.0, b = 0.0;
    for (int i = t; i < NP; i += 256) {
        double v = (double)pos[3 * i];
        a += v; b += v * v;
    }
    ss[t] = a; sq[t] = b;
    __syncthreads();
    for (int o = 128; o > 0; o >>= 1) {
        if (t < o) { ss[t] += ss[t + o]; sq[t] += sq[t + o]; }
        __syncthreads();
    }
    if (t == 0) {
        double mean = ss[0] / NP;
        double var  = (sq[0] - ss[0] * ss[0] / NP) / (NP - 1);
        st[0] = (float)mean;
        st[1] = (float)(1.0 / (sqrt(var) + 1e-8));
    }
}

__global__ void k_posenc(const float* __restrict__ pos, const float* __restrict__ st,
                         float* __restrict__ pe) {
    int n = blockIdx.x;
    int j = threadIdx.x;
    float px  = (pos[3 * n] - st[0]) * st[1];
    float dv  = expf((float)(2 * j) * (-9.210340371976184f / 128.0f));
    float ang = px * dv;
    float s, c;
    sincosf(ang, &s, &c);
    pe[(size_t)n * DM + 2 * j]     = s;
    pe[(size_t)n * DM + 2 * j + 1] = c;
}

// ---------------------------------------------------------------------------
// Build A[n, 64, 128] (mask derived as idx != n)
// ---------------------------------------------------------------------------
__global__ void k_buildA(const float* __restrict__ fx, const float* __restrict__ fy,
                         const float* __restrict__ pos, const int* __restrict__ idx,
                         float* __restrict__ Abuf) {
    __shared__ float sA[64 * 128];
    int n = blockIdx.x;
    const float* feat = blockIdx.y ? fy : fx;
    float* Aout = Abuf + (size_t)blockIdx.y * SZ_A1 + (size_t)n * 8192;
    int c = threadIdx.x;

#pragma unroll
    for (int g = 0; g < 64; ++g) sA[g * 128 + c] = 0.0f;

    const float RAD  = 0.22499999403953552f * 0.5f;
    const float invR = 1.0f / RAD;
    float p0 = pos[3 * n], p1 = pos[3 * n + 1], p2 = pos[3 * n + 2];

    for (int k = 0; k < KN; k++) {
        int nb = idx[n * KN + k];
        if (nb == n) continue;
        float rx = (pos[3 * nb]     - p0) * invR;
        float ry = (pos[3 * nb + 1] - p1) * invR;
        float rz = (pos[3 * nb + 2] - p2) * invR;
        float r2 = rx * rx + ry * ry + rz * rz;
        float w1 = 1.0f - r2;
        float win = fminf(fmaxf(w1 * w1 * w1, 0.0f), 1.0f);
        if (win <= 0.0f) continue;
        float nrm  = sqrtf(fmaxf(r2, 1e-12f));
        float linf = fmaxf(fmaxf(fabsf(rx), fabsf(ry)), fabsf(rz));
        linf = fmaxf(linf, 1e-9f);
        float sc = nrm / linf;
        float gx = fminf(fmaxf((rx * sc + 1.0f) * 1.5f, 0.0f), 3.0f);
        float gy = fminf(fmaxf((ry * sc + 1.0f) * 1.5f, 0.0f), 3.0f);
        float gz = fminf(fmaxf((rz * sc + 1.0f) * 1.5f, 0.0f), 3.0f);
        float f0x = fminf(floorf(gx), 2.0f);
        float f0y = fminf(floorf(gy), 2.0f);
        float f0z = fminf(floorf(gz), 2.0f);
        float tx = gx - f0x, ty = gy - f0y, tz = gz - f0z;
        int base = (int)f0x * 16 + (int)f0y * 4 + (int)f0z;
        float f = feat[(size_t)nb * DM + c];
        float wx[2] = {1.0f - tx, tx};
        float wy[2] = {1.0f - ty, ty};
        float wz[2] = {1.0f - tz, tz};
#pragma unroll
        for (int dx = 0; dx < 2; dx++)
#pragma unroll
            for (int dy = 0; dy < 2; dy++)
#pragma unroll
                for (int dz = 0; dz < 2; dz++) {
                    int cell = base + dx * 16 + dy * 4 + dz;
                    sA[cell * 128 + c] += win * wx[dx] * wy[dy] * wz[dz] * f;
                }
    }
#pragma unroll 8
    for (int g = 0; g < 64; ++g)
        Aout[(size_t)g * 128 + c] = sA[g * 128 + c];
}

// split-K reduce over 8 partials, both streams
__global__ void k_reduce8(const float* __restrict__ part, const float* __restrict__ bx,
                          const float* __restrict__ by, float* __restrict__ out) {
    size_t i = (size_t)blockIdx.x * 256 + threadIdx.x;   // < 2*SZ_ND
    int str = (int)(i / SZ_ND);
    const float* p = part + (size_t)str * 8 * SZ_ND + (i - (size_t)str * SZ_ND);
    float v = 0.0f;
#pragma unroll
    for (int j = 0; j < 8; j++) v += p[j * SZ_ND];
    const float* bias = str ? by : bx;
    out[i] = v + bias[i & 127];
}

// pack Wq/Wk/Wv -> [384,128], biases -> [384]
__global__ void k_pack_qkv(const float* __restrict__ Wq, const float* __restrict__ Wk,
                           const float* __restrict__ Wv, const float* __restrict__ bq,
                           const float* __restrict__ bk, const float* __restrict__ bv,
                           float* __restrict__ W, float* __restrict__ b) {
    int i = blockIdx.x * 256 + threadIdx.x;
    if (i < 16384) W[i] = Wq[i];
    else if (i < 32768) W[i] = Wk[i - 16384];
    else if (i < 49152) W[i] = Wv[i - 32768];
    if (i < 128) b[i] = bq[i];
    else if (i < 256) b[i] = bk[i - 128];
    else if (i < 384) b[i] = bv[i - 256];
}

// ---------------------------------------------------------------------------
// batchnorm (batched over streams via blockIdx.y)
// ---------------------------------------------------------------------------
__global__ void k_bn_stats(const float* __restrict__ h, float* __restrict__ st) {
    __shared__ float ss[256], sq[256];
    int c = blockIdx.x, str = blockIdx.y, t = threadIdx.x;
    const float* hs = h + (size_t)str * SZ_ND;
    float a = 0.f, b = 0.f;
    for (int n = t; n < NP; n += 256) {
        float v = hs[(size_t)n * DM + c];
        a += v; b += v * v;
    }
    ss[t] = a; sq[t] = b;
    __syncthreads();
    for (int o = 128; o > 0; o >>= 1) {
        if (t < o) { ss[t] += ss[t + o]; sq[t] += sq[t + o]; }
        __syncthreads();
    }
    if (t == 0) {
        float mean = ss[0] / NP;
        float var  = sq[0] / NP - mean * mean;
        st[str * 256 + c]       = mean;
        st[str * 256 + 128 + c] = rsqrtf(var + 1e-5f);
    }
}

__global__ void k_bn_apply(const float* __restrict__ conv, const float* __restrict__ st,
                           const float* __restrict__ gx, const float* __restrict__ bxp,
                           const float* __restrict__ gy, const float* __restrict__ byp,
                           const float* __restrict__ pe,
                           float* __restrict__ feat0, float* __restrict__ h) {
    size_t i = (size_t)blockIdx.x * 256 + threadIdx.x;   // < 2*SZ_ND
    int str = (int)(i / SZ_ND);
    size_t local = i - (size_t)str * SZ_ND;
    int c = (int)(i & 127);
    const float* g = str ? gy : gx;
    const float* b = str ? byp : bxp;
    const float* s = st + str * 256;
    float v = (conv[i] - s[c]) * s[128 + c] * g[c] + b[c];
    v = fmaxf(v, 0.0f);
    feat0[i] = v;
    h[i] = v + pe[local];
}

// ---------------------------------------------------------------------------
// LayerNorm(a + b) * g + beta  (grid = 2*NP rows over contiguous 2-stream bufs)
// ---------------------------------------------------------------------------
__global__ void k_ln(const float* __restrict__ a, const float* __restrict__ b,
                     const float* __restrict__ g, const float* __restrict__ beta,
                     float* __restrict__ out) {
    int r = blockIdx.x, t = threadIdx.x;
    float v = a[(size_t)r * DM + t] + b[(size_t)r * DM + t];
    float s = v, q = v * v;
#pragma unroll
    for (int o = 16; o > 0; o >>= 1) {
        s += __shfl_xor_sync(0xffffffffu, s, o);
        q += __shfl_xor_sync(0xffffffffu, q, o);
    }
    __shared__ float ws[4], wq[4];
    int w = t >> 5, lane = t & 31;
    if (lane == 0) { ws[w] = s; wq[w] = q; }
    __syncthreads();
    if (t == 0) {
        float S_ = ws[0] + ws[1] + ws[2] + ws[3];
        float Q_ = wq[0] + wq[1] + wq[2] + wq[3];
        float mean = S_ / 128.0f;
        float var  = Q_ / 128.0f - mean * mean;
        ws[0] = mean;
        wq[0] = rsqrtf(var + 1e-5f);
    }
    __syncthreads();
    out[(size_t)r * DM + t] = (v - ws[0]) * wq[0] * g[t] + beta[t];
}

__global__ void k_combine(const float* __restrict__ x, const float* __restrict__ y,
                          const float* __restrict__ xf, const float* __restrict__ yf,
                          float* __restrict__ out) {
    int i = blockIdx.x * 256 + threadIdx.x;
    float z = xf[i] + yf[i];
    float s = 1.0f / (1.0f + expf(-z));
    out[i] = 2.0f * x[i] * s + 2.0f * y[i] * (1.0f - s);
}

// ---------------------------------------------------------------------------
// Launch
// ---------------------------------------------------------------------------
extern "C" void kernel_launch(void* const* d_in, const int* in_sizes, int n_in,
                              void* d_out, int out_size) {
    const float* x    = (const float*)d_in[0];
    const float* y    = (const float*)d_in[1];
    const float* pos  = (const float*)d_in[2];
    const int*   idx  = (const int*)d_in[3];
    const float* Wx   = (const float*)d_in[5];
    const float* bx   = (const float*)d_in[6];
    const float* bnxg = (const float*)d_in[7];
    const float* bnxb = (const float*)d_in[8];
    const float* Wy   = (const float*)d_in[9];
    const float* by   = (const float*)d_in[10];
    const float* bnyg = (const float*)d_in[11];
    const float* bnyb = (const float*)d_in[12];
    const float* Wq   = (const float*)d_in[13];
    const float* bq   = (const float*)d_in[14];
    const float* Wk   = (const float*)d_in[15];
    const float* bk   = (const float*)d_in[16];
    const float* Wv   = (const float*)d_in[17];
    const float* bv   = (const float*)d_in[18];
    const float* Wo   = (const float*)d_in[19];
    const float* bo   = (const float*)d_in[20];
    const float* ln1g = (const float*)d_in[21];
    const float* ln1b = (const float*)d_in[22];
    const float* W1   = (const float*)d_in[23];
    const float* b1   = (const float*)d_in[24];
    const float* W2   = (const float*)d_in[25];
    const float* b2   = (const float*)d_in[26];
    const float* ln2g = (const float*)d_in[27];
    const float* ln2b = (const float*)d_in[28];
    float* out = (float*)d_out;

    float* base = nullptr;
    cudaGetSymbolAddress((void**)&base, g_scratch);

    float* A    = base + OFF_A;
    float* pe   = base + OFF_PE;
    float* conv = base + OFF_CONV;
    float* f0   = base + OFF_F0;
    float* h    = base + OFF_H;
    float* qkv  = base + OFF_QKV;
    float* o    = base + OFF_O;
    float* tmp  = base + OFF_T;
    float* f1   = base + OFF_F1;
    float* ff   = base + OFF_FF;
    float* fo   = base + OFF_OUT;
    float* part = base + OFF_PART;
    float* Wqkv = base + OFF_WQKV;
    float* bqkv = base + OFF_WQKV + 384 * 128;
    float* st   = base + OFF_ST;

    cudaFuncSetAttribute(k_flash, cudaFuncAttributeMaxDynamicSharedMemorySize,
                         FLASH_SMEM);

    const float alphaS = 0.17677669529663687f;  // 1/sqrt(32)

    k_pos_stats<<<1, 256>>>(pos, st + 512);
    k_posenc<<<NP, 64>>>(pos, st + 512, pe);
    k_buildA<<<dim3(NP, 2), 128>>>(x, y, pos, idx, A);
    k_pack_qkv<<<192, 256>>>(Wq, Wk, Wv, bq, bk, bv, Wqkv, bqkv);

    // conv GEMMs: split-K=8 (slices of 1024), per stream
    const float* Wc[2] = {Wx, Wy};
    for (int s = 0; s < 2; s++) {
        k_mma<128, 128, 64, 32, 0, 0><<<dim3(1, 32, 8), 256>>>(
            A + (size_t)s * SZ_A1, 8192, 1024,
            Wc[s], 128, 1024LL * 128,
            part + (size_t)s * 8 * SZ_ND, 128, (long long)SZ_ND, nullptr,
            NP, 128, 1024, 1.0f);
    }
    k_reduce8<<<(2 * SZ_ND) / 256, 256>>>(part, bx, by, conv);
    k_bn_stats<<<dim3(128, 2), 256>>>(conv, st);
    k_bn_apply<<<(2 * SZ_ND) / 256, 256>>>(conv, st, bnxg, bnxb, bnyg, bnyb,
                                           pe, f0, h);

    // fused QKV, both streams
    k_mma<128, 128, 64, 32, 1, 0><<<dim3(3, 32, 2), 256>>>(
        h, 128, (long long)SZ_ND, Wqkv, 128, 0,
        qkv, 384, (long long)SZ_QKV, bqkv, NP, 384, 128, 1.0f);

    // flash attention, both streams
    k_flash<<<dim3(32, 4, 2), 256, FLASH_SMEM>>>(qkv, o, alphaS);

    // Wo + residual + LN1
    k_mma<128, 128, 64, 32, 1, 0><<<dim3(1, 32, 2), 256>>>(
        o, 128, (long long)SZ_ND, Wo, 128, 0,
        tmp, 128, (long long)SZ_ND, bo, NP, 128, 128, 1.0f);
    k_ln<<<2 * NP, 128>>>(f0, tmp, ln1g, ln1b, f1);

    // FFN
    k_mma<128, 128, 64, 32, 1, 1><<<dim3(4, 32, 2), 256>>>(
        f1, 128, (long long)SZ_ND, W1, 128, 0,
        ff, FFD, (long long)NP * FFD, b1, NP, FFD, 128, 1.0f);
    k_mma<128, 128, 64, 32, 1, 0><<<dim3(1, 32, 2), 256>>>(
        ff, FFD, (long long)NP * FFD, W2, FFD, 0,
        tmp, 128, (long long)SZ_ND, b2, NP, 128, FFD, 1.0f);
    k_ln<<<2 * NP, 128>>>(f1, tmp, ln2g, ln2b, fo);

    k_combine<<<(NP * DM) / 256, 256>>>(x, y, fo, fo + SZ_ND, out);
}

// round 6
// speedup vs baseline: 4.2413x; 1.2093x over previous
#include <cuda_runtime.h>
#include <math.h>
#include <stdint.h>

// ---------------------------------------------------------------------------
// Problem constants
// ---------------------------------------------------------------------------
#define NP 4096
#define KN 80
#define DM 128
#define FFD 512

static constexpr size_t SZ_ND  = (size_t)NP * DM;              // 524288
static constexpr size_t SZ_A1  = (size_t)NP * 8192;            // per-stream A
static constexpr size_t SZ_QKV = (size_t)NP * 384;

static constexpr size_t OFF_A    = 0;
static constexpr size_t OFF_PE   = OFF_A + 2 * SZ_A1;
static constexpr size_t OFF_CONV = OFF_PE + SZ_ND;
static constexpr size_t OFF_F0   = OFF_CONV + 2 * SZ_ND;
static constexpr size_t OFF_H    = OFF_F0 + 2 * SZ_ND;
static constexpr size_t OFF_QKV  = OFF_H + 2 * SZ_ND;
static constexpr size_t OFF_O    = OFF_QKV + 2 * SZ_QKV;
static constexpr size_t OFF_T    = OFF_O + 2 * SZ_ND;
static constexpr size_t OFF_F1   = OFF_T + 2 * SZ_ND;
static constexpr size_t OFF_FF   = OFF_F1 + 2 * SZ_ND;         // 2*NP*512
static constexpr size_t OFF_OUT  = OFF_FF + 2 * (size_t)NP * FFD;
static constexpr size_t OFF_PART = OFF_OUT + 2 * SZ_ND;        // 16 partials
static constexpr size_t OFF_WQKV = OFF_PART + 16 * SZ_ND;      // 384*128 + 512
static constexpr size_t OFF_WXQ  = OFF_WQKV + 384 * 128 + 512;
static constexpr size_t OFF_WYQ  = OFF_WXQ + (size_t)8192 * 128;
static constexpr size_t OFF_WOQ  = OFF_WYQ + (size_t)8192 * 128;
static constexpr size_t OFF_W1Q  = OFF_WOQ + 16384;
static constexpr size_t OFF_W2Q  = OFF_W1Q + 65536;
static constexpr size_t OFF_ST   = OFF_W2Q + 65536;
static constexpr size_t SCRATCH_TOTAL = OFF_ST + 1024;

__device__ float g_scratch[SCRATCH_TOTAL];

// ---------------------------------------------------------------------------
// helpers
// ---------------------------------------------------------------------------
__device__ __forceinline__ uint32_t f2tf32(float x) {
    float r;
    asm("cvt.rna.tf32.f32 %0, %1;" : "=f"(r) : "f"(x));
    return __float_as_uint(r);
}
__device__ __forceinline__ float qtf32(float x) {
    return __uint_as_float(f2tf32(x));
}

__device__ __forceinline__ void mma_tf32(float c[4],
                                         uint32_t a0, uint32_t a1, uint32_t a2, uint32_t a3,
                                         uint32_t b0, uint32_t b1) {
    asm volatile(
        "mma.sync.aligned.m16n8k8.row.col.f32.tf32.tf32.f32 "
        "{%0,%1,%2,%3}, {%4,%5,%6,%7}, {%8,%9}, {%0,%1,%2,%3};\n"
        : "+f"(c[0]), "+f"(c[1]), "+f"(c[2]), "+f"(c[3])
        : "r"(a0), "r"(a1), "r"(a2), "r"(a3), "r"(b0), "r"(b1));
}

__device__ __forceinline__ void cp16(uint32_t s, const void* g) {
    asm volatile("cp.async.ca.shared.global [%0], [%1], 16;\n" :: "r"(s), "l"(g));
}
__device__ __forceinline__ void cp_commit() {
    asm volatile("cp.async.commit_group;\n");
}
template <int N>
__device__ __forceinline__ void cp_wait() {
    asm volatile("cp.async.wait_group %0;\n" :: "n"(N));
}

// ---------------------------------------------------------------------------
// tf32 GEMM v2: cp.async double-buffered, cvt-free (inputs pre-rounded tf32)
//   C = act(alpha * A @ op(B) + bias), optional tf32-rounded store (QUANT)
// ---------------------------------------------------------------------------
template <int BM, int BN, int WM, int WN, int TRANSB, int ACT, int QUANT>
__global__ __launch_bounds__((BM / WM) * (BN / WN) * 32)
void k_mma(const float* __restrict__ A, int lda, long long strideA,
           const float* __restrict__ B, int ldb, long long strideB,
           float* __restrict__ C, int ldc, long long strideC,
           const float* __restrict__ bias,
           int M, int N, int K, float alpha) {
    constexpr int MI = WM / 16;
    constexpr int NI = WN / 8;
    constexpr int NWARP = (BM / WM) * (BN / WN);
    constexpr int NT = NWARP * 32;
    constexpr int LDA = 36;
    constexpr int LDB = TRANSB ? 36 : (BN + 8);     // 136 for BN=128
    constexpr int SA = BM * LDA;
    constexpr int SB = TRANSB ? (BN * LDB) : (32 * LDB);

    extern __shared__ uint32_t sm[];
    uint32_t* sAst[2] = {sm, sm + SA + SB};
    uint32_t* sBst[2] = {sm + SA, sm + SA + SB + SA};

    A += (size_t)blockIdx.z * strideA;
    B += (size_t)blockIdx.z * strideB;
    C += (size_t)blockIdx.z * strideC;

    const int n0 = blockIdx.x * BN;
    const int m0 = blockIdx.y * BM;
    const int tid = threadIdx.x;
    const int w = tid >> 5, lane = tid & 31;
    const int grp = lane >> 2, qid = lane & 3;
    const int wm = w % (BM / WM), wn = w / (BM / WM);

    const uint32_t smem_base = (uint32_t)__cvta_generic_to_shared(sm);

    auto load_tile = [&](int st, int k0) {
        uint32_t aBase = smem_base + (uint32_t)(st * (SA + SB)) * 4u;
        uint32_t bBase = aBase + (uint32_t)SA * 4u;
#pragma unroll
        for (int i = tid; i < BM * 8; i += NT) {
            int r = i >> 3, c4 = (i & 7) * 4;
            cp16(aBase + (uint32_t)(r * LDA + c4) * 4u,
                 A + (size_t)(m0 + r) * lda + k0 + c4);
        }
        if (TRANSB == 1) {
#pragma unroll
            for (int i = tid; i < BN * 8; i += NT) {
                int r = i >> 3, c4 = (i & 7) * 4;
                cp16(bBase + (uint32_t)(r * LDB + c4) * 4u,
                     B + (size_t)(n0 + r) * ldb + k0 + c4);
            }
        } else {
#pragma unroll
            for (int i = tid; i < 32 * (BN / 4); i += NT) {
                int kr = i / (BN / 4);
                int n4 = (i % (BN / 4)) * 4;
                cp16(bBase + (uint32_t)(kr * LDB + n4) * 4u,
                     B + (size_t)(k0 + kr) * ldb + n0 + n4);
            }
        }
        cp_commit();
    };

    float acc[MI][NI][4];
#pragma unroll
    for (int i = 0; i < MI; i++)
#pragma unroll
        for (int j = 0; j < NI; j++)
#pragma unroll
            for (int q = 0; q < 4; q++) acc[i][j][q] = 0.0f;

    const int KT = K / 32;
    load_tile(0, 0);

    for (int kt = 0; kt < KT; kt++) {
        if (kt + 1 < KT) {
            load_tile((kt + 1) & 1, (kt + 1) * 32);
            cp_wait<1>();
        } else {
            cp_wait<0>();
        }
        __syncthreads();

        const uint32_t* sA = sAst[kt & 1];
        const uint32_t* sB = sBst[kt & 1];

#pragma unroll
        for (int ks = 0; ks < 4; ks++) {
            const int kk = ks * 8;
            uint32_t af[MI][4], bf[NI][2];
#pragma unroll
            for (int mi = 0; mi < MI; mi++) {
                int r = wm * WM + mi * 16 + grp;
                af[mi][0] = sA[r * LDA + kk + qid];
                af[mi][1] = sA[(r + 8) * LDA + kk + qid];
                af[mi][2] = sA[r * LDA + kk + qid + 4];
                af[mi][3] = sA[(r + 8) * LDA + kk + qid + 4];
            }
#pragma unroll
            for (int ni = 0; ni < NI; ni++) {
                int c = wn * WN + ni * 8 + grp;
                if (TRANSB == 1) {
                    bf[ni][0] = sB[c * LDB + kk + qid];
                    bf[ni][1] = sB[c * LDB + kk + qid + 4];
                } else {
                    bf[ni][0] = sB[(kk + qid) * LDB + c];
                    bf[ni][1] = sB[(kk + qid + 4) * LDB + c];
                }
            }
#pragma unroll
            for (int mi = 0; mi < MI; mi++)
#pragma unroll
                for (int ni = 0; ni < NI; ni++)
                    mma_tf32(acc[mi][ni], af[mi][0], af[mi][1], af[mi][2], af[mi][3],
                             bf[ni][0], bf[ni][1]);
        }
        __syncthreads();
    }

#pragma unroll
    for (int mi = 0; mi < MI; mi++) {
#pragma unroll
        for (int ni = 0; ni < NI; ni++) {
            int r = m0 + wm * WM + mi * 16 + grp;
            int c = n0 + wn * WN + ni * 8 + qid * 2;
            float b0 = 0.f, b1 = 0.f;
            if (bias) { b0 = bias[c]; b1 = bias[c + 1]; }
            float v0 = acc[mi][ni][0] * alpha + b0;
            float v1 = acc[mi][ni][1] * alpha + b1;
            float v2 = acc[mi][ni][2] * alpha + b0;
            float v3 = acc[mi][ni][3] * alpha + b1;
            if (ACT) {
                v0 = fmaxf(v0, 0.f); v1 = fmaxf(v1, 0.f);
                v2 = fmaxf(v2, 0.f); v3 = fmaxf(v3, 0.f);
            }
            if (QUANT) {
                v0 = qtf32(v0); v1 = qtf32(v1);
                v2 = qtf32(v2); v3 = qtf32(v3);
            }
            *reinterpret_cast<float2*>(C + (size_t)r * ldc + c) = make_float2(v0, v1);
            *reinterpret_cast<float2*>(C + (size_t)(r + 8) * ldc + c) = make_float2(v2, v3);
        }
    }
}

// ---------------------------------------------------------------------------
// k_convA: per-point A build via tensor cores.
//   A_n[64 x 128] = wcell_n^T [64 x 80] @ F_n [80 x 128], both streams.
//   One CTA per point, 256 threads (8 warps).
// ---------------------------------------------------------------------------
static constexpr int LDW = 84;   // 84 % 8 == 4 -> conflict-free frag loads
// FIX (round 5 IMA): gnb[80] needs 320 bytes; reserve 512 after the tiles.
static constexpr int CONVA_SMEM = (64 * LDW + 2 * 128 * LDW) * 4 + 512;

__global__ __launch_bounds__(256)
void k_convA(const float* __restrict__ fx, const float* __restrict__ fy,
             const float* __restrict__ pos, const int* __restrict__ idx,
             float* __restrict__ Abuf) {
    extern __shared__ uint32_t dsm[];
    uint32_t* sWc = dsm;                     // [64][LDW]
    uint32_t* sF  = sWc + 64 * LDW;          // [2][128][LDW]
    int* gnb      = (int*)(sF + 2 * 128 * LDW);  // [80] (512 B reserved)

    const int n = blockIdx.x;
    const int tid = threadIdx.x;
    const int w = tid >> 5, lane = tid & 31;
    const int grp = lane >> 2, qid = lane & 3;

    // zero wcell tile
    for (int i = tid; i < 64 * LDW; i += 256) sWc[i] = 0u;
    __syncthreads();

    // ---- geometry: one thread per neighbor ----
    if (tid < KN) {
        const float RAD  = 0.22499999403953552f * 0.5f;
        const float invR = 1.0f / RAD;
        float p0 = pos[3 * n], p1 = pos[3 * n + 1], p2 = pos[3 * n + 2];
        int nb = idx[n * KN + tid];
        gnb[tid] = nb;
        if (nb != n) {
            float rx = (pos[3 * nb]     - p0) * invR;
            float ry = (pos[3 * nb + 1] - p1) * invR;
            float rz = (pos[3 * nb + 2] - p2) * invR;
            float r2 = rx * rx + ry * ry + rz * rz;
            float w1 = 1.0f - r2;
            float win = fminf(fmaxf(w1 * w1 * w1, 0.0f), 1.0f);
            if (win > 0.0f) {
                float nrm  = sqrtf(fmaxf(r2, 1e-12f));
                float linf = fmaxf(fmaxf(fabsf(rx), fabsf(ry)), fabsf(rz));
                linf = fmaxf(linf, 1e-9f);
                float sc = nrm / linf;
                float gx = fminf(fmaxf((rx * sc + 1.0f) * 1.5f, 0.0f), 3.0f);
                float gy = fminf(fmaxf((ry * sc + 1.0f) * 1.5f, 0.0f), 3.0f);
                float gz = fminf(fmaxf((rz * sc + 1.0f) * 1.5f, 0.0f), 3.0f);
                float f0x = fminf(floorf(gx), 2.0f);
                float f0y = fminf(floorf(gy), 2.0f);
                float f0z = fminf(floorf(gz), 2.0f);
                float tx = gx - f0x, ty = gy - f0y, tz = gz - f0z;
                int base = (int)f0x * 16 + (int)f0y * 4 + (int)f0z;
                float wx[2] = {1.0f - tx, tx};
                float wy[2] = {1.0f - ty, ty};
                float wz[2] = {1.0f - tz, tz};
#pragma unroll
                for (int dx = 0; dx < 2; dx++)
#pragma unroll
                    for (int dy = 0; dy < 2; dy++)
#pragma unroll
                        for (int dz = 0; dz < 2; dz++) {
                            int cell = base + dx * 16 + dy * 4 + dz;
                            sWc[cell * LDW + tid] =
                                f2tf32(win * wx[dx] * wy[dy] * wz[dz]);
                        }
            }
        }
    }
    __syncthreads();

    // ---- gather: thread t<160 copies one neighbor feature row (transposed) ----
    if (tid < 2 * KN) {
        int s = tid / KN, k = tid - s * KN;
        int nb = gnb[k];
        const float* src = (s ? fy : fx) + (size_t)nb * DM;
        uint32_t* dst = sF + s * 128 * LDW;
#pragma unroll 8
        for (int c4 = 0; c4 < 32; c4++) {
            float4 v = *reinterpret_cast<const float4*>(src + c4 * 4);
            dst[(c4 * 4 + 0) * LDW + k] = f2tf32(v.x);
            dst[(c4 * 4 + 1) * LDW + k] = f2tf32(v.y);
            dst[(c4 * 4 + 2) * LDW + k] = f2tf32(v.z);
            dst[(c4 * 4 + 3) * LDW + k] = f2tf32(v.w);
        }
    }
    __syncthreads();

    // ---- mma: M=64 (cells), N=128 (channels), K=80, warp tile 32x32 ----
    const int wm = w & 1, wn = w >> 1;       // 2 x 4 warp grid
    for (int s = 0; s < 2; s++) {
        const uint32_t* sFs = sF + s * 128 * LDW;
        float acc[2][4][4];
#pragma unroll
        for (int mi = 0; mi < 2; mi++)
#pragma unroll
            for (int ni = 0; ni < 4; ni++)
#pragma unroll
                for (int q = 0; q < 4; q++) acc[mi][ni][q] = 0.0f;

#pragma unroll
        for (int ks = 0; ks < 10; ks++) {
            const int kk = ks * 8;
            uint32_t af[2][4], bf[4][2];
#pragma unroll
            for (int mi = 0; mi < 2; mi++) {
                int r = wm * 32 + mi * 16 + grp;
                af[mi][0] = sWc[r * LDW + kk + qid];
                af[mi][1] = sWc[(r + 8) * LDW + kk + qid];
                af[mi][2] = sWc[r * LDW + kk + qid + 4];
                af[mi][3] = sWc[(r + 8) * LDW + kk + qid + 4];
            }
#pragma unroll
            for (int ni = 0; ni < 4; ni++) {
                int c = wn * 32 + ni * 8 + grp;
                bf[ni][0] = sFs[c * LDW + kk + qid];
                bf[ni][1] = sFs[c * LDW + kk + qid + 4];
            }
#pragma unroll
            for (int mi = 0; mi < 2; mi++)
#pragma unroll
                for (int ni = 0; ni < 4; ni++)
                    mma_tf32(acc[mi][ni], af[mi][0], af[mi][1], af[mi][2], af[mi][3],
                             bf[ni][0], bf[ni][1]);
        }

        float* Aout = Abuf + (size_t)s * SZ_A1 + (size_t)n * 8192;
#pragma unroll
        for (int mi = 0; mi < 2; mi++) {
#pragma unroll
            for (int ni = 0; ni < 4; ni++) {
                int g = wm * 32 + mi * 16 + grp;
                int c = wn * 32 + ni * 8 + qid * 2;
                *reinterpret_cast<float2*>(Aout + (size_t)g * 128 + c) =
                    make_float2(qtf32(acc[mi][ni][0]), qtf32(acc[mi][ni][1]));
                *reinterpret_cast<float2*>(Aout + (size_t)(g + 8) * 128 + c) =
                    make_float2(qtf32(acc[mi][ni][2]), qtf32(acc[mi][ni][3]));
            }
        }
    }
}

// ---------------------------------------------------------------------------
// Flash attention (raw-bit K/V loads; inputs pre-rounded tf32)
// ---------------------------------------------------------------------------
static constexpr int FLASH_SMEM = (128 * 36 + 128 * 36 + 32 * 132 + 128 * 132) * 4;

__global__ __launch_bounds__(256)
void k_flash(const float* __restrict__ qkvbuf, float* __restrict__ obuf, float alpha) {
    constexpr int LDQ = 36, LDV = 132, LDP = 132;
    extern __shared__ uint32_t smf[];
    uint32_t* sQ = smf;
    uint32_t* sK = sQ + 128 * LDQ;
    uint32_t* sV = sK + 128 * LDQ;
    uint32_t* sP = sV + 32 * LDV;

    const int qb = blockIdx.x, head = blockIdx.y, str = blockIdx.z;
    const float* Qg = qkvbuf + (size_t)str * SZ_QKV + head * 32;
    const float* Kg = Qg + 128;
    const float* Vg = Qg + 256;

    const int tid = threadIdx.x;
    const int w = tid >> 5, lane = tid & 31;
    const int grp = lane >> 2, qid = lane & 3;

    for (int i = tid; i < 1024; i += 256) {
        int r = i >> 3, c = (i & 7) * 4;
        float4 v = *reinterpret_cast<const float4*>(
            Qg + (size_t)(qb * 128 + r) * 384 + c);
        sQ[r * LDQ + c + 0] = f2tf32(v.x * alpha);
        sQ[r * LDQ + c + 1] = f2tf32(v.y * alpha);
        sQ[r * LDQ + c + 2] = f2tf32(v.z * alpha);
        sQ[r * LDQ + c + 3] = f2tf32(v.w * alpha);
    }

    float acc[4][4];
#pragma unroll
    for (int ni = 0; ni < 4; ni++)
#pragma unroll
        for (int q = 0; q < 4; q++) acc[ni][q] = 0.0f;
    float m0 = -1e30f, m1 = -1e30f, l0 = 0.0f, l1 = 0.0f;

    const int pr0 = (w * 16 + grp) * LDP;
    const int pr1 = (w * 16 + grp + 8) * LDP;

    for (int kt = 0; kt < 32; kt++) {
        __syncthreads();
        for (int i = tid; i < 1024; i += 256) {
            int r = i >> 3, c = (i & 7) * 4;
            uint4 kv = *reinterpret_cast<const uint4*>(
                Kg + (size_t)(kt * 128 + r) * 384 + c);
            sK[r * LDQ + c + 0] = kv.x;
            sK[r * LDQ + c + 1] = kv.y;
            sK[r * LDQ + c + 2] = kv.z;
            sK[r * LDQ + c + 3] = kv.w;
            uint4 vv = *reinterpret_cast<const uint4*>(
                Vg + (size_t)(kt * 128 + r) * 384 + c);
            sV[(c + 0) * LDV + r] = vv.x;
            sV[(c + 1) * LDV + r] = vv.y;
            sV[(c + 2) * LDV + r] = vv.z;
            sV[(c + 3) * LDV + r] = vv.w;
        }
        __syncthreads();

        float s[16][4];
#pragma unroll
        for (int ni = 0; ni < 16; ni++)
#pragma unroll
            for (int q = 0; q < 4; q++) s[ni][q] = 0.0f;

#pragma unroll
        for (int ks = 0; ks < 4; ks++) {
            const int kk = ks * 8;
            const int r0 = w * 16 + grp;
            uint32_t a0 = sQ[r0 * LDQ + kk + qid];
            uint32_t a1 = sQ[(r0 + 8) * LDQ + kk + qid];
            uint32_t a2 = sQ[r0 * LDQ + kk + qid + 4];
            uint32_t a3 = sQ[(r0 + 8) * LDQ + kk + qid + 4];
#pragma unroll
            for (int ni = 0; ni < 16; ni++) {
                uint32_t b0 = sK[(ni * 8 + grp) * LDQ + kk + qid];
                uint32_t b1 = sK[(ni * 8 + grp) * LDQ + kk + qid + 4];
                mma_tf32(s[ni], a0, a1, a2, a3, b0, b1);
            }
        }

        float rm0 = -1e30f, rm1 = -1e30f;
#pragma unroll
        for (int ni = 0; ni < 16; ni++) {
            rm0 = fmaxf(rm0, fmaxf(s[ni][0], s[ni][1]));
            rm1 = fmaxf(rm1, fmaxf(s[ni][2], s[ni][3]));
        }
        rm0 = fmaxf(rm0, __shfl_xor_sync(0xffffffffu, rm0, 1));
        rm0 = fmaxf(rm0, __shfl_xor_sync(0xffffffffu, rm0, 2));
        rm1 = fmaxf(rm1, __shfl_xor_sync(0xffffffffu, rm1, 1));
        rm1 = fmaxf(rm1, __shfl_xor_sync(0xffffffffu, rm1, 2));

        float mn0 = fmaxf(m0, rm0), mn1 = fmaxf(m1, rm1);
        float c0 = __expf(m0 - mn0), c1 = __expf(m1 - mn1);
        float rs0 = 0.0f, rs1 = 0.0f;
#pragma unroll
        for (int ni = 0; ni < 16; ni++) {
            float p00 = __expf(s[ni][0] - mn0);
            float p01 = __expf(s[ni][1] - mn0);
            float p10 = __expf(s[ni][2] - mn1);
            float p11 = __expf(s[ni][3] - mn1);
            rs0 += p00 + p01;
            rs1 += p10 + p11;
            int col = ni * 8 + qid * 2;
            *reinterpret_cast<uint2*>(&sP[pr0 + col]) =
                make_uint2(f2tf32(p00), f2tf32(p01));
            *reinterpret_cast<uint2*>(&sP[pr1 + col]) =
                make_uint2(f2tf32(p10), f2tf32(p11));
        }
        rs0 += __shfl_xor_sync(0xffffffffu, rs0, 1);
        rs0 += __shfl_xor_sync(0xffffffffu, rs0, 2);
        rs1 += __shfl_xor_sync(0xffffffffu, rs1, 1);
        rs1 += __shfl_xor_sync(0xffffffffu, rs1, 2);

        l0 = l0 * c0 + rs0;
        l1 = l1 * c1 + rs1;
        m0 = mn0; m1 = mn1;
#pragma unroll
        for (int ni = 0; ni < 4; ni++) {
            acc[ni][0] *= c0; acc[ni][1] *= c0;
            acc[ni][2] *= c1; acc[ni][3] *= c1;
        }
        __syncwarp();

#pragma unroll
        for (int ks = 0; ks < 16; ks++) {
            const int kk = ks * 8;
            uint32_t a0 = sP[pr0 + kk + qid];
            uint32_t a1 = sP[pr1 + kk + qid];
            uint32_t a2 = sP[pr0 + kk + qid + 4];
            uint32_t a3 = sP[pr1 + kk + qid + 4];
#pragma unroll
            for (int ni = 0; ni < 4; ni++) {
                uint32_t b0 = sV[(ni * 8 + grp) * LDV + kk + qid];
                uint32_t b1 = sV[(ni * 8 + grp) * LDV + kk + qid + 4];
                mma_tf32(acc[ni], a0, a1, a2, a3, b0, b1);
            }
        }
    }

    float i0 = 1.0f / l0, i1 = 1.0f / l1;
    float* O = obuf + (size_t)str * SZ_ND;
    int r0 = qb * 128 + w * 16 + grp;
#pragma unroll
    for (int ni = 0; ni < 4; ni++) {
        int col = head * 32 + ni * 8 + qid * 2;
        *reinterpret_cast<float2*>(O + (size_t)r0 * DM + col) =
            make_float2(qtf32(acc[ni][0] * i0), qtf32(acc[ni][1] * i0));
        *reinterpret_cast<float2*>(O + (size_t)(r0 + 8) * DM + col) =
            make_float2(qtf32(acc[ni][2] * i1), qtf32(acc[ni][3] * i1));
    }
}

// ---------------------------------------------------------------------------
// small kernels
// ---------------------------------------------------------------------------
__global__ void k_quant(const float* __restrict__ src, float* __restrict__ dst, int n) {
    int i = blockIdx.x * 256 + threadIdx.x;
    if (i < n) dst[i] = qtf32(src[i]);
}

__global__ void k_pos_stats(const float* __restrict__ pos, float* __restrict__ st) {
    __shared__ double ss[256], sq[256];
    int t = threadIdx.x;
    double a = 0.0, b = 0.0;
    for (int i = t; i < NP; i += 256) {
        double v = (double)pos[3 * i];
        a += v; b += v * v;
    }
    ss[t] = a; sq[t] = b;
    __syncthreads();
    for (int o = 128; o > 0; o >>= 1) {
        if (t < o) { ss[t] += ss[t + o]; sq[t] += sq[t + o]; }
        __syncthreads();
    }
    if (t == 0) {
        double mean = ss[0] / NP;
        double var  = (sq[0] - ss[0] * ss[0] / NP) / (NP - 1);
        st[0] = (float)mean;
        st[1] = (float)(1.0 / (sqrt(var) + 1e-8));
    }
}

__global__ void k_posenc(const float* __restrict__ pos, const float* __restrict__ st,
                         float* __restrict__ pe) {
    int n = blockIdx.x;
    int j = threadIdx.x;
    float px  = (pos[3 * n] - st[0]) * st[1];
    float dv  = expf((float)(2 * j) * (-9.210340371976184f / 128.0f));
    float ang = px * dv;
    float s, c;
    sincosf(ang, &s, &c);
    pe[(size_t)n * DM + 2 * j]     = s;
    pe[(size_t)n * DM + 2 * j + 1] = c;
}

__global__ void k_reduce8(const float* __restrict__ part, const float* __restrict__ bx,
                          const float* __restrict__ by, float* __restrict__ out) {
    size_t i = (size_t)blockIdx.x * 256 + threadIdx.x;
    int str = (int)(i / SZ_ND);
    const float* p = part + (size_t)str * 8 * SZ_ND + (i - (size_t)str * SZ_ND);
    float v = 0.0f;
#pragma unroll
    for (int j = 0; j < 8; j++) v += p[j * SZ_ND];
    const float* bias = str ? by : bx;
    out[i] = v + bias[i & 127];
}

__global__ void k_pack_qkv(const float* __restrict__ Wq, const float* __restrict__ Wk,
                           const float* __restrict__ Wv, const float* __restrict__ bq,
                           const float* __restrict__ bk, const float* __restrict__ bv,
                           float* __restrict__ W, float* __restrict__ b) {
    int i = blockIdx.x * 256 + threadIdx.x;
    if (i < 16384) W[i] = qtf32(Wq[i]);
    else if (i < 32768) W[i] = qtf32(Wk[i - 16384]);
    else if (i < 49152) W[i] = qtf32(Wv[i - 32768]);
    if (i < 128) b[i] = bq[i];
    else if (i < 256) b[i] = bk[i - 128];
    else if (i < 384) b[i] = bv[i - 256];
}

__global__ void k_bn_stats(const float* __restrict__ h, float* __restrict__ st) {
    __shared__ float ss[256], sq[256];
    int c = blockIdx.x, str = blockIdx.y, t = threadIdx.x;
    const float* hs = h + (size_t)str * SZ_ND;
    float a = 0.f, b = 0.f;
    for (int n = t; n < NP; n += 256) {
        float v = hs[(size_t)n * DM + c];
        a += v; b += v * v;
    }
    ss[t] = a; sq[t] = b;
    __syncthreads();
    for (int o = 128; o > 0; o >>= 1) {
        if (t < o) { ss[t] += ss[t + o]; sq[t] += sq[t + o]; }
        __syncthreads();
    }
    if (t == 0) {
        float mean = ss[0] / NP;
        float var  = sq[0] / NP - mean * mean;
        st[str * 256 + c]       = mean;
        st[str * 256 + 128 + c] = rsqrtf(var + 1e-5f);
    }
}

__global__ void k_bn_apply(const float* __restrict__ conv, const float* __restrict__ st,
                           const float* __restrict__ gx, const float* __restrict__ bxp,
                           const float* __restrict__ gy, const float* __restrict__ byp,
                           const float* __restrict__ pe,
                           float* __restrict__ feat0, float* __restrict__ h) {
    size_t i = (size_t)blockIdx.x * 256 + threadIdx.x;
    int str = (int)(i / SZ_ND);
    size_t local = i - (size_t)str * SZ_ND;
    int c = (int)(i & 127);
    const float* g = str ? gy : gx;
    const float* b = str ? byp : bxp;
    const float* s = st + str * 256;
    float v = (conv[i] - s[c]) * s[128 + c] * g[c] + b[c];
    v = fmaxf(v, 0.0f);
    feat0[i] = v;
    h[i] = qtf32(v + pe[local]);     // h feeds QKV GEMM only
}

__global__ void k_ln(const float* __restrict__ a, const float* __restrict__ b,
                     const float* __restrict__ g, const float* __restrict__ beta,
                     float* __restrict__ out, int quant) {
    int r = blockIdx.x, t = threadIdx.x;
    float v = a[(size_t)r * DM + t] + b[(size_t)r * DM + t];
    float s = v, q = v * v;
#pragma unroll
    for (int o = 16; o > 0; o >>= 1) {
        s += __shfl_xor_sync(0xffffffffu, s, o);
        q += __shfl_xor_sync(0xffffffffu, q, o);
    }
    __shared__ float ws[4], wq[4];
    int w = t >> 5, lane = t & 31;
    if (lane == 0) { ws[w] = s; wq[w] = q; }
    __syncthreads();
    if (t == 0) {
        float S_ = ws[0] + ws[1] + ws[2] + ws[3];
        float Q_ = wq[0] + wq[1] + wq[2] + wq[3];
        float mean = S_ / 128.0f;
        float var  = Q_ / 128.0f - mean * mean;
        ws[0] = mean;
        wq[0] = rsqrtf(var + 1e-5f);
    }
    __syncthreads();
    float o = (v - ws[0]) * wq[0] * g[t] + beta[t];
    out[(size_t)r * DM + t] = quant ? qtf32(o) : o;
}

__global__ void k_combine(const float* __restrict__ x, const float* __restrict__ y,
                          const float* __restrict__ xf, const float* __restrict__ yf,
                          float* __restrict__ out) {
    int i = blockIdx.x * 256 + threadIdx.x;
    float z = xf[i] + yf[i];
    float s = 1.0f / (1.0f + expf(-z));
    out[i] = 2.0f * x[i] * s + 2.0f * y[i] * (1.0f - s);
}

// ---------------------------------------------------------------------------
// Launch
// ---------------------------------------------------------------------------
extern "C" void kernel_launch(void* const* d_in, const int* in_sizes, int n_in,
                              void* d_out, int out_size) {
    const float* x    = (const float*)d_in[0];
    const float* y    = (const float*)d_in[1];
    const float* pos  = (const float*)d_in[2];
    const int*   idx  = (const int*)d_in[3];
    const float* Wx   = (const float*)d_in[5];
    const float* bx   = (const float*)d_in[6];
    const float* bnxg = (const float*)d_in[7];
    const float* bnxb = (const float*)d_in[8];
    const float* Wy   = (const float*)d_in[9];
    const float* by   = (const float*)d_in[10];
    const float* bnyg = (const float*)d_in[11];
    const float* bnyb = (const float*)d_in[12];
    const float* Wq   = (const float*)d_in[13];
    const float* bq   = (const float*)d_in[14];
    const float* Wk   = (const float*)d_in[15];
    const float* bk   = (const float*)d_in[16];
    const float* Wv   = (const float*)d_in[17];
    const float* bv   = (const float*)d_in[18];
    const float* Wo   = (const float*)d_in[19];
    const float* bo   = (const float*)d_in[20];
    const float* ln1g = (const float*)d_in[21];
    const float* ln1b = (const float*)d_in[22];
    const float* W1   = (const float*)d_in[23];
    const float* b1   = (const float*)d_in[24];
    const float* W2   = (const float*)d_in[25];
    const float* b2   = (const float*)d_in[26];
    const float* ln2g = (const float*)d_in[27];
    const float* ln2b = (const float*)d_in[28];
    float* out = (float*)d_out;

    float* base = nullptr;
    cudaGetSymbolAddress((void**)&base, g_scratch);

    float* A    = base + OFF_A;
    float* pe   = base + OFF_PE;
    float* conv = base + OFF_CONV;
    float* f0   = base + OFF_F0;
    float* h    = base + OFF_H;
    float* qkv  = base + OFF_QKV;
    float* o    = base + OFF_O;
    float* tmp  = base + OFF_T;
    float* f1   = base + OFF_F1;
    float* ff   = base + OFF_FF;
    float* fo   = base + OFF_OUT;
    float* part = base + OFF_PART;
    float* Wqkv = base + OFF_WQKV;
    float* bqkv = base + OFF_WQKV + 384 * 128;
    float* Wxq  = base + OFF_WXQ;
    float* Wyq  = base + OFF_WYQ;
    float* Woq  = base + OFF_WOQ;
    float* W1q  = base + OFF_W1Q;
    float* W2q  = base + OFF_W2Q;
    float* st   = base + OFF_ST;

    // smem attributes (idempotent)
    constexpr int SMEM_NT = 2 * (128 * 36 + 128 * 36) * 4;       // TRANSB=1
    constexpr int SMEM_T0 = 2 * (128 * 36 + 32 * 136) * 4;       // TRANSB=0
    cudaFuncSetAttribute(k_mma<128, 128, 64, 32, 0, 0, 0>,
                         cudaFuncAttributeMaxDynamicSharedMemorySize, SMEM_T0);
    cudaFuncSetAttribute(k_mma<128, 128, 64, 32, 1, 0, 0>,
                         cudaFuncAttributeMaxDynamicSharedMemorySize, SMEM_NT);
    cudaFuncSetAttribute(k_mma<128, 128, 64, 32, 1, 0, 1>,
                         cudaFuncAttributeMaxDynamicSharedMemorySize, SMEM_NT);
    cudaFuncSetAttribute(k_mma<128, 128, 64, 32, 1, 1, 1>,
                         cudaFuncAttributeMaxDynamicSharedMemorySize, SMEM_NT);
    cudaFuncSetAttribute(k_convA,
                         cudaFuncAttributeMaxDynamicSharedMemorySize, CONVA_SMEM);
    cudaFuncSetAttribute(k_flash,
                         cudaFuncAttributeMaxDynamicSharedMemorySize, FLASH_SMEM);

    const float alphaS = 0.17677669529663687f;  // 1/sqrt(32)

    k_pos_stats<<<1, 256>>>(pos, st + 512);
    k_posenc<<<NP, 64>>>(pos, st + 512, pe);

    // quantized weight copies
    k_quant<<<4096, 256>>>(Wx, Wxq, 8192 * 128);
    k_quant<<<4096, 256>>>(Wy, Wyq, 8192 * 128);
    k_quant<<<64, 256>>>(Wo, Woq, 16384);
    k_quant<<<256, 256>>>(W1, W1q, 65536);
    k_quant<<<256, 256>>>(W2, W2q, 65536);
    k_pack_qkv<<<192, 256>>>(Wq, Wk, Wv, bq, bk, bv, Wqkv, bqkv);

    // A build via tensor cores (both streams)
    k_convA<<<NP, 256, CONVA_SMEM>>>(x, y, pos, idx, A);

    // conv GEMMs: split-K=8 per stream
    const float* Wcq[2] = {Wxq, Wyq};
    for (int s = 0; s < 2; s++) {
        k_mma<128, 128, 64, 32, 0, 0, 0><<<dim3(1, 32, 8), 256, SMEM_T0>>>(
            A + (size_t)s * SZ_A1, 8192, 1024,
            Wcq[s], 128, 1024LL * 128,
            part + (size_t)s * 8 * SZ_ND, 128, (long long)SZ_ND, nullptr,
            NP, 128, 1024, 1.0f);
    }
    k_reduce8<<<(2 * SZ_ND) / 256, 256>>>(part, bx, by, conv);
    k_bn_stats<<<dim3(128, 2), 256>>>(conv, st);
    k_bn_apply<<<(2 * SZ_ND) / 256, 256>>>(conv, st, bnxg, bnxb, bnyg, bnyb,
                                           pe, f0, h);

    // fused QKV, both streams (output tf32-rounded)
    k_mma<128, 128, 64, 32, 1, 0, 1><<<dim3(3, 32, 2), 256, SMEM_NT>>>(
        h, 128, (long long)SZ_ND, Wqkv, 128, 0,
        qkv, 384, (long long)SZ_QKV, bqkv, NP, 384, 128, 1.0f);

    // flash attention
    k_flash<<<dim3(32, 4, 2), 256, FLASH_SMEM>>>(qkv, o, alphaS);

    // Wo + residual + LN1 (f1 rounded for FFN GEMM)
    k_mma<128, 128, 64, 32, 1, 0, 0><<<dim3(1, 32, 2), 256, SMEM_NT>>>(
        o, 128, (long long)SZ_ND, Woq, 128, 0,
        tmp, 128, (long long)SZ_ND, bo, NP, 128, 128, 1.0f);
    k_ln<<<2 * NP, 128>>>(f0, tmp, ln1g, ln1b, f1, 1);

    // FFN
    k_mma<128, 128, 64, 32, 1, 1, 1><<<dim3(4, 32, 2), 256, SMEM_NT>>>(
        f1, 128, (long long)SZ_ND, W1q, 128, 0,
        ff, FFD, (long long)NP * FFD, b1, NP, FFD, 128, 1.0f);
    k_mma<128, 128, 64, 32, 1, 0, 0><<<dim3(1, 32, 2), 256, SMEM_NT>>>(
        ff, FFD, (long long)NP * FFD, W2q, FFD, 0,
        tmp, 128, (long long)SZ_ND, b2, NP, 128, FFD, 1.0f);
    k_ln<<<2 * NP, 128>>>(f1, tmp, ln2g, ln2b, fo, 0);

    k_combine<<<(NP * DM) / 256, 256>>>(x, y, fo, fo + SZ_ND, out);
}

// round 9
// speedup vs baseline: 4.5916x; 1.0826x over previous
#include <cuda_runtime.h>
#include <math.h>
#include <stdint.h>

// ---------------------------------------------------------------------------
// Problem constants
// ---------------------------------------------------------------------------
#define NP 4096
#define KN 80
#define DM 128
#define FFD 512

static constexpr size_t SZ_ND  = (size_t)NP * DM;              // 524288
static constexpr size_t SZ_A1  = (size_t)NP * 8192;            // per-stream A
static constexpr size_t SZ_QKV = (size_t)NP * 384;

static constexpr size_t OFF_A    = 0;
static constexpr size_t OFF_PE   = OFF_A + 2 * SZ_A1;
static constexpr size_t OFF_CONV = OFF_PE + SZ_ND;
static constexpr size_t OFF_F0   = OFF_CONV + 2 * SZ_ND;
static constexpr size_t OFF_H    = OFF_F0 + 2 * SZ_ND;
static constexpr size_t OFF_QKV  = OFF_H + 2 * SZ_ND;
static constexpr size_t OFF_O    = OFF_QKV + 2 * SZ_QKV;
static constexpr size_t OFF_T    = OFF_O + 2 * SZ_ND;
static constexpr size_t OFF_F1   = OFF_T + 2 * SZ_ND;
static constexpr size_t OFF_FF   = OFF_F1 + 2 * SZ_ND;         // 2*NP*512
static constexpr size_t OFF_OUT  = OFF_FF + 2 * (size_t)NP * FFD;
static constexpr size_t OFF_PART = OFF_OUT + 2 * SZ_ND;        // 16 partials
static constexpr size_t OFF_WQKV = OFF_PART + 16 * SZ_ND;      // 384*128 + 512
static constexpr size_t OFF_WXQ  = OFF_WQKV + 384 * 128 + 512;
static constexpr size_t OFF_WYQ  = OFF_WXQ + (size_t)8192 * 128;
static constexpr size_t OFF_WOQ  = OFF_WYQ + (size_t)8192 * 128;
static constexpr size_t OFF_W1Q  = OFF_WOQ + 16384;
static constexpr size_t OFF_W2Q  = OFF_W1Q + 65536;
static constexpr size_t OFF_ST   = OFF_W2Q + 65536;
static constexpr size_t SCRATCH_TOTAL = OFF_ST + 1024;

__device__ float g_scratch[SCRATCH_TOTAL];

// ---------------------------------------------------------------------------
// helpers
// ---------------------------------------------------------------------------
__device__ __forceinline__ uint32_t f2tf32(float x) {
    float r;
    asm("cvt.rna.tf32.f32 %0, %1;" : "=f"(r) : "f"(x));
    return __float_as_uint(r);
}
__device__ __forceinline__ float qtf32(float x) {
    return __uint_as_float(f2tf32(x));
}

__device__ __forceinline__ void mma_tf32(float c[4],
                                         uint32_t a0, uint32_t a1, uint32_t a2, uint32_t a3,
                                         uint32_t b0, uint32_t b1) {
    asm volatile(
        "mma.sync.aligned.m16n8k8.row.col.f32.tf32.tf32.f32 "
        "{%0,%1,%2,%3}, {%4,%5,%6,%7}, {%8,%9}, {%0,%1,%2,%3};\n"
        : "+f"(c[0]), "+f"(c[1]), "+f"(c[2]), "+f"(c[3])
        : "r"(a0), "r"(a1), "r"(a2), "r"(a3), "r"(b0), "r"(b1));
}

__device__ __forceinline__ void cp16(uint32_t s, const void* g) {
    asm volatile("cp.async.ca.shared.global [%0], [%1], 16;\n" :: "r"(s), "l"(g));
}
__device__ __forceinline__ void cp_commit() {
    asm volatile("cp.async.commit_group;\n");
}
template <int N>
__device__ __forceinline__ void cp_wait() {
    asm volatile("cp.async.wait_group %0;\n" :: "n"(N));
}

// ---------------------------------------------------------------------------
// tf32 GEMM: cp.async double-buffered, cvt-free (inputs pre-rounded tf32)
// ---------------------------------------------------------------------------
template <int BM, int BN, int WM, int WN, int TRANSB, int ACT, int QUANT>
__global__ __launch_bounds__((BM / WM) * (BN / WN) * 32)
void k_mma(const float* __restrict__ A, int lda, long long strideA,
           const float* __restrict__ B, int ldb, long long strideB,
           float* __restrict__ C, int ldc, long long strideC,
           const float* __restrict__ bias,
           int M, int N, int K, float alpha) {
    constexpr int MI = WM / 16;
    constexpr int NI = WN / 8;
    constexpr int NWARP = (BM / WM) * (BN / WN);
    constexpr int NT = NWARP * 32;
    constexpr int LDA = 36;
    constexpr int LDB = TRANSB ? 36 : (BN + 8);
    constexpr int SA = BM * LDA;
    constexpr int SB = TRANSB ? (BN * LDB) : (32 * LDB);

    extern __shared__ uint32_t sm[];
    uint32_t* sAst[2] = {sm, sm + SA + SB};
    uint32_t* sBst[2] = {sm + SA, sm + SA + SB + SA};

    A += (size_t)blockIdx.z * strideA;
    B += (size_t)blockIdx.z * strideB;
    C += (size_t)blockIdx.z * strideC;

    const int n0 = blockIdx.x * BN;
    const int m0 = blockIdx.y * BM;
    const int tid = threadIdx.x;
    const int w = tid >> 5, lane = tid & 31;
    const int grp = lane >> 2, qid = lane & 3;
    const int wm = w % (BM / WM), wn = w / (BM / WM);

    const uint32_t smem_base = (uint32_t)__cvta_generic_to_shared(sm);

    auto load_tile = [&](int st, int k0) {
        uint32_t aBase = smem_base + (uint32_t)(st * (SA + SB)) * 4u;
        uint32_t bBase = aBase + (uint32_t)SA * 4u;
#pragma unroll
        for (int i = tid; i < BM * 8; i += NT) {
            int r = i >> 3, c4 = (i & 7) * 4;
            cp16(aBase + (uint32_t)(r * LDA + c4) * 4u,
                 A + (size_t)(m0 + r) * lda + k0 + c4);
        }
        if (TRANSB == 1) {
#pragma unroll
            for (int i = tid; i < BN * 8; i += NT) {
                int r = i >> 3, c4 = (i & 7) * 4;
                cp16(bBase + (uint32_t)(r * LDB + c4) * 4u,
                     B + (size_t)(n0 + r) * ldb + k0 + c4);
            }
        } else {
#pragma unroll
            for (int i = tid; i < 32 * (BN / 4); i += NT) {
                int kr = i / (BN / 4);
                int n4 = (i % (BN / 4)) * 4;
                cp16(bBase + (uint32_t)(kr * LDB + n4) * 4u,
                     B + (size_t)(k0 + kr) * ldb + n0 + n4);
            }
        }
        cp_commit();
    };

    float acc[MI][NI][4];
#pragma unroll
    for (int i = 0; i < MI; i++)
#pragma unroll
        for (int j = 0; j < NI; j++)
#pragma unroll
            for (int q = 0; q < 4; q++) acc[i][j][q] = 0.0f;

    const int KT = K / 32;
    load_tile(0, 0);

    for (int kt = 0; kt < KT; kt++) {
        if (kt + 1 < KT) {
            load_tile((kt + 1) & 1, (kt + 1) * 32);
            cp_wait<1>();
        } else {
            cp_wait<0>();
        }
        __syncthreads();

        const uint32_t* sA = sAst[kt & 1];
        const uint32_t* sB = sBst[kt & 1];

#pragma unroll
        for (int ks = 0; ks < 4; ks++) {
            const int kk = ks * 8;
            uint32_t af[MI][4], bf[NI][2];
#pragma unroll
            for (int mi = 0; mi < MI; mi++) {
                int r = wm * WM + mi * 16 + grp;
                af[mi][0] = sA[r * LDA + kk + qid];
                af[mi][1] = sA[(r + 8) * LDA + kk + qid];
                af[mi][2] = sA[r * LDA + kk + qid + 4];
                af[mi][3] = sA[(r + 8) * LDA + kk + qid + 4];
            }
#pragma unroll
            for (int ni = 0; ni < NI; ni++) {
                int c = wn * WN + ni * 8 + grp;
                if (TRANSB == 1) {
                    bf[ni][0] = sB[c * LDB + kk + qid];
                    bf[ni][1] = sB[c * LDB + kk + qid + 4];
                } else {
                    bf[ni][0] = sB[(kk + qid) * LDB + c];
                    bf[ni][1] = sB[(kk + qid + 4) * LDB + c];
                }
            }
#pragma unroll
            for (int mi = 0; mi < MI; mi++)
#pragma unroll
                for (int ni = 0; ni < NI; ni++)
                    mma_tf32(acc[mi][ni], af[mi][0], af[mi][1], af[mi][2], af[mi][3],
                             bf[ni][0], bf[ni][1]);
        }
        __syncthreads();
    }

#pragma unroll
    for (int mi = 0; mi < MI; mi++) {
#pragma unroll
        for (int ni = 0; ni < NI; ni++) {
            int r = m0 + wm * WM + mi * 16 + grp;
            int c = n0 + wn * WN + ni * 8 + qid * 2;
            float b0 = 0.f, b1 = 0.f;
            if (bias) { b0 = bias[c]; b1 = bias[c + 1]; }
            float v0 = acc[mi][ni][0] * alpha + b0;
            float v1 = acc[mi][ni][1] * alpha + b1;
            float v2 = acc[mi][ni][2] * alpha + b0;
            float v3 = acc[mi][ni][3] * alpha + b1;
            if (ACT) {
                v0 = fmaxf(v0, 0.f); v1 = fmaxf(v1, 0.f);
                v2 = fmaxf(v2, 0.f); v3 = fmaxf(v3, 0.f);
            }
            if (QUANT) {
                v0 = qtf32(v0); v1 = qtf32(v1);
                v2 = qtf32(v2); v3 = qtf32(v3);
            }
            *reinterpret_cast<float2*>(C + (size_t)r * ldc + c) = make_float2(v0, v1);
            *reinterpret_cast<float2*>(C + (size_t)(r + 8) * ldc + c) = make_float2(v2, v3);
        }
    }
}

// ---------------------------------------------------------------------------
// k_convA: per-point A build via tensor cores (both streams).
// ---------------------------------------------------------------------------
static constexpr int LDW = 84;
static constexpr int CONVA_SMEM = (64 * LDW + 2 * 128 * LDW) * 4 + 512;

__global__ __launch_bounds__(256, 2)
void k_convA(const float* __restrict__ fx, const float* __restrict__ fy,
             const float* __restrict__ pos, const int* __restrict__ idx,
             float* __restrict__ Abuf) {
    extern __shared__ uint32_t dsm[];
    uint32_t* sWc = dsm;                     // [64][LDW]
    uint32_t* sF  = sWc + 64 * LDW;          // [2][128][LDW]
    int* gnb      = (int*)(sF + 2 * 128 * LDW);  // [80]

    const int n = blockIdx.x;
    const int tid = threadIdx.x;
    const int w = tid >> 5, lane = tid & 31;
    const int grp = lane >> 2, qid = lane & 3;

    for (int i = tid; i < 64 * LDW; i += 256) sWc[i] = 0u;
    __syncthreads();

    if (tid < KN) {
        const float RAD  = 0.22499999403953552f * 0.5f;
        const float invR = 1.0f / RAD;
        float p0 = pos[3 * n], p1 = pos[3 * n + 1], p2 = pos[3 * n + 2];
        int nb = idx[n * KN + tid];
        gnb[tid] = nb;
        if (nb != n) {
            float rx = (pos[3 * nb]     - p0) * invR;
            float ry = (pos[3 * nb + 1] - p1) * invR;
            float rz = (pos[3 * nb + 2] - p2) * invR;
            float r2 = rx * rx + ry * ry + rz * rz;
            float w1 = 1.0f - r2;
            float win = fminf(fmaxf(w1 * w1 * w1, 0.0f), 1.0f);
            if (win > 0.0f) {
                float nrm  = sqrtf(fmaxf(r2, 1e-12f));
                float linf = fmaxf(fmaxf(fabsf(rx), fabsf(ry)), fabsf(rz));
                linf = fmaxf(linf, 1e-9f);
                float sc = nrm / linf;
                float gx = fminf(fmaxf((rx * sc + 1.0f) * 1.5f, 0.0f), 3.0f);
                float gy = fminf(fmaxf((ry * sc + 1.0f) * 1.5f, 0.0f), 3.0f);
                float gz = fminf(fmaxf((rz * sc + 1.0f) * 1.5f, 0.0f), 3.0f);
                float f0x = fminf(floorf(gx), 2.0f);
                float f0y = fminf(floorf(gy), 2.0f);
                float f0z = fminf(floorf(gz), 2.0f);
                float tx = gx - f0x, ty = gy - f0y, tz = gz - f0z;
                int base = (int)f0x * 16 + (int)f0y * 4 + (int)f0z;
                float wx[2] = {1.0f - tx, tx};
                float wy[2] = {1.0f - ty, ty};
                float wz[2] = {1.0f - tz, tz};
#pragma unroll
                for (int dx = 0; dx < 2; dx++)
#pragma unroll
                    for (int dy = 0; dy < 2; dy++)
#pragma unroll
                        for (int dz = 0; dz < 2; dz++) {
                            int cell = base + dx * 16 + dy * 4 + dz;
                            sWc[cell * LDW + tid] =
                                f2tf32(win * wx[dx] * wy[dy] * wz[dz]);
                        }
            }
        }
    }
    __syncthreads();

    // gather: 320 half-row tasks over 256 threads
    for (int t = tid; t < 320; t += 256) {
        int half = t & 1, row = t >> 1;
        int s = row / KN, k = row - s * KN;
        int nb = gnb[k];
        const float* src = (s ? fy : fx) + (size_t)nb * DM + half * 64;
        uint32_t* dst = sF + s * 128 * LDW;
#pragma unroll 4
        for (int c4 = 0; c4 < 16; c4++) {
            float4 v = *reinterpret_cast<const float4*>(src + c4 * 4);
            int c = half * 64 + c4 * 4;
            dst[(c + 0) * LDW + k] = f2tf32(v.x);
            dst[(c + 1) * LDW + k] = f2tf32(v.y);
            dst[(c + 2) * LDW + k] = f2tf32(v.z);
            dst[(c + 3) * LDW + k] = f2tf32(v.w);
        }
    }
    __syncthreads();

    const int wm = w & 1, wn = w >> 1;
    for (int s = 0; s < 2; s++) {
        const uint32_t* sFs = sF + s * 128 * LDW;
        float acc[2][4][4];
#pragma unroll
        for (int mi = 0; mi < 2; mi++)
#pragma unroll
            for (int ni = 0; ni < 4; ni++)
#pragma unroll
                for (int q = 0; q < 4; q++) acc[mi][ni][q] = 0.0f;

#pragma unroll
        for (int ks = 0; ks < 10; ks++) {
            const int kk = ks * 8;
            uint32_t af[2][4], bf[4][2];
#pragma unroll
            for (int mi = 0; mi < 2; mi++) {
                int r = wm * 32 + mi * 16 + grp;
                af[mi][0] = sWc[r * LDW + kk + qid];
                af[mi][1] = sWc[(r + 8) * LDW + kk + qid];
                af[mi][2] = sWc[r * LDW + kk + qid + 4];
                af[mi][3] = sWc[(r + 8) * LDW + kk + qid + 4];
            }
#pragma unroll
            for (int ni = 0; ni < 4; ni++) {
                int c = wn * 32 + ni * 8 + grp;
                bf[ni][0] = sFs[c * LDW + kk + qid];
                bf[ni][1] = sFs[c * LDW + kk + qid + 4];
            }
#pragma unroll
            for (int mi = 0; mi < 2; mi++)
#pragma unroll
                for (int ni = 0; ni < 4; ni++)
                    mma_tf32(acc[mi][ni], af[mi][0], af[mi][1], af[mi][2], af[mi][3],
                             bf[ni][0], bf[ni][1]);
        }

        float* Aout = Abuf + (size_t)s * SZ_A1 + (size_t)n * 8192;
#pragma unroll
        for (int mi = 0; mi < 2; mi++) {
#pragma unroll
            for (int ni = 0; ni < 4; ni++) {
                int g = wm * 32 + mi * 16 + grp;
                int c = wn * 32 + ni * 8 + qid * 2;
                *reinterpret_cast<float2*>(Aout + (size_t)g * 128 + c) =
                    make_float2(qtf32(acc[mi][ni][0]), qtf32(acc[mi][ni][1]));
                *reinterpret_cast<float2*>(Aout + (size_t)(g + 8) * 128 + c) =
                    make_float2(qtf32(acc[mi][ni][2]), qtf32(acc[mi][ni][3]));
            }
        }
    }
}

// ---------------------------------------------------------------------------
// Flash attention v2: no sP — within-warp shfl transpose of P fragments.
// smem = sQ + sK + sV = 53.8 KB -> 2 CTAs/SM, all 256 CTAs in one wave.
// ---------------------------------------------------------------------------
static constexpr int FLASH_SMEM = (128 * 36 + 128 * 36 + 32 * 132) * 4;

__global__ __launch_bounds__(256, 2)
void k_flash(const float* __restrict__ qkvbuf, float* __restrict__ obuf, float alpha) {
    constexpr int LDQ = 36, LDV = 132;
    extern __shared__ uint32_t smf[];
    uint32_t* sQ = smf;
    uint32_t* sK = sQ + 128 * LDQ;
    uint32_t* sV = sK + 128 * LDQ;

    const int qb = blockIdx.x, head = blockIdx.y, str = blockIdx.z;
    const float* Qg = qkvbuf + (size_t)str * SZ_QKV + head * 32;
    const float* Kg = Qg + 128;
    const float* Vg = Qg + 256;

    const int tid = threadIdx.x;
    const int w = tid >> 5, lane = tid & 31;
    const int grp = lane >> 2, qid = lane & 3;
    const unsigned FULL = 0xffffffffu;
    const int srcA = (lane & 28) | (qid >> 1);   // base + qid/2
    const int srcB = srcA + 2;
    const bool odd = (qid & 1);

    for (int i = tid; i < 1024; i += 256) {
        int r = i >> 3, c = (i & 7) * 4;
        float4 v = *reinterpret_cast<const float4*>(
            Qg + (size_t)(qb * 128 + r) * 384 + c);
        sQ[r * LDQ + c + 0] = f2tf32(v.x * alpha);
        sQ[r * LDQ + c + 1] = f2tf32(v.y * alpha);
        sQ[r * LDQ + c + 2] = f2tf32(v.z * alpha);
        sQ[r * LDQ + c + 3] = f2tf32(v.w * alpha);
    }

    float acc[4][4];
#pragma unroll
    for (int ni = 0; ni < 4; ni++)
#pragma unroll
        for (int q = 0; q < 4; q++) acc[ni][q] = 0.0f;
    float m0 = -1e30f, m1 = -1e30f, l0 = 0.0f, l1 = 0.0f;

    for (int kt = 0; kt < 32; kt++) {
        __syncthreads();
        for (int i = tid; i < 1024; i += 256) {
            int r = i >> 3, c = (i & 7) * 4;
            uint4 kv = *reinterpret_cast<const uint4*>(
                Kg + (size_t)(kt * 128 + r) * 384 + c);
            sK[r * LDQ + c + 0] = kv.x;
            sK[r * LDQ + c + 1] = kv.y;
            sK[r * LDQ + c + 2] = kv.z;
            sK[r * LDQ + c + 3] = kv.w;
            uint4 vv = *reinterpret_cast<const uint4*>(
                Vg + (size_t)(kt * 128 + r) * 384 + c);
            sV[(c + 0) * LDV + r] = vv.x;
            sV[(c + 1) * LDV + r] = vv.y;
            sV[(c + 2) * LDV + r] = vv.z;
            sV[(c + 3) * LDV + r] = vv.w;
        }
        __syncthreads();

        float s[16][4];
#pragma unroll
        for (int ni = 0; ni < 16; ni++)
#pragma unroll
            for (int q = 0; q < 4; q++) s[ni][q] = 0.0f;

#pragma unroll
        for (int ks = 0; ks < 4; ks++) {
            const int kk = ks * 8;
            const int r0 = w * 16 + grp;
            uint32_t a0 = sQ[r0 * LDQ + kk + qid];
            uint32_t a1 = sQ[(r0 + 8) * LDQ + kk + qid];
            uint32_t a2 = sQ[r0 * LDQ + kk + qid + 4];
            uint32_t a3 = sQ[(r0 + 8) * LDQ + kk + qid + 4];
#pragma unroll
            for (int ni = 0; ni < 16; ni++) {
                uint32_t b0 = sK[(ni * 8 + grp) * LDQ + kk + qid];
                uint32_t b1 = sK[(ni * 8 + grp) * LDQ + kk + qid + 4];
                mma_tf32(s[ni], a0, a1, a2, a3, b0, b1);
            }
        }

        // ---- online softmax (P kept in registers, tf32-rounded) ----
        float rm0 = -1e30f, rm1 = -1e30f;
#pragma unroll
        for (int ni = 0; ni < 16; ni++) {
            rm0 = fmaxf(rm0, fmaxf(s[ni][0], s[ni][1]));
            rm1 = fmaxf(rm1, fmaxf(s[ni][2], s[ni][3]));
        }
        rm0 = fmaxf(rm0, __shfl_xor_sync(FULL, rm0, 1));
        rm0 = fmaxf(rm0, __shfl_xor_sync(FULL, rm0, 2));
        rm1 = fmaxf(rm1, __shfl_xor_sync(FULL, rm1, 1));
        rm1 = fmaxf(rm1, __shfl_xor_sync(FULL, rm1, 2));

        float mn0 = fmaxf(m0, rm0), mn1 = fmaxf(m1, rm1);
        float c0 = __expf(m0 - mn0), c1 = __expf(m1 - mn1);
        float rs0 = 0.0f, rs1 = 0.0f;
#pragma unroll
        for (int ni = 0; ni < 16; ni++) {
            float p00 = __expf(s[ni][0] - mn0);
            float p01 = __expf(s[ni][1] - mn0);
            float p10 = __expf(s[ni][2] - mn1);
            float p11 = __expf(s[ni][3] - mn1);
            rs0 += p00 + p01;
            rs1 += p10 + p11;
            s[ni][0] = qtf32(p00);
            s[ni][1] = qtf32(p01);
            s[ni][2] = qtf32(p10);
            s[ni][3] = qtf32(p11);
        }
        rs0 += __shfl_xor_sync(FULL, rs0, 1);
        rs0 += __shfl_xor_sync(FULL, rs0, 2);
        rs1 += __shfl_xor_sync(FULL, rs1, 1);
        rs1 += __shfl_xor_sync(FULL, rs1, 2);

        l0 = l0 * c0 + rs0;
        l1 = l1 * c1 + rs1;
        m0 = mn0; m1 = mn1;
#pragma unroll
        for (int ni = 0; ni < 4; ni++) {
            acc[ni][0] *= c0; acc[ni][1] *= c0;
            acc[ni][2] *= c1; acc[ni][3] *= c1;
        }

        // ---- O += P V with shfl-transposed P fragments ----
#pragma unroll
        for (int ks = 0; ks < 16; ks++) {
            float v0 = __shfl_sync(FULL, s[ks][0], srcA);
            float v1 = __shfl_sync(FULL, s[ks][1], srcA);
            float v2 = __shfl_sync(FULL, s[ks][2], srcA);
            float v3 = __shfl_sync(FULL, s[ks][3], srcA);
            float w0 = __shfl_sync(FULL, s[ks][0], srcB);
            float w1 = __shfl_sync(FULL, s[ks][1], srcB);
            float w2 = __shfl_sync(FULL, s[ks][2], srcB);
            float w3 = __shfl_sync(FULL, s[ks][3], srcB);
            uint32_t a0 = __float_as_uint(odd ? v1 : v0);
            uint32_t a1 = __float_as_uint(odd ? v3 : v2);
            uint32_t a2 = __float_as_uint(odd ? w1 : w0);
            uint32_t a3 = __float_as_uint(odd ? w3 : w2);
            const int kk = ks * 8;
#pragma unroll
            for (int ni = 0; ni < 4; ni++) {
                uint32_t b0 = sV[(ni * 8 + grp) * LDV + kk + qid];
                uint32_t b1 = sV[(ni * 8 + grp) * LDV + kk + qid + 4];
                mma_tf32(acc[ni], a0, a1, a2, a3, b0, b1);
            }
        }
    }

    float i0 = 1.0f / l0, i1 = 1.0f / l1;
    float* O = obuf + (size_t)str * SZ_ND;
    int r0 = qb * 128 + w * 16 + grp;
#pragma unroll
    for (int ni = 0; ni < 4; ni++) {
        int col = head * 32 + ni * 8 + qid * 2;
        *reinterpret_cast<float2*>(O + (size_t)r0 * DM + col) =
            make_float2(qtf32(acc[ni][0] * i0), qtf32(acc[ni][1] * i0));
        *reinterpret_cast<float2*>(O + (size_t)(r0 + 8) * DM + col) =
            make_float2(qtf32(acc[ni][2] * i1), qtf32(acc[ni][3] * i1));
    }
}

// ---------------------------------------------------------------------------
// merged weight prep: quantize Wx/Wy/Wo/W1/W2 + pack&quantize Wqkv + biases
// ---------------------------------------------------------------------------
__global__ void k_prep(const float* __restrict__ Wx, const float* __restrict__ Wy,
                       const float* __restrict__ Wo, const float* __restrict__ W1,
                       const float* __restrict__ W2,
                       const float* __restrict__ Wq, const float* __restrict__ Wk,
                       const float* __restrict__ Wv, const float* __restrict__ bq,
                       const float* __restrict__ bk, const float* __restrict__ bv,
                       float* __restrict__ base) {
    const int NWX = 1048576;
    size_t i = (size_t)blockIdx.x * 256 + threadIdx.x;
    size_t total = 2 * (size_t)NWX + 16384 + 65536 + 65536 + 49152 + 384;
    for (; i < total; i += (size_t)gridDim.x * 256) {
        size_t j = i;
        if (j < NWX) { base[OFF_WXQ + j] = qtf32(Wx[j]); continue; }
        j -= NWX;
        if (j < NWX) { base[OFF_WYQ + j] = qtf32(Wy[j]); continue; }
        j -= NWX;
        if (j < 16384) { base[OFF_WOQ + j] = qtf32(Wo[j]); continue; }
        j -= 16384;
        if (j < 65536) { base[OFF_W1Q + j] = qtf32(W1[j]); continue; }
        j -= 65536;
        if (j < 65536) { base[OFF_W2Q + j] = qtf32(W2[j]); continue; }
        j -= 65536;
        if (j < 49152) {
            float v = (j < 16384) ? Wq[j] : (j < 32768) ? Wk[j - 16384]
                                                        : Wv[j - 32768];
            base[OFF_WQKV + j] = qtf32(v);
            continue;
        }
        j -= 49152;
        float bvv = (j < 128) ? bq[j] : (j < 256) ? bk[j - 128] : bv[j - 256];
        base[OFF_WQKV + 384 * 128 + j] = bvv;
    }
}

// ---------------------------------------------------------------------------
// small kernels
// ---------------------------------------------------------------------------
__global__ void k_pos_stats(const float* __restrict__ pos, float* __restrict__ st) {
    __shared__ double ss[256], sq[256];
    int t = threadIdx.x;
    double a = 0.0, b = 0.0;
    for (int i = t; i < NP; i += 256) {
        double v = (double)pos[3 * i];
        a += v; b += v * v;
    }
    ss[t] = a; sq[t] = b;
    __syncthreads();
    for (int o = 128; o > 0; o >>= 1) {
        if (t < o) { ss[t] += ss[t + o]; sq[t] += sq[t + o]; }
        __syncthreads();
    }
    if (t == 0) {
        double mean = ss[0] / NP;
        double var  = (sq[0] - ss[0] * ss[0] / NP) / (NP - 1);
        st[0] = (float)mean;
        st[1] = (float)(1.0 / (sqrt(var) + 1e-8));
    }
}

__global__ void k_posenc(const float* __restrict__ pos, const float* __restrict__ st,
                         float* __restrict__ pe) {
    int n = blockIdx.x;
    int j = threadIdx.x;
    float px  = (pos[3 * n] - st[0]) * st[1];
    float dv  = expf((float)(2 * j) * (-9.210340371976184f / 128.0f));
    float ang = px * dv;
    float s, c;
    sincosf(ang, &s, &c);
    pe[(size_t)n * DM + 2 * j]     = s;
    pe[(size_t)n * DM + 2 * j + 1] = c;
}

__global__ void k_reduce8(const float* __restrict__ part, const float* __restrict__ bx,
                          const float* __restrict__ by, float* __restrict__ out) {
    size_t i = (size_t)blockIdx.x * 256 + threadIdx.x;
    int str = (int)(i / SZ_ND);
    const float* p = part + (size_t)str * 8 * SZ_ND + (i - (size_t)str * SZ_ND);
    float v = 0.0f;
#pragma unroll
    for (int j = 0; j < 8; j++) v += p[j * SZ_ND];
    const float* bias = str ? by : bx;
    out[i] = v + bias[i & 127];
}

__global__ void k_bn_stats(const float* __restrict__ h, float* __restrict__ st) {
    __shared__ float ss[256], sq[256];
    int c = blockIdx.x, str = blockIdx.y, t = threadIdx.x;
    const float* hs = h + (size_t)str * SZ_ND;
    float a = 0.f, b = 0.f;
    for (int n = t; n < NP; n += 256) {
        float v = hs[(size_t)n * DM + c];
        a += v; b += v * v;
    }
    ss[t] = a; sq[t] = b;
    __syncthreads();
    for (int o = 128; o > 0; o >>= 1) {
        if (t < o) { ss[t] += ss[t + o]; sq[t] += sq[t + o]; }
        __syncthreads();
    }
    if (t == 0) {
        float mean = ss[0] / NP;
        float var  = sq[0] / NP - mean * mean;
        st[str * 256 + c]       = mean;
        st[str * 256 + 128 + c] = rsqrtf(var + 1e-5f);
    }
}

__global__ void k_bn_apply(const float* __restrict__ conv, const float* __restrict__ st,
                           const float* __restrict__ gx, const float* __restrict__ bxp,
                           const float* __restrict__ gy, const float* __restrict__ byp,
                           const float* __restrict__ pe,
                           float* __restrict__ feat0, float* __restrict__ h) {
    size_t i = (size_t)blockIdx.x * 256 + threadIdx.x;
    int str = (int)(i / SZ_ND);
    size_t local = i - (size_t)str * SZ_ND;
    int c = (int)(i & 127);
    const float* g = str ? gy : gx;
    const float* b = str ? byp : bxp;
    const float* s = st + str * 256;
    float v = (conv[i] - s[c]) * s[128 + c] * g[c] + b[c];
    v = fmaxf(v, 0.0f);
    feat0[i] = v;
    h[i] = qtf32(v + pe[local]);
}

__global__ void k_ln(const float* __restrict__ a, const float* __restrict__ b,
                     const float* __restrict__ g, const float* __restrict__ beta,
                     float* __restrict__ out, int quant) {
    int r = blockIdx.x, t = threadIdx.x;
    float v = a[(size_t)r * DM + t] + b[(size_t)r * DM + t];
    float s = v, q = v * v;
#pragma unroll
    for (int o = 16; o > 0; o >>= 1) {
        s += __shfl_xor_sync(0xffffffffu, s, o);
        q += __shfl_xor_sync(0xffffffffu, q, o);
    }
    __shared__ float ws[4], wq[4];
    int w = t >> 5, lane = t & 31;
    if (lane == 0) { ws[w] = s; wq[w] = q; }
    __syncthreads();
    if (t == 0) {
        float S_ = ws[0] + ws[1] + ws[2] + ws[3];
        float Q_ = wq[0] + wq[1] + wq[2] + wq[3];
        float mean = S_ / 128.0f;
        float var  = Q_ / 128.0f - mean * mean;
        ws[0] = mean;
        wq[0] = rsqrtf(var + 1e-5f);
    }
    __syncthreads();
    float o = (v - ws[0]) * wq[0] * g[t] + beta[t];
    out[(size_t)r * DM + t] = quant ? qtf32(o) : o;
}

__global__ void k_combine(const float* __restrict__ x, const float* __restrict__ y,
                          const float* __restrict__ xf, const float* __restrict__ yf,
                          float* __restrict__ out) {
    int i = blockIdx.x * 256 + threadIdx.x;
    float z = xf[i] + yf[i];
    float s = 1.0f / (1.0f + expf(-z));
    out[i] = 2.0f * x[i] * s + 2.0f * y[i] * (1.0f - s);
}

// ---------------------------------------------------------------------------
// Launch
// ---------------------------------------------------------------------------
extern "C" void kernel_launch(void* const* d_in, const int* in_sizes, int n_in,
                              void* d_out, int out_size) {
    const float* x    = (const float*)d_in[0];
    const float* y    = (const float*)d_in[1];
    const float* pos  = (const float*)d_in[2];
    const int*   idx  = (const int*)d_in[3];
    const float* Wx   = (const float*)d_in[5];
    const float* bx   = (const float*)d_in[6];
    const float* bnxg = (const float*)d_in[7];
    const float* bnxb = (const float*)d_in[8];
    const float* Wy   = (const float*)d_in[9];
    const float* by   = (const float*)d_in[10];
    const float* bnyg = (const float*)d_in[11];
    const float* bnyb = (const float*)d_in[12];
    const float* Wq   = (const float*)d_in[13];
    const float* bq   = (const float*)d_in[14];
    const float* Wk   = (const float*)d_in[15];
    const float* bk   = (const float*)d_in[16];
    const float* Wv   = (const float*)d_in[17];
    const float* bv   = (const float*)d_in[18];
    const float* Wo   = (const float*)d_in[19];
    const float* bo   = (const float*)d_in[20];
    const float* ln1g = (const float*)d_in[21];
    const float* ln1b = (const float*)d_in[22];
    const float* W1   = (const float*)d_in[23];
    const float* b1   = (const float*)d_in[24];
    const float* W2   = (const float*)d_in[25];
    const float* b2   = (const float*)d_in[26];
    const float* ln2g = (const float*)d_in[27];
    const float* ln2b = (const float*)d_in[28];
    float* out = (float*)d_out;

    float* base = nullptr;
    cudaGetSymbolAddress((void**)&base, g_scratch);

    float* A    = base + OFF_A;
    float* pe   = base + OFF_PE;
    float* conv = base + OFF_CONV;
    float* f0   = base + OFF_F0;
    float* h    = base + OFF_H;
    float* qkv  = base + OFF_QKV;
    float* o    = base + OFF_O;
    float* tmp  = base + OFF_T;
    float* f1   = base + OFF_F1;
    float* ff   = base + OFF_FF;
    float* fo   = base + OFF_OUT;
    float* part = base + OFF_PART;
    float* Wqkv = base + OFF_WQKV;
    float* bqkv = base + OFF_WQKV + 384 * 128;
    float* Wxq  = base + OFF_WXQ;
    float* Wyq  = base + OFF_WYQ;
    float* Woq  = base + OFF_WOQ;
    float* W1q  = base + OFF_W1Q;
    float* W2q  = base + OFF_W2Q;
    float* st   = base + OFF_ST;

    constexpr int SMEM_NT = 2 * (128 * 36 + 128 * 36) * 4;
    constexpr int SMEM_T0 = 2 * (128 * 36 + 32 * 136) * 4;
    cudaFuncSetAttribute(k_mma<128, 128, 64, 32, 0, 0, 0>,
                         cudaFuncAttributeMaxDynamicSharedMemorySize, SMEM_T0);
    cudaFuncSetAttribute(k_mma<128, 128, 64, 32, 1, 0, 0>,
                         cudaFuncAttributeMaxDynamicSharedMemorySize, SMEM_NT);
    cudaFuncSetAttribute(k_mma<128, 128, 64, 32, 1, 0, 1>,
                         cudaFuncAttributeMaxDynamicSharedMemorySize, SMEM_NT);
    cudaFuncSetAttribute(k_mma<128, 128, 64, 32, 1, 1, 1>,
                         cudaFuncAttributeMaxDynamicSharedMemorySize, SMEM_NT);
    cudaFuncSetAttribute(k_convA,
                         cudaFuncAttributeMaxDynamicSharedMemorySize, CONVA_SMEM);
    cudaFuncSetAttribute(k_flash,
                         cudaFuncAttributeMaxDynamicSharedMemorySize, FLASH_SMEM);

    const float alphaS = 0.17677669529663687f;  // 1/sqrt(32)

    // launch order chosen so the ncu -s 5 -c 1 slot (#6) hits the conv GEMM
    k_prep<<<2048, 256>>>(Wx, Wy, Wo, W1, W2, Wq, Wk, Wv, bq, bk, bv, base); // 1
    k_pos_stats<<<1, 256>>>(pos, st + 512);                                  // 2
    k_posenc<<<NP, 64>>>(pos, st + 512, pe);                                 // 3
    k_convA<<<NP, 256, CONVA_SMEM>>>(x, y, pos, idx, A);                     // 4

    const float* Wcq[2] = {Wxq, Wyq};
    for (int s = 0; s < 2; s++) {                                            // 5, 6
        k_mma<128, 128, 64, 32, 0, 0, 0><<<dim3(1, 32, 8), 256, SMEM_T0>>>(
            A + (size_t)s * SZ_A1, 8192, 1024,
            Wcq[s], 128, 1024LL * 128,
            part + (size_t)s * 8 * SZ_ND, 128, (long long)SZ_ND, nullptr,
            NP, 128, 1024, 1.0f);
    }
    k_reduce8<<<(2 * SZ_ND) / 256, 256>>>(part, bx, by, conv);
    k_bn_stats<<<dim3(128, 2), 256>>>(conv, st);
    k_bn_apply<<<(2 * SZ_ND) / 256, 256>>>(conv, st, bnxg, bnxb, bnyg, bnyb,
                                           pe, f0, h);

    k_mma<128, 128, 64, 32, 1, 0, 1><<<dim3(3, 32, 2), 256, SMEM_NT>>>(
        h, 128, (long long)SZ_ND, Wqkv, 128, 0,
        qkv, 384, (long long)SZ_QKV, bqkv, NP, 384, 128, 1.0f);

    k_flash<<<dim3(32, 4, 2), 256, FLASH_SMEM>>>(qkv, o, alphaS);

    k_mma<128, 128, 64, 32, 1, 0, 0><<<dim3(1, 32, 2), 256, SMEM_NT>>>(
        o, 128, (long long)SZ_ND, Woq, 128, 0,
        tmp, 128, (long long)SZ_ND, bo, NP, 128, 128, 1.0f);
    k_ln<<<2 * NP, 128>>>(f0, tmp, ln1g, ln1b, f1, 1);

    k_mma<128, 128, 64, 32, 1, 1, 1><<<dim3(4, 32, 2), 256, SMEM_NT>>>(
        f1, 128, (long long)SZ_ND, W1q, 128, 0,
        ff, FFD, (long long)NP * FFD, b1, NP, FFD, 128, 1.0f);
    k_mma<128, 128, 64, 32, 1, 0, 0><<<dim3(1, 32, 2), 256, SMEM_NT>>>(
        ff, FFD, (long long)NP * FFD, W2q, FFD, 0,
        tmp, 128, (long long)SZ_ND, b2, NP, 128, FFD, 1.0f);
    k_ln<<<2 * NP, 128>>>(f1, tmp, ln2g, ln2b, fo, 0);

    k_combine<<<(NP * DM) / 256, 256>>>(x, y, fo, fo + SZ_ND, out);
}

// round 10
// speedup vs baseline: 4.7806x; 1.0412x over previous
#include <cuda_runtime.h>
#include <math.h>
#include <stdint.h>

// ---------------------------------------------------------------------------
// Problem constants
// ---------------------------------------------------------------------------
#define NP 4096
#define KN 80
#define DM 128
#define FFD 512

static constexpr size_t SZ_ND  = (size_t)NP * DM;              // 524288
static constexpr size_t SZ_A1  = (size_t)NP * 8192;            // per-stream A
static constexpr size_t SZ_QKV = (size_t)NP * 384;

static constexpr size_t OFF_A    = 0;
static constexpr size_t OFF_PE   = OFF_A + 2 * SZ_A1;
static constexpr size_t OFF_CONV = OFF_PE + SZ_ND;
static constexpr size_t OFF_F0   = OFF_CONV + 2 * SZ_ND;
static constexpr size_t OFF_H    = OFF_F0 + 2 * SZ_ND;
static constexpr size_t OFF_QKV  = OFF_H + 2 * SZ_ND;
static constexpr size_t OFF_O    = OFF_QKV + 2 * SZ_QKV;
static constexpr size_t OFF_T    = OFF_O + 2 * SZ_ND;
static constexpr size_t OFF_F1   = OFF_T + 2 * SZ_ND;
static constexpr size_t OFF_FF   = OFF_F1 + 2 * SZ_ND;         // 2*NP*512
static constexpr size_t OFF_OUT  = OFF_FF + 2 * (size_t)NP * FFD;
static constexpr size_t OFF_PART = OFF_OUT + 2 * SZ_ND;        // 16 partials
static constexpr size_t OFF_WQKV = OFF_PART + 16 * SZ_ND;      // 384*128 + 512
static constexpr size_t OFF_WXQ  = OFF_WQKV + 384 * 128 + 512;
static constexpr size_t OFF_WYQ  = OFF_WXQ + (size_t)8192 * 128;
static constexpr size_t OFF_WOQ  = OFF_WYQ + (size_t)8192 * 128;
static constexpr size_t OFF_W1Q  = OFF_WOQ + 16384;
static constexpr size_t OFF_W2Q  = OFF_W1Q + 65536;
static constexpr size_t OFF_ST   = OFF_W2Q + 65536;
static constexpr size_t SCRATCH_TOTAL = OFF_ST + 1024;

__device__ float g_scratch[SCRATCH_TOTAL];

// ---------------------------------------------------------------------------
// helpers
// ---------------------------------------------------------------------------
__device__ __forceinline__ uint32_t f2tf32(float x) {
    float r;
    asm("cvt.rna.tf32.f32 %0, %1;" : "=f"(r) : "f"(x));
    return __float_as_uint(r);
}
__device__ __forceinline__ float qtf32(float x) {
    return __uint_as_float(f2tf32(x));
}

__device__ __forceinline__ void mma_tf32(float c[4],
                                         uint32_t a0, uint32_t a1, uint32_t a2, uint32_t a3,
                                         uint32_t b0, uint32_t b1) {
    asm volatile(
        "mma.sync.aligned.m16n8k8.row.col.f32.tf32.tf32.f32 "
        "{%0,%1,%2,%3}, {%4,%5,%6,%7}, {%8,%9}, {%0,%1,%2,%3};\n"
        : "+f"(c[0]), "+f"(c[1]), "+f"(c[2]), "+f"(c[3])
        : "r"(a0), "r"(a1), "r"(a2), "r"(a3), "r"(b0), "r"(b1));
}

__device__ __forceinline__ void cp16(uint32_t s, const void* g) {
    asm volatile("cp.async.ca.shared.global [%0], [%1], 16;\n" :: "r"(s), "l"(g));
}
__device__ __forceinline__ void cp_commit() {
    asm volatile("cp.async.commit_group;\n");
}
template <int N>
__device__ __forceinline__ void cp_wait() {
    asm volatile("cp.async.wait_group %0;\n" :: "n"(N));
}

// ---------------------------------------------------------------------------
// tf32 GEMM: cp.async double-buffered, cvt-free (inputs pre-rounded tf32)
// ---------------------------------------------------------------------------
template <int BM, int BN, int WM, int WN, int TRANSB, int ACT, int QUANT>
__global__ __launch_bounds__((BM / WM) * (BN / WN) * 32)
void k_mma(const float* __restrict__ A, int lda, long long strideA,
           const float* __restrict__ B, int ldb, long long strideB,
           float* __restrict__ C, int ldc, long long strideC,
           const float* __restrict__ bias,
           int M, int N, int K, float alpha) {
    constexpr int MI = WM / 16;
    constexpr int NI = WN / 8;
    constexpr int NWARP = (BM / WM) * (BN / WN);
    constexpr int NT = NWARP * 32;
    constexpr int LDA = 36;
    constexpr int LDB = TRANSB ? 36 : (BN + 8);
    constexpr int SA = BM * LDA;
    constexpr int SB = TRANSB ? (BN * LDB) : (32 * LDB);

    extern __shared__ uint32_t sm[];
    uint32_t* sAst[2] = {sm, sm + SA + SB};
    uint32_t* sBst[2] = {sm + SA, sm + SA + SB + SA};

    A += (size_t)blockIdx.z * strideA;
    B += (size_t)blockIdx.z * strideB;
    C += (size_t)blockIdx.z * strideC;

    const int n0 = blockIdx.x * BN;
    const int m0 = blockIdx.y * BM;
    const int tid = threadIdx.x;
    const int w = tid >> 5, lane = tid & 31;
    const int grp = lane >> 2, qid = lane & 3;
    const int wm = w % (BM / WM), wn = w / (BM / WM);

    const uint32_t smem_base = (uint32_t)__cvta_generic_to_shared(sm);

    auto load_tile = [&](int st, int k0) {
        uint32_t aBase = smem_base + (uint32_t)(st * (SA + SB)) * 4u;
        uint32_t bBase = aBase + (uint32_t)SA * 4u;
#pragma unroll
        for (int i = tid; i < BM * 8; i += NT) {
            int r = i >> 3, c4 = (i & 7) * 4;
            cp16(aBase + (uint32_t)(r * LDA + c4) * 4u,
                 A + (size_t)(m0 + r) * lda + k0 + c4);
        }
        if (TRANSB == 1) {
#pragma unroll
            for (int i = tid; i < BN * 8; i += NT) {
                int r = i >> 3, c4 = (i & 7) * 4;
                cp16(bBase + (uint32_t)(r * LDB + c4) * 4u,
                     B + (size_t)(n0 + r) * ldb + k0 + c4);
            }
        } else {
#pragma unroll
            for (int i = tid; i < 32 * (BN / 4); i += NT) {
                int kr = i / (BN / 4);
                int n4 = (i % (BN / 4)) * 4;
                cp16(bBase + (uint32_t)(kr * LDB + n4) * 4u,
                     B + (size_t)(k0 + kr) * ldb + n0 + n4);
            }
        }
        cp_commit();
    };

    float acc[MI][NI][4];
#pragma unroll
    for (int i = 0; i < MI; i++)
#pragma unroll
        for (int j = 0; j < NI; j++)
#pragma unroll
            for (int q = 0; q < 4; q++) acc[i][j][q] = 0.0f;

    const int KT = K / 32;
    load_tile(0, 0);

    for (int kt = 0; kt < KT; kt++) {
        if (kt + 1 < KT) {
            load_tile((kt + 1) & 1, (kt + 1) * 32);
            cp_wait<1>();
        } else {
            cp_wait<0>();
        }
        __syncthreads();

        const uint32_t* sA = sAst[kt & 1];
        const uint32_t* sB = sBst[kt & 1];

#pragma unroll
        for (int ks = 0; ks < 4; ks++) {
            const int kk = ks * 8;
            uint32_t af[MI][4], bf[NI][2];
#pragma unroll
            for (int mi = 0; mi < MI; mi++) {
                int r = wm * WM + mi * 16 + grp;
                af[mi][0] = sA[r * LDA + kk + qid];
                af[mi][1] = sA[(r + 8) * LDA + kk + qid];
                af[mi][2] = sA[r * LDA + kk + qid + 4];
                af[mi][3] = sA[(r + 8) * LDA + kk + qid + 4];
            }
#pragma unroll
            for (int ni = 0; ni < NI; ni++) {
                int c = wn * WN + ni * 8 + grp;
                if (TRANSB == 1) {
                    bf[ni][0] = sB[c * LDB + kk + qid];
                    bf[ni][1] = sB[c * LDB + kk + qid + 4];
                } else {
                    bf[ni][0] = sB[(kk + qid) * LDB + c];
                    bf[ni][1] = sB[(kk + qid + 4) * LDB + c];
                }
            }
#pragma unroll
            for (int mi = 0; mi < MI; mi++)
#pragma unroll
                for (int ni = 0; ni < NI; ni++)
                    mma_tf32(acc[mi][ni], af[mi][0], af[mi][1], af[mi][2], af[mi][3],
                             bf[ni][0], bf[ni][1]);
        }
        __syncthreads();
    }

#pragma unroll
    for (int mi = 0; mi < MI; mi++) {
#pragma unroll
        for (int ni = 0; ni < NI; ni++) {
            int r = m0 + wm * WM + mi * 16 + grp;
            int c = n0 + wn * WN + ni * 8 + qid * 2;
            float b0 = 0.f, b1 = 0.f;
            if (bias) { b0 = bias[c]; b1 = bias[c + 1]; }
            float v0 = acc[mi][ni][0] * alpha + b0;
            float v1 = acc[mi][ni][1] * alpha + b1;
            float v2 = acc[mi][ni][2] * alpha + b0;
            float v3 = acc[mi][ni][3] * alpha + b1;
            if (ACT) {
                v0 = fmaxf(v0, 0.f); v1 = fmaxf(v1, 0.f);
                v2 = fmaxf(v2, 0.f); v3 = fmaxf(v3, 0.f);
            }
            if (QUANT) {
                v0 = qtf32(v0); v1 = qtf32(v1);
                v2 = qtf32(v2); v3 = qtf32(v3);
            }
            *reinterpret_cast<float2*>(C + (size_t)r * ldc + c) = make_float2(v0, v1);
            *reinterpret_cast<float2*>(C + (size_t)(r + 8) * ldc + c) = make_float2(v2, v3);
        }
    }
}

// ---------------------------------------------------------------------------
// k_convA v3: one stream per CTA (grid 4096 x 2), 3 CTAs/SM,
// vectorized 4x4 register-transpose gather (float4 loads + STS.128 stores).
// ---------------------------------------------------------------------------
static constexpr int LDW = 84;   // pad: conflict-free fragment loads
static constexpr int CONVA_SMEM = (64 * LDW + 128 * LDW) * 4 + 512;  // 65 KB

__global__ __launch_bounds__(256, 3)
void k_convA(const float* __restrict__ fx, const float* __restrict__ fy,
             const float* __restrict__ pos, const int* __restrict__ idx,
             float* __restrict__ Abuf) {
    extern __shared__ uint32_t dsm[];
    uint32_t* sWc = dsm;                     // [64][LDW]
    uint32_t* sF  = sWc + 64 * LDW;          // [128][LDW]
    int* gnb      = (int*)(sF + 128 * LDW);  // [80]

    const int n = blockIdx.x;
    const int s = blockIdx.y;
    const float* feat = s ? fy : fx;
    const int tid = threadIdx.x;
    const int w = tid >> 5, lane = tid & 31;
    const int grp = lane >> 2, qid = lane & 3;

    for (int i = tid; i < 64 * LDW; i += 256) sWc[i] = 0u;
    __syncthreads();

    // ---- geometry: one thread per neighbor (duplicated across the 2 CTAs) ----
    if (tid < KN) {
        const float RAD  = 0.22499999403953552f * 0.5f;
        const float invR = 1.0f / RAD;
        float p0 = pos[3 * n], p1 = pos[3 * n + 1], p2 = pos[3 * n + 2];
        int nb = idx[n * KN + tid];
        gnb[tid] = nb;
        if (nb != n) {
            float rx = (pos[3 * nb]     - p0) * invR;
            float ry = (pos[3 * nb + 1] - p1) * invR;
            float rz = (pos[3 * nb + 2] - p2) * invR;
            float r2 = rx * rx + ry * ry + rz * rz;
            float w1 = 1.0f - r2;
            float win = fminf(fmaxf(w1 * w1 * w1, 0.0f), 1.0f);
            if (win > 0.0f) {
                float nrm  = sqrtf(fmaxf(r2, 1e-12f));
                float linf = fmaxf(fmaxf(fabsf(rx), fabsf(ry)), fabsf(rz));
                linf = fmaxf(linf, 1e-9f);
                float sc = nrm / linf;
                float gx = fminf(fmaxf((rx * sc + 1.0f) * 1.5f, 0.0f), 3.0f);
                float gy = fminf(fmaxf((ry * sc + 1.0f) * 1.5f, 0.0f), 3.0f);
                float gz = fminf(fmaxf((rz * sc + 1.0f) * 1.5f, 0.0f), 3.0f);
                float f0x = fminf(floorf(gx), 2.0f);
                float f0y = fminf(floorf(gy), 2.0f);
                float f0z = fminf(floorf(gz), 2.0f);
                float tx = gx - f0x, ty = gy - f0y, tz = gz - f0z;
                int base = (int)f0x * 16 + (int)f0y * 4 + (int)f0z;
                float wx[2] = {1.0f - tx, tx};
                float wy[2] = {1.0f - ty, ty};
                float wz[2] = {1.0f - tz, tz};
#pragma unroll
                for (int dx = 0; dx < 2; dx++)
#pragma unroll
                    for (int dy = 0; dy < 2; dy++)
#pragma unroll
                        for (int dz = 0; dz < 2; dz++) {
                            int cell = base + dx * 16 + dy * 4 + dz;
                            sWc[cell * LDW + tid] =
                                f2tf32(win * wx[dx] * wy[dy] * wz[dz]);
                        }
            }
        }
    }
    __syncthreads();

    // ---- gather: 640 4x4-tile tasks, register transpose, STS.128 stores ----
    for (int t = tid; t < 640; t += 256) {
        int kg = t % 20, cg = t / 20;        // kg: neighbor quad, cg: channel quad
        int k4 = kg * 4, c0 = cg * 4;
        float4 r0 = *reinterpret_cast<const float4*>(
            feat + (size_t)gnb[k4 + 0] * DM + c0);
        float4 r1 = *reinterpret_cast<const float4*>(
            feat + (size_t)gnb[k4 + 1] * DM + c0);
        float4 r2 = *reinterpret_cast<const float4*>(
            feat + (size_t)gnb[k4 + 2] * DM + c0);
        float4 r3 = *reinterpret_cast<const float4*>(
            feat + (size_t)gnb[k4 + 3] * DM + c0);
        *reinterpret_cast<uint4*>(&sF[(c0 + 0) * LDW + k4]) =
            make_uint4(f2tf32(r0.x), f2tf32(r1.x), f2tf32(r2.x), f2tf32(r3.x));
        *reinterpret_cast<uint4*>(&sF[(c0 + 1) * LDW + k4]) =
            make_uint4(f2tf32(r0.y), f2tf32(r1.y), f2tf32(r2.y), f2tf32(r3.y));
        *reinterpret_cast<uint4*>(&sF[(c0 + 2) * LDW + k4]) =
            make_uint4(f2tf32(r0.z), f2tf32(r1.z), f2tf32(r2.z), f2tf32(r3.z));
        *reinterpret_cast<uint4*>(&sF[(c0 + 3) * LDW + k4]) =
            make_uint4(f2tf32(r0.w), f2tf32(r1.w), f2tf32(r2.w), f2tf32(r3.w));
    }
    __syncthreads();

    // ---- mma: M=64 (cells), N=128 (channels), K=80; warp tile 32x32 ----
    const int wm = w & 1, wn = w >> 1;
    float acc[2][4][4];
#pragma unroll
    for (int mi = 0; mi < 2; mi++)
#pragma unroll
        for (int ni = 0; ni < 4; ni++)
#pragma unroll
            for (int q = 0; q < 4; q++) acc[mi][ni][q] = 0.0f;

#pragma unroll
    for (int ks = 0; ks < 10; ks++) {
        const int kk = ks * 8;
        uint32_t af[2][4], bf[4][2];
#pragma unroll
        for (int mi = 0; mi < 2; mi++) {
            int r = wm * 32 + mi * 16 + grp;
            af[mi][0] = sWc[r * LDW + kk + qid];
            af[mi][1] = sWc[(r + 8) * LDW + kk + qid];
            af[mi][2] = sWc[r * LDW + kk + qid + 4];
            af[mi][3] = sWc[(r + 8) * LDW + kk + qid + 4];
        }
#pragma unroll
        for (int ni = 0; ni < 4; ni++) {
            int c = wn * 32 + ni * 8 + grp;
            bf[ni][0] = sF[c * LDW + kk + qid];
            bf[ni][1] = sF[c * LDW + kk + qid + 4];
        }
#pragma unroll
        for (int mi = 0; mi < 2; mi++)
#pragma unroll
            for (int ni = 0; ni < 4; ni++)
                mma_tf32(acc[mi][ni], af[mi][0], af[mi][1], af[mi][2], af[mi][3],
                         bf[ni][0], bf[ni][1]);
    }

    float* Aout = Abuf + (size_t)s * SZ_A1 + (size_t)n * 8192;
#pragma unroll
    for (int mi = 0; mi < 2; mi++) {
#pragma unroll
        for (int ni = 0; ni < 4; ni++) {
            int g = wm * 32 + mi * 16 + grp;
            int c = wn * 32 + ni * 8 + qid * 2;
            *reinterpret_cast<float2*>(Aout + (size_t)g * 128 + c) =
                make_float2(qtf32(acc[mi][ni][0]), qtf32(acc[mi][ni][1]));
            *reinterpret_cast<float2*>(Aout + (size_t)(g + 8) * 128 + c) =
                make_float2(qtf32(acc[mi][ni][2]), qtf32(acc[mi][ni][3]));
        }
    }
}

// ---------------------------------------------------------------------------
// Flash attention v3: log2-domain softmax, shfl-transposed P fragments.
// ---------------------------------------------------------------------------
static constexpr int FLASH_SMEM = (128 * 36 + 128 * 36 + 32 * 132) * 4;

__global__ __launch_bounds__(256, 2)
void k_flash(const float* __restrict__ qkvbuf, float* __restrict__ obuf,
             float alpha2 /* alphaS * log2(e) */) {
    constexpr int LDQ = 36, LDV = 132;
    extern __shared__ uint32_t smf[];
    uint32_t* sQ = smf;
    uint32_t* sK = sQ + 128 * LDQ;
    uint32_t* sV = sK + 128 * LDQ;

    const int qb = blockIdx.x, head = blockIdx.y, str = blockIdx.z;
    const float* Qg = qkvbuf + (size_t)str * SZ_QKV + head * 32;
    const float* Kg = Qg + 128;
    const float* Vg = Qg + 256;

    const int tid = threadIdx.x;
    const int w = tid >> 5, lane = tid & 31;
    const int grp = lane >> 2, qid = lane & 3;
    const unsigned FULL = 0xffffffffu;
    const int srcA = (lane & 28) | (qid >> 1);
    const int srcB = srcA + 2;
    const bool odd = (qid & 1);

    for (int i = tid; i < 1024; i += 256) {
        int r = i >> 3, c = (i & 7) * 4;
        float4 v = *reinterpret_cast<const float4*>(
            Qg + (size_t)(qb * 128 + r) * 384 + c);
        sQ[r * LDQ + c + 0] = f2tf32(v.x * alpha2);
        sQ[r * LDQ + c + 1] = f2tf32(v.y * alpha2);
        sQ[r * LDQ + c + 2] = f2tf32(v.z * alpha2);
        sQ[r * LDQ + c + 3] = f2tf32(v.w * alpha2);
    }

    float acc[4][4];
#pragma unroll
    for (int ni = 0; ni < 4; ni++)
#pragma unroll
        for (int q = 0; q < 4; q++) acc[ni][q] = 0.0f;
    float m0 = -1e30f, m1 = -1e30f, l0 = 0.0f, l1 = 0.0f;

    for (int kt = 0; kt < 32; kt++) {
        __syncthreads();
        for (int i = tid; i < 1024; i += 256) {
            int r = i >> 3, c = (i & 7) * 4;
            uint4 kv = *reinterpret_cast<const uint4*>(
                Kg + (size_t)(kt * 128 + r) * 384 + c);
            sK[r * LDQ + c + 0] = kv.x;
            sK[r * LDQ + c + 1] = kv.y;
            sK[r * LDQ + c + 2] = kv.z;
            sK[r * LDQ + c + 3] = kv.w;
            uint4 vv = *reinterpret_cast<const uint4*>(
                Vg + (size_t)(kt * 128 + r) * 384 + c);
            sV[(c + 0) * LDV + r] = vv.x;
            sV[(c + 1) * LDV + r] = vv.y;
            sV[(c + 2) * LDV + r] = vv.z;
            sV[(c + 3) * LDV + r] = vv.w;
        }
        __syncthreads();

        float s[16][4];
#pragma unroll
        for (int ni = 0; ni < 16; ni++)
#pragma unroll
            for (int q = 0; q < 4; q++) s[ni][q] = 0.0f;

#pragma unroll
        for (int ks = 0; ks < 4; ks++) {
            const int kk = ks * 8;
            const int r0 = w * 16 + grp;
            uint32_t a0 = sQ[r0 * LDQ + kk + qid];
            uint32_t a1 = sQ[(r0 + 8) * LDQ + kk + qid];
            uint32_t a2 = sQ[r0 * LDQ + kk + qid + 4];
            uint32_t a3 = sQ[(r0 + 8) * LDQ + kk + qid + 4];
#pragma unroll
            for (int ni = 0; ni < 16; ni++) {
                uint32_t b0 = sK[(ni * 8 + grp) * LDQ + kk + qid];
                uint32_t b1 = sK[(ni * 8 + grp) * LDQ + kk + qid + 4];
                mma_tf32(s[ni], a0, a1, a2, a3, b0, b1);
            }
        }

        // ---- online softmax in log2 domain ----
        float rm0 = -1e30f, rm1 = -1e30f;
#pragma unroll
        for (int ni = 0; ni < 16; ni++) {
            rm0 = fmaxf(rm0, fmaxf(s[ni][0], s[ni][1]));
            rm1 = fmaxf(rm1, fmaxf(s[ni][2], s[ni][3]));
        }
        rm0 = fmaxf(rm0, __shfl_xor_sync(FULL, rm0, 1));
        rm0 = fmaxf(rm0, __shfl_xor_sync(FULL, rm0, 2));
        rm1 = fmaxf(rm1, __shfl_xor_sync(FULL, rm1, 1));
        rm1 = fmaxf(rm1, __shfl_xor_sync(FULL, rm1, 2));

        float mn0 = fmaxf(m0, rm0), mn1 = fmaxf(m1, rm1);
        float c0 = exp2f(m0 - mn0), c1 = exp2f(m1 - mn1);
        float rs0 = 0.0f, rs1 = 0.0f;
#pragma unroll
        for (int ni = 0; ni < 16; ni++) {
            float p00 = exp2f(s[ni][0] - mn0);
            float p01 = exp2f(s[ni][1] - mn0);
            float p10 = exp2f(s[ni][2] - mn1);
            float p11 = exp2f(s[ni][3] - mn1);
            rs0 += p00 + p01;
            rs1 += p10 + p11;
            s[ni][0] = qtf32(p00);
            s[ni][1] = qtf32(p01);
            s[ni][2] = qtf32(p10);
            s[ni][3] = qtf32(p11);
        }
        rs0 += __shfl_xor_sync(FULL, rs0, 1);
        rs0 += __shfl_xor_sync(FULL, rs0, 2);
        rs1 += __shfl_xor_sync(FULL, rs1, 1);
        rs1 += __shfl_xor_sync(FULL, rs1, 2);

        l0 = l0 * c0 + rs0;
        l1 = l1 * c1 + rs1;
        m0 = mn0; m1 = mn1;
#pragma unroll
        for (int ni = 0; ni < 4; ni++) {
            acc[ni][0] *= c0; acc[ni][1] *= c0;
            acc[ni][2] *= c1; acc[ni][3] *= c1;
        }

        // ---- O += P V with shfl-transposed P fragments ----
#pragma unroll
        for (int ks = 0; ks < 16; ks++) {
            float v0 = __shfl_sync(FULL, s[ks][0], srcA);
            float v1 = __shfl_sync(FULL, s[ks][1], srcA);
            float v2 = __shfl_sync(FULL, s[ks][2], srcA);
            float v3 = __shfl_sync(FULL, s[ks][3], srcA);
            float w0 = __shfl_sync(FULL, s[ks][0], srcB);
            float w1 = __shfl_sync(FULL, s[ks][1], srcB);
            float w2 = __shfl_sync(FULL, s[ks][2], srcB);
            float w3 = __shfl_sync(FULL, s[ks][3], srcB);
            uint32_t a0 = __float_as_uint(odd ? v1 : v0);
            uint32_t a1 = __float_as_uint(odd ? v3 : v2);
            uint32_t a2 = __float_as_uint(odd ? w1 : w0);
            uint32_t a3 = __float_as_uint(odd ? w3 : w2);
            const int kk = ks * 8;
#pragma unroll
            for (int ni = 0; ni < 4; ni++) {
                uint32_t b0 = sV[(ni * 8 + grp) * LDV + kk + qid];
                uint32_t b1 = sV[(ni * 8 + grp) * LDV + kk + qid + 4];
                mma_tf32(acc[ni], a0, a1, a2, a3, b0, b1);
            }
        }
    }

    float i0 = 1.0f / l0, i1 = 1.0f / l1;
    float* O = obuf + (size_t)str * SZ_ND;
    int r0 = qb * 128 + w * 16 + grp;
#pragma unroll
    for (int ni = 0; ni < 4; ni++) {
        int col = head * 32 + ni * 8 + qid * 2;
        *reinterpret_cast<float2*>(O + (size_t)r0 * DM + col) =
            make_float2(qtf32(acc[ni][0] * i0), qtf32(acc[ni][1] * i0));
        *reinterpret_cast<float2*>(O + (size_t)(r0 + 8) * DM + col) =
            make_float2(qtf32(acc[ni][2] * i1), qtf32(acc[ni][3] * i1));
    }
}

// ---------------------------------------------------------------------------
// merged weight prep
// ---------------------------------------------------------------------------
__global__ void k_prep(const float* __restrict__ Wx, const float* __restrict__ Wy,
                       const float* __restrict__ Wo, const float* __restrict__ W1,
                       const float* __restrict__ W2,
                       const float* __restrict__ Wq, const float* __restrict__ Wk,
                       const float* __restrict__ Wv, const float* __restrict__ bq,
                       const float* __restrict__ bk, const float* __restrict__ bv,
                       float* __restrict__ base) {
    const int NWX = 1048576;
    size_t i = (size_t)blockIdx.x * 256 + threadIdx.x;
    size_t total = 2 * (size_t)NWX + 16384 + 65536 + 65536 + 49152 + 384;
    for (; i < total; i += (size_t)gridDim.x * 256) {
        size_t j = i;
        if (j < NWX) { base[OFF_WXQ + j] = qtf32(Wx[j]); continue; }
        j -= NWX;
        if (j < NWX) { base[OFF_WYQ + j] = qtf32(Wy[j]); continue; }
        j -= NWX;
        if (j < 16384) { base[OFF_WOQ + j] = qtf32(Wo[j]); continue; }
        j -= 16384;
        if (j < 65536) { base[OFF_W1Q + j] = qtf32(W1[j]); continue; }
        j -= 65536;
        if (j < 65536) { base[OFF_W2Q + j] = qtf32(W2[j]); continue; }
        j -= 65536;
        if (j < 49152) {
            float v = (j < 16384) ? Wq[j] : (j < 32768) ? Wk[j - 16384]
                                                        : Wv[j - 32768];
            base[OFF_WQKV + j] = qtf32(v);
            continue;
        }
        j -= 49152;
        float bvv = (j < 128) ? bq[j] : (j < 256) ? bk[j - 128] : bv[j - 256];
        base[OFF_WQKV + 384 * 128 + j] = bvv;
    }
}

// ---------------------------------------------------------------------------
// small kernels
// ---------------------------------------------------------------------------
__global__ void k_pos_stats(const float* __restrict__ pos, float* __restrict__ st) {
    __shared__ double ss[256], sq[256];
    int t = threadIdx.x;
    double a = 0.0, b = 0.0;
    for (int i = t; i < NP; i += 256) {
        double v = (double)pos[3 * i];
        a += v; b += v * v;
    }
    ss[t] = a; sq[t] = b;
    __syncthreads();
    for (int o = 128; o > 0; o >>= 1) {
        if (t < o) { ss[t] += ss[t + o]; sq[t] += sq[t + o]; }
        __syncthreads();
    }
    if (t == 0) {
        double mean = ss[0] / NP;
        double var  = (sq[0] - ss[0] * ss[0] / NP) / (NP - 1);
        st[0] = (float)mean;
        st[1] = (float)(1.0 / (sqrt(var) + 1e-8));
    }
}

__global__ void k_posenc(const float* __restrict__ pos, const float* __restrict__ st,
                         float* __restrict__ pe) {
    int n = blockIdx.x;
    int j = threadIdx.x;
    float px  = (pos[3 * n] - st[0]) * st[1];
    float dv  = expf((float)(2 * j) * (-9.210340371976184f / 128.0f));
    float ang = px * dv;
    float s, c;
    sincosf(ang, &s, &c);
    pe[(size_t)n * DM + 2 * j]     = s;
    pe[(size_t)n * DM + 2 * j + 1] = c;
}

__global__ void k_reduce8(const float* __restrict__ part, const float* __restrict__ bx,
                          const float* __restrict__ by, float* __restrict__ out) {
    size_t i = (size_t)blockIdx.x * 256 + threadIdx.x;
    int str = (int)(i / SZ_ND);
    const float* p = part + (size_t)str * 8 * SZ_ND + (i - (size_t)str * SZ_ND);
    float v = 0.0f;
#pragma unroll
    for (int j = 0; j < 8; j++) v += p[j * SZ_ND];
    const float* bias = str ? by : bx;
    out[i] = v + bias[i & 127];
}

__global__ void k_bn_stats(const float* __restrict__ h, float* __restrict__ st) {
    __shared__ float ss[256], sq[256];
    int c = blockIdx.x, str = blockIdx.y, t = threadIdx.x;
    const float* hs = h + (size_t)str * SZ_ND;
    float a = 0.f, b = 0.f;
    for (int n = t; n < NP; n += 256) {
        float v = hs[(size_t)n * DM + c];
        a += v; b += v * v;
    }
    ss[t] = a; sq[t] = b;
    __syncthreads();
    for (int o = 128; o > 0; o >>= 1) {
        if (t < o) { ss[t] += ss[t + o]; sq[t] += sq[t + o]; }
        __syncthreads();
    }
    if (t == 0) {
        float mean = ss[0] / NP;
        float var  = sq[0] / NP - mean * mean;
        st[str * 256 + c]       = mean;
        st[str * 256 + 128 + c] = rsqrtf(var + 1e-5f);
    }
}

__global__ void k_bn_apply(const float* __restrict__ conv, const float* __restrict__ st,
                           const float* __restrict__ gx, const float* __restrict__ bxp,
                           const float* __restrict__ gy, const float* __restrict__ byp,
                           const float* __restrict__ pe,
                           float* __restrict__ feat0, float* __restrict__ h) {
    size_t i = (size_t)blockIdx.x * 256 + threadIdx.x;
    int str = (int)(i / SZ_ND);
    size_t local = i - (size_t)str * SZ_ND;
    int c = (int)(i & 127);
    const float* g = str ? gy : gx;
    const float* b = str ? byp : bxp;
    const float* s = st + str * 256;
    float v = (conv[i] - s[c]) * s[128 + c] * g[c] + b[c];
    v = fmaxf(v, 0.0f);
    feat0[i] = v;
    h[i] = qtf32(v + pe[local]);
}

__global__ void k_ln(const float* __restrict__ a, const float* __restrict__ b,
                     const float* __restrict__ g, const float* __restrict__ beta,
                     float* __restrict__ out, int quant) {
    int r = blockIdx.x, t = threadIdx.x;
    float v = a[(size_t)r * DM + t] + b[(size_t)r * DM + t];
    float s = v, q = v * v;
#pragma unroll
    for (int o = 16; o > 0; o >>= 1) {
        s += __shfl_xor_sync(0xffffffffu, s, o);
        q += __shfl_xor_sync(0xffffffffu, q, o);
    }
    __shared__ float ws[4], wq[4];
    int w = t >> 5, lane = t & 31;
    if (lane == 0) { ws[w] = s; wq[w] = q; }
    __syncthreads();
    if (t == 0) {
        float S_ = ws[0] + ws[1] + ws[2] + ws[3];
        float Q_ = wq[0] + wq[1] + wq[2] + wq[3];
        float mean = S_ / 128.0f;
        float var  = Q_ / 128.0f - mean * mean;
        ws[0] = mean;
        wq[0] = rsqrtf(var + 1e-5f);
    }
    __syncthreads();
    float o = (v - ws[0]) * wq[0] * g[t] + beta[t];
    out[(size_t)r * DM + t] = quant ? qtf32(o) : o;
}

__global__ void k_combine(const float* __restrict__ x, const float* __restrict__ y,
                          const float* __restrict__ xf, const float* __restrict__ yf,
                          float* __restrict__ out) {
    int i = blockIdx.x * 256 + threadIdx.x;
    float z = xf[i] + yf[i];
    float s = 1.0f / (1.0f + expf(-z));
    out[i] = 2.0f * x[i] * s + 2.0f * y[i] * (1.0f - s);
}

// ---------------------------------------------------------------------------
// Launch
// ---------------------------------------------------------------------------
extern "C" void kernel_launch(void* const* d_in, const int* in_sizes, int n_in,
                              void* d_out, int out_size) {
    const float* x    = (const float*)d_in[0];
    const float* y    = (const float*)d_in[1];
    const float* pos  = (const float*)d_in[2];
    const int*   idx  = (const int*)d_in[3];
    const float* Wx   = (const float*)d_in[5];
    const float* bx   = (const float*)d_in[6];
    const float* bnxg = (const float*)d_in[7];
    const float* bnxb = (const float*)d_in[8];
    const float* Wy   = (const float*)d_in[9];
    const float* by   = (const float*)d_in[10];
    const float* bnyg = (const float*)d_in[11];
    const float* bnyb = (const float*)d_in[12];
    const float* Wq   = (const float*)d_in[13];
    const float* bq   = (const float*)d_in[14];
    const float* Wk   = (const float*)d_in[15];
    const float* bk   = (const float*)d_in[16];
    const float* Wv   = (const float*)d_in[17];
    const float* bv   = (const float*)d_in[18];
    const float* Wo   = (const float*)d_in[19];
    const float* bo   = (const float*)d_in[20];
    const float* ln1g = (const float*)d_in[21];
    const float* ln1b = (const float*)d_in[22];
    const float* W1   = (const float*)d_in[23];
    const float* b1   = (const float*)d_in[24];
    const float* W2   = (const float*)d_in[25];
    const float* b2   = (const float*)d_in[26];
    const float* ln2g = (const float*)d_in[27];
    const float* ln2b = (const float*)d_in[28];
    float* out = (float*)d_out;

    float* base = nullptr;
    cudaGetSymbolAddress((void**)&base, g_scratch);

    float* A    = base + OFF_A;
    float* pe   = base + OFF_PE;
    float* conv = base + OFF_CONV;
    float* f0   = base + OFF_F0;
    float* h    = base + OFF_H;
    float* qkv  = base + OFF_QKV;
    float* o    = base + OFF_O;
    float* tmp  = base + OFF_T;
    float* f1   = base + OFF_F1;
    float* ff   = base + OFF_FF;
    float* fo   = base + OFF_OUT;
    float* part = base + OFF_PART;
    float* Wqkv = base + OFF_WQKV;
    float* bqkv = base + OFF_WQKV + 384 * 128;
    float* Wxq  = base + OFF_WXQ;
    float* Wyq  = base + OFF_WYQ;
    float* Woq  = base + OFF_WOQ;
    float* W1q  = base + OFF_W1Q;
    float* W2q  = base + OFF_W2Q;
    float* st   = base + OFF_ST;

    constexpr int SMEM_NT = 2 * (128 * 36 + 128 * 36) * 4;
    constexpr int SMEM_T0 = 2 * (128 * 36 + 32 * 136) * 4;
    cudaFuncSetAttribute(k_mma<128, 128, 64, 32, 0, 0, 0>,
                         cudaFuncAttributeMaxDynamicSharedMemorySize, SMEM_T0);
    cudaFuncSetAttribute(k_mma<128, 128, 64, 32, 1, 0, 0>,
                         cudaFuncAttributeMaxDynamicSharedMemorySize, SMEM_NT);
    cudaFuncSetAttribute(k_mma<128, 128, 64, 32, 1, 0, 1>,
                         cudaFuncAttributeMaxDynamicSharedMemorySize, SMEM_NT);
    cudaFuncSetAttribute(k_mma<128, 128, 64, 32, 1, 1, 1>,
                         cudaFuncAttributeMaxDynamicSharedMemorySize, SMEM_NT);
    cudaFuncSetAttribute(k_convA,
                         cudaFuncAttributeMaxDynamicSharedMemorySize, CONVA_SMEM);
    cudaFuncSetAttribute(k_flash,
                         cudaFuncAttributeMaxDynamicSharedMemorySize, FLASH_SMEM);

    const float alphaS = 0.17677669529663687f;           // 1/sqrt(32)
    const float alpha2 = alphaS * 1.4426950408889634f;   // * log2(e)

    k_prep<<<2048, 256>>>(Wx, Wy, Wo, W1, W2, Wq, Wk, Wv, bq, bk, bv, base);
    k_pos_stats<<<1, 256>>>(pos, st + 512);
    k_posenc<<<NP, 64>>>(pos, st + 512, pe);
    k_convA<<<dim3(NP, 2), 256, CONVA_SMEM>>>(x, y, pos, idx, A);

    const float* Wcq[2] = {Wxq, Wyq};
    for (int s = 0; s < 2; s++) {
        k_mma<128, 128, 64, 32, 0, 0, 0><<<dim3(1, 32, 8), 256, SMEM_T0>>>(
            A + (size_t)s * SZ_A1, 8192, 1024,
            Wcq[s], 128, 1024LL * 128,
            part + (size_t)s * 8 * SZ_ND, 128, (long long)SZ_ND, nullptr,
            NP, 128, 1024, 1.0f);
    }
    k_reduce8<<<(2 * SZ_ND) / 256, 256>>>(part, bx, by, conv);
    k_bn_stats<<<dim3(128, 2), 256>>>(conv, st);
    k_bn_apply<<<(2 * SZ_ND) / 256, 256>>>(conv, st, bnxg, bnxb, bnyg, bnyb,
                                           pe, f0, h);

    k_mma<128, 128, 64, 32, 1, 0, 1><<<dim3(3, 32, 2), 256, SMEM_NT>>>(
        h, 128, (long long)SZ_ND, Wqkv, 128, 0,
        qkv, 384, (long long)SZ_QKV, bqkv, NP, 384, 128, 1.0f);

    k_flash<<<dim3(32, 4, 2), 256, FLASH_SMEM>>>(qkv, o, alpha2);

    k_mma<128, 128, 64, 32, 1, 0, 0><<<dim3(1, 32, 2), 256, SMEM_NT>>>(
        o, 128, (long long)SZ_ND, Woq, 128, 0,
        tmp, 128, (long long)SZ_ND, bo, NP, 128, 128, 1.0f);
    k_ln<<<2 * NP, 128>>>(f0, tmp, ln1g, ln1b, f1, 1);

    k_mma<128, 128, 64, 32, 1, 1, 1><<<dim3(4, 32, 2), 256, SMEM_NT>>>(
        f1, 128, (long long)SZ_ND, W1q, 128, 0,
        ff, FFD, (long long)NP * FFD, b1, NP, FFD, 128, 1.0f);
    k_mma<128, 128, 64, 32, 1, 0, 0><<<dim3(1, 32, 2), 256, SMEM_NT>>>(
        ff, FFD, (long long)NP * FFD, W2q, FFD, 0,
        tmp, 128, (long long)SZ_ND, b2, NP, 128, FFD, 1.0f);
    k_ln<<<2 * NP, 128>>>(f1, tmp, ln2g, ln2b, fo, 0);

    k_combine<<<(NP * DM) / 256, 256>>>(x, y, fo, fo + SZ_ND, out);
}

// round 11
// speedup vs baseline: 4.9060x; 1.0262x over previous
#include <cuda_runtime.h>
#include <math.h>
#include <stdint.h>

// ---------------------------------------------------------------------------
// Problem constants
// ---------------------------------------------------------------------------
#define NP 4096
#define KN 80
#define DM 128
#define FFD 512

static constexpr size_t SZ_ND  = (size_t)NP * DM;              // 524288
static constexpr size_t SZ_A1  = (size_t)NP * 8192;            // per-stream A
static constexpr size_t SZ_QKV = (size_t)NP * 384;

static constexpr size_t OFF_A    = 0;
static constexpr size_t OFF_PE   = OFF_A + 2 * SZ_A1;
static constexpr size_t OFF_CONV = OFF_PE + SZ_ND;
static constexpr size_t OFF_F0   = OFF_CONV + 2 * SZ_ND;
static constexpr size_t OFF_H    = OFF_F0 + 2 * SZ_ND;
static constexpr size_t OFF_QKV  = OFF_H + 2 * SZ_ND;
static constexpr size_t OFF_O    = OFF_QKV + 2 * SZ_QKV;
static constexpr size_t OFF_T    = OFF_O + 2 * SZ_ND;
static constexpr size_t OFF_F1   = OFF_T + 2 * SZ_ND;
static constexpr size_t OFF_FF   = OFF_F1 + 2 * SZ_ND;         // 2*NP*512
static constexpr size_t OFF_OUT  = OFF_FF + 2 * (size_t)NP * FFD;
static constexpr size_t OFF_PART = OFF_OUT + 2 * SZ_ND;        // 16 partials
static constexpr size_t OFF_WQKV = OFF_PART + 16 * SZ_ND;      // 384*128 + 512
static constexpr size_t OFF_WXQ  = OFF_WQKV + 384 * 128 + 512;
static constexpr size_t OFF_WYQ  = OFF_WXQ + (size_t)8192 * 128;
static constexpr size_t OFF_WOQ  = OFF_WYQ + (size_t)8192 * 128;
static constexpr size_t OFF_W1Q  = OFF_WOQ + 16384;
static constexpr size_t OFF_W2Q  = OFF_W1Q + 65536;
static constexpr size_t OFF_ST   = OFF_W2Q + 65536;
static constexpr size_t SCRATCH_TOTAL = OFF_ST + 1024;

__device__ float g_scratch[SCRATCH_TOTAL];

// ---------------------------------------------------------------------------
// helpers
// ---------------------------------------------------------------------------
__device__ __forceinline__ uint32_t f2tf32(float x) {
    float r;
    asm("cvt.rna.tf32.f32 %0, %1;" : "=f"(r) : "f"(x));
    return __float_as_uint(r);
}
__device__ __forceinline__ float qtf32(float x) {
    return __uint_as_float(f2tf32(x));
}

__device__ __forceinline__ void mma_tf32(float c[4],
                                         uint32_t a0, uint32_t a1, uint32_t a2, uint32_t a3,
                                         uint32_t b0, uint32_t b1) {
    asm volatile(
        "mma.sync.aligned.m16n8k8.row.col.f32.tf32.tf32.f32 "
        "{%0,%1,%2,%3}, {%4,%5,%6,%7}, {%8,%9}, {%0,%1,%2,%3};\n"
        : "+f"(c[0]), "+f"(c[1]), "+f"(c[2]), "+f"(c[3])
        : "r"(a0), "r"(a1), "r"(a2), "r"(a3), "r"(b0), "r"(b1));
}

__device__ __forceinline__ void cp16(uint32_t s, const void* g) {
    asm volatile("cp.async.ca.shared.global [%0], [%1], 16;\n" :: "r"(s), "l"(g));
}
__device__ __forceinline__ void cp_commit() {
    asm volatile("cp.async.commit_group;\n");
}
template <int N>
__device__ __forceinline__ void cp_wait() {
    asm volatile("cp.async.wait_group %0;\n" :: "n"(N));
}

// ---------------------------------------------------------------------------
// tf32 GEMM: cp.async double-buffered, cvt-free (inputs pre-rounded tf32)
// ---------------------------------------------------------------------------
template <int BM, int BN, int WM, int WN, int TRANSB, int ACT, int QUANT>
__global__ __launch_bounds__((BM / WM) * (BN / WN) * 32)
void k_mma(const float* __restrict__ A, int lda, long long strideA,
           const float* __restrict__ B, int ldb, long long strideB,
           float* __restrict__ C, int ldc, long long strideC,
           const float* __restrict__ bias,
           int M, int N, int K, float alpha) {
    constexpr int MI = WM / 16;
    constexpr int NI = WN / 8;
    constexpr int NWARP = (BM / WM) * (BN / WN);
    constexpr int NT = NWARP * 32;
    constexpr int LDA = 36;
    constexpr int LDB = TRANSB ? 36 : (BN + 8);
    constexpr int SA = BM * LDA;
    constexpr int SB = TRANSB ? (BN * LDB) : (32 * LDB);

    extern __shared__ uint32_t sm[];
    uint32_t* sAst[2] = {sm, sm + SA + SB};
    uint32_t* sBst[2] = {sm + SA, sm + SA + SB + SA};

    A += (size_t)blockIdx.z * strideA;
    B += (size_t)blockIdx.z * strideB;
    C += (size_t)blockIdx.z * strideC;

    const int n0 = blockIdx.x * BN;
    const int m0 = blockIdx.y * BM;
    const int tid = threadIdx.x;
    const int w = tid >> 5, lane = tid & 31;
    const int grp = lane >> 2, qid = lane & 3;
    const int wm = w % (BM / WM), wn = w / (BM / WM);

    const uint32_t smem_base = (uint32_t)__cvta_generic_to_shared(sm);

    auto load_tile = [&](int st, int k0) {
        uint32_t aBase = smem_base + (uint32_t)(st * (SA + SB)) * 4u;
        uint32_t bBase = aBase + (uint32_t)SA * 4u;
#pragma unroll
        for (int i = tid; i < BM * 8; i += NT) {
            int r = i >> 3, c4 = (i & 7) * 4;
            cp16(aBase + (uint32_t)(r * LDA + c4) * 4u,
                 A + (size_t)(m0 + r) * lda + k0 + c4);
        }
        if (TRANSB == 1) {
#pragma unroll
            for (int i = tid; i < BN * 8; i += NT) {
                int r = i >> 3, c4 = (i & 7) * 4;
                cp16(bBase + (uint32_t)(r * LDB + c4) * 4u,
                     B + (size_t)(n0 + r) * ldb + k0 + c4);
            }
        } else {
#pragma unroll
            for (int i = tid; i < 32 * (BN / 4); i += NT) {
                int kr = i / (BN / 4);
                int n4 = (i % (BN / 4)) * 4;
                cp16(bBase + (uint32_t)(kr * LDB + n4) * 4u,
                     B + (size_t)(k0 + kr) * ldb + n0 + n4);
            }
        }
        cp_commit();
    };

    float acc[MI][NI][4];
#pragma unroll
    for (int i = 0; i < MI; i++)
#pragma unroll
        for (int j = 0; j < NI; j++)
#pragma unroll
            for (int q = 0; q < 4; q++) acc[i][j][q] = 0.0f;

    const int KT = K / 32;
    load_tile(0, 0);

    for (int kt = 0; kt < KT; kt++) {
        if (kt + 1 < KT) {
            load_tile((kt + 1) & 1, (kt + 1) * 32);
            cp_wait<1>();
        } else {
            cp_wait<0>();
        }
        __syncthreads();

        const uint32_t* sA = sAst[kt & 1];
        const uint32_t* sB = sBst[kt & 1];

#pragma unroll
        for (int ks = 0; ks < 4; ks++) {
            const int kk = ks * 8;
            uint32_t af[MI][4], bf[NI][2];
#pragma unroll
            for (int mi = 0; mi < MI; mi++) {
                int r = wm * WM + mi * 16 + grp;
                af[mi][0] = sA[r * LDA + kk + qid];
                af[mi][1] = sA[(r + 8) * LDA + kk + qid];
                af[mi][2] = sA[r * LDA + kk + qid + 4];
                af[mi][3] = sA[(r + 8) * LDA + kk + qid + 4];
            }
#pragma unroll
            for (int ni = 0; ni < NI; ni++) {
                int c = wn * WN + ni * 8 + grp;
                if (TRANSB == 1) {
                    bf[ni][0] = sB[c * LDB + kk + qid];
                    bf[ni][1] = sB[c * LDB + kk + qid + 4];
                } else {
                    bf[ni][0] = sB[(kk + qid) * LDB + c];
                    bf[ni][1] = sB[(kk + qid + 4) * LDB + c];
                }
            }
#pragma unroll
            for (int mi = 0; mi < MI; mi++)
#pragma unroll
                for (int ni = 0; ni < NI; ni++)
                    mma_tf32(acc[mi][ni], af[mi][0], af[mi][1], af[mi][2], af[mi][3],
                             bf[ni][0], bf[ni][1]);
        }
        __syncthreads();
    }

#pragma unroll
    for (int mi = 0; mi < MI; mi++) {
#pragma unroll
        for (int ni = 0; ni < NI; ni++) {
            int r = m0 + wm * WM + mi * 16 + grp;
            int c = n0 + wn * WN + ni * 8 + qid * 2;
            float b0 = 0.f, b1 = 0.f;
            if (bias) { b0 = bias[c]; b1 = bias[c + 1]; }
            float v0 = acc[mi][ni][0] * alpha + b0;
            float v1 = acc[mi][ni][1] * alpha + b1;
            float v2 = acc[mi][ni][2] * alpha + b0;
            float v3 = acc[mi][ni][3] * alpha + b1;
            if (ACT) {
                v0 = fmaxf(v0, 0.f); v1 = fmaxf(v1, 0.f);
                v2 = fmaxf(v2, 0.f); v3 = fmaxf(v3, 0.f);
            }
            if (QUANT) {
                v0 = qtf32(v0); v1 = qtf32(v1);
                v2 = qtf32(v2); v3 = qtf32(v3);
            }
            *reinterpret_cast<float2*>(C + (size_t)r * ldc + c) = make_float2(v0, v1);
            *reinterpret_cast<float2*>(C + (size_t)(r + 8) * ldc + c) = make_float2(v2, v3);
        }
    }
}

// ---------------------------------------------------------------------------
// k_convA v4: natural-layout F gather via cp.async (no transpose, no cvt —
// raw fp32 bits feed tf32 mma = RZ truncation; BN downstream cancels bias).
// Grid (4096, 2): one stream per CTA, 3 CTAs/SM.
// ---------------------------------------------------------------------------
static constexpr int LDW = 84;    // wcell row stride (words)
static constexpr int LDC = 132;   // F row stride (words): [nbr][chan]
static constexpr int CONVA_SMEM = (64 * LDW + KN * LDC) * 4 + 256;  // ~62.3 KB

__global__ __launch_bounds__(256, 3)
void k_convA(const float* __restrict__ fx, const float* __restrict__ fy,
             const float* __restrict__ pos, const int* __restrict__ idx,
             float* __restrict__ Abuf) {
    extern __shared__ uint32_t dsm[];
    uint32_t* sWc = dsm;                     // [64][LDW]
    uint32_t* sF  = sWc + 64 * LDW;          // [80][LDC], raw fp32 bits

    const int n = blockIdx.x;
    const int s = blockIdx.y;
    const float* feat = s ? fy : fx;
    const int tid = threadIdx.x;
    const int w = tid >> 5, lane = tid & 31;
    const int grp = lane >> 2, qid = lane & 3;

    const uint32_t sFbase = (uint32_t)__cvta_generic_to_shared(sF);

    // ---- gather F rows (coalesced, one warp covers one 512B row) ----
    // t = tid + it*256 -> row = t>>5 (constant per warp), chunk = lane
#pragma unroll
    for (int t = tid; t < KN * 32; t += 256) {
        int row = t >> 5, chunk = t & 31;
        int nb = idx[n * KN + row];
        cp16(sFbase + (uint32_t)(row * LDC + chunk * 4) * 4u,
             feat + (size_t)nb * DM + chunk * 4);
    }
    cp_commit();

    // ---- zero wcell tile (overlaps cp.async flight) ----
    for (int i = tid; i < 64 * LDW; i += 256) sWc[i] = 0u;
    __syncthreads();

    // ---- geometry: one thread per neighbor ----
    if (tid < KN) {
        const float RAD  = 0.22499999403953552f * 0.5f;
        const float invR = 1.0f / RAD;
        float p0 = pos[3 * n], p1 = pos[3 * n + 1], p2 = pos[3 * n + 2];
        int nb = idx[n * KN + tid];
        if (nb != n) {
            float rx = (pos[3 * nb]     - p0) * invR;
            float ry = (pos[3 * nb + 1] - p1) * invR;
            float rz = (pos[3 * nb + 2] - p2) * invR;
            float r2 = rx * rx + ry * ry + rz * rz;
            float w1 = 1.0f - r2;
            float win = fminf(fmaxf(w1 * w1 * w1, 0.0f), 1.0f);
            if (win > 0.0f) {
                float nrm  = sqrtf(fmaxf(r2, 1e-12f));
                float linf = fmaxf(fmaxf(fabsf(rx), fabsf(ry)), fabsf(rz));
                linf = fmaxf(linf, 1e-9f);
                float sc = nrm / linf;
                float gx = fminf(fmaxf((rx * sc + 1.0f) * 1.5f, 0.0f), 3.0f);
                float gy = fminf(fmaxf((ry * sc + 1.0f) * 1.5f, 0.0f), 3.0f);
                float gz = fminf(fmaxf((rz * sc + 1.0f) * 1.5f, 0.0f), 3.0f);
                float f0x = fminf(floorf(gx), 2.0f);
                float f0y = fminf(floorf(gy), 2.0f);
                float f0z = fminf(floorf(gz), 2.0f);
                float tx = gx - f0x, ty = gy - f0y, tz = gz - f0z;
                int base = (int)f0x * 16 + (int)f0y * 4 + (int)f0z;
                float wx[2] = {1.0f - tx, tx};
                float wy[2] = {1.0f - ty, ty};
                float wz[2] = {1.0f - tz, tz};
#pragma unroll
                for (int dx = 0; dx < 2; dx++)
#pragma unroll
                    for (int dy = 0; dy < 2; dy++)
#pragma unroll
                        for (int dz = 0; dz < 2; dz++) {
                            int cell = base + dx * 16 + dy * 4 + dz;
                            sWc[cell * LDW + tid] =
                                f2tf32(win * wx[dx] * wy[dy] * wz[dz]);
                        }
            }
        }
    }
    cp_wait<0>();
    __syncthreads();

    // ---- mma: M=64 (cells), N=128 (channels), K=80; warp tile 32x32 ----
    // B operand read directly from row-major F: B[n=c][k] = sF[k][c]
    const int wm = w & 1, wn = w >> 1;
    float acc[2][4][4];
#pragma unroll
    for (int mi = 0; mi < 2; mi++)
#pragma unroll
        for (int ni = 0; ni < 4; ni++)
#pragma unroll
            for (int q = 0; q < 4; q++) acc[mi][ni][q] = 0.0f;

#pragma unroll
    for (int ks = 0; ks < 10; ks++) {
        const int kk = ks * 8;
        uint32_t af[2][4], bf[4][2];
#pragma unroll
        for (int mi = 0; mi < 2; mi++) {
            int r = wm * 32 + mi * 16 + grp;
            af[mi][0] = sWc[r * LDW + kk + qid];
            af[mi][1] = sWc[(r + 8) * LDW + kk + qid];
            af[mi][2] = sWc[r * LDW + kk + qid + 4];
            af[mi][3] = sWc[(r + 8) * LDW + kk + qid + 4];
        }
#pragma unroll
        for (int ni = 0; ni < 4; ni++) {
            int c = wn * 32 + ni * 8 + grp;
            bf[ni][0] = sF[(kk + qid) * LDC + c];
            bf[ni][1] = sF[(kk + qid + 4) * LDC + c];
        }
#pragma unroll
        for (int mi = 0; mi < 2; mi++)
#pragma unroll
            for (int ni = 0; ni < 4; ni++)
                mma_tf32(acc[mi][ni], af[mi][0], af[mi][1], af[mi][2], af[mi][3],
                         bf[ni][0], bf[ni][1]);
    }

    float* Aout = Abuf + (size_t)s * SZ_A1 + (size_t)n * 8192;
#pragma unroll
    for (int mi = 0; mi < 2; mi++) {
#pragma unroll
        for (int ni = 0; ni < 4; ni++) {
            int g = wm * 32 + mi * 16 + grp;
            int c = wn * 32 + ni * 8 + qid * 2;
            *reinterpret_cast<float2*>(Aout + (size_t)g * 128 + c) =
                make_float2(qtf32(acc[mi][ni][0]), qtf32(acc[mi][ni][1]));
            *reinterpret_cast<float2*>(Aout + (size_t)(g + 8) * 128 + c) =
                make_float2(qtf32(acc[mi][ni][2]), qtf32(acc[mi][ni][3]));
        }
    }
}

// ---------------------------------------------------------------------------
// Flash attention v3: log2-domain softmax, shfl-transposed P fragments.
// ---------------------------------------------------------------------------
static constexpr int FLASH_SMEM = (128 * 36 + 128 * 36 + 32 * 132) * 4;

__global__ __launch_bounds__(256, 2)
void k_flash(const float* __restrict__ qkvbuf, float* __restrict__ obuf,
             float alpha2 /* alphaS * log2(e) */) {
    constexpr int LDQ = 36, LDV = 132;
    extern __shared__ uint32_t smf[];
    uint32_t* sQ = smf;
    uint32_t* sK = sQ + 128 * LDQ;
    uint32_t* sV = sK + 128 * LDQ;

    const int qb = blockIdx.x, head = blockIdx.y, str = blockIdx.z;
    const float* Qg = qkvbuf + (size_t)str * SZ_QKV + head * 32;
    const float* Kg = Qg + 128;
    const float* Vg = Qg + 256;

    const int tid = threadIdx.x;
    const int w = tid >> 5, lane = tid & 31;
    const int grp = lane >> 2, qid = lane & 3;
    const unsigned FULL = 0xffffffffu;
    const int srcA = (lane & 28) | (qid >> 1);
    const int srcB = srcA + 2;
    const bool odd = (qid & 1);

    for (int i = tid; i < 1024; i += 256) {
        int r = i >> 3, c = (i & 7) * 4;
        float4 v = *reinterpret_cast<const float4*>(
            Qg + (size_t)(qb * 128 + r) * 384 + c);
        sQ[r * LDQ + c + 0] = f2tf32(v.x * alpha2);
        sQ[r * LDQ + c + 1] = f2tf32(v.y * alpha2);
        sQ[r * LDQ + c + 2] = f2tf32(v.z * alpha2);
        sQ[r * LDQ + c + 3] = f2tf32(v.w * alpha2);
    }

    float acc[4][4];
#pragma unroll
    for (int ni = 0; ni < 4; ni++)
#pragma unroll
        for (int q = 0; q < 4; q++) acc[ni][q] = 0.0f;
    float m0 = -1e30f, m1 = -1e30f, l0 = 0.0f, l1 = 0.0f;

    for (int kt = 0; kt < 32; kt++) {
        __syncthreads();
        for (int i = tid; i < 1024; i += 256) {
            int r = i >> 3, c = (i & 7) * 4;
            uint4 kv = *reinterpret_cast<const uint4*>(
                Kg + (size_t)(kt * 128 + r) * 384 + c);
            sK[r * LDQ + c + 0] = kv.x;
            sK[r * LDQ + c + 1] = kv.y;
            sK[r * LDQ + c + 2] = kv.z;
            sK[r * LDQ + c + 3] = kv.w;
            uint4 vv = *reinterpret_cast<const uint4*>(
                Vg + (size_t)(kt * 128 + r) * 384 + c);
            sV[(c + 0) * LDV + r] = vv.x;
            sV[(c + 1) * LDV + r] = vv.y;
            sV[(c + 2) * LDV + r] = vv.z;
            sV[(c + 3) * LDV + r] = vv.w;
        }
        __syncthreads();

        float s[16][4];
#pragma unroll
        for (int ni = 0; ni < 16; ni++)
#pragma unroll
            for (int q = 0; q < 4; q++) s[ni][q] = 0.0f;

#pragma unroll
        for (int ks = 0; ks < 4; ks++) {
            const int kk = ks * 8;
            const int r0 = w * 16 + grp;
            uint32_t a0 = sQ[r0 * LDQ + kk + qid];
            uint32_t a1 = sQ[(r0 + 8) * LDQ + kk + qid];
            uint32_t a2 = sQ[r0 * LDQ + kk + qid + 4];
            uint32_t a3 = sQ[(r0 + 8) * LDQ + kk + qid + 4];
#pragma unroll
            for (int ni = 0; ni < 16; ni++) {
                uint32_t b0 = sK[(ni * 8 + grp) * LDQ + kk + qid];
                uint32_t b1 = sK[(ni * 8 + grp) * LDQ + kk + qid + 4];
                mma_tf32(s[ni], a0, a1, a2, a3, b0, b1);
            }
        }

        float rm0 = -1e30f, rm1 = -1e30f;
#pragma unroll
        for (int ni = 0; ni < 16; ni++) {
            rm0 = fmaxf(rm0, fmaxf(s[ni][0], s[ni][1]));
            rm1 = fmaxf(rm1, fmaxf(s[ni][2], s[ni][3]));
        }
        rm0 = fmaxf(rm0, __shfl_xor_sync(FULL, rm0, 1));
        rm0 = fmaxf(rm0, __shfl_xor_sync(FULL, rm0, 2));
        rm1 = fmaxf(rm1, __shfl_xor_sync(FULL, rm1, 1));
        rm1 = fmaxf(rm1, __shfl_xor_sync(FULL, rm1, 2));

        float mn0 = fmaxf(m0, rm0), mn1 = fmaxf(m1, rm1);
        float c0 = exp2f(m0 - mn0), c1 = exp2f(m1 - mn1);
        float rs0 = 0.0f, rs1 = 0.0f;
#pragma unroll
        for (int ni = 0; ni < 16; ni++) {
            float p00 = exp2f(s[ni][0] - mn0);
            float p01 = exp2f(s[ni][1] - mn0);
            float p10 = exp2f(s[ni][2] - mn1);
            float p11 = exp2f(s[ni][3] - mn1);
            rs0 += p00 + p01;
            rs1 += p10 + p11;
            s[ni][0] = qtf32(p00);
            s[ni][1] = qtf32(p01);
            s[ni][2] = qtf32(p10);
            s[ni][3] = qtf32(p11);
        }
        rs0 += __shfl_xor_sync(FULL, rs0, 1);
        rs0 += __shfl_xor_sync(FULL, rs0, 2);
        rs1 += __shfl_xor_sync(FULL, rs1, 1);
        rs1 += __shfl_xor_sync(FULL, rs1, 2);

        l0 = l0 * c0 + rs0;
        l1 = l1 * c1 + rs1;
        m0 = mn0; m1 = mn1;
#pragma unroll
        for (int ni = 0; ni < 4; ni++) {
            acc[ni][0] *= c0; acc[ni][1] *= c0;
            acc[ni][2] *= c1; acc[ni][3] *= c1;
        }

#pragma unroll
        for (int ks = 0; ks < 16; ks++) {
            float v0 = __shfl_sync(FULL, s[ks][0], srcA);
            float v1 = __shfl_sync(FULL, s[ks][1], srcA);
            float v2 = __shfl_sync(FULL, s[ks][2], srcA);
            float v3 = __shfl_sync(FULL, s[ks][3], srcA);
            float w0 = __shfl_sync(FULL, s[ks][0], srcB);
            float w1 = __shfl_sync(FULL, s[ks][1], srcB);
            float w2 = __shfl_sync(FULL, s[ks][2], srcB);
            float w3 = __shfl_sync(FULL, s[ks][3], srcB);
            uint32_t a0 = __float_as_uint(odd ? v1 : v0);
            uint32_t a1 = __float_as_uint(odd ? v3 : v2);
            uint32_t a2 = __float_as_uint(odd ? w1 : w0);
            uint32_t a3 = __float_as_uint(odd ? w3 : w2);
            const int kk = ks * 8;
#pragma unroll
            for (int ni = 0; ni < 4; ni++) {
                uint32_t b0 = sV[(ni * 8 + grp) * LDV + kk + qid];
                uint32_t b1 = sV[(ni * 8 + grp) * LDV + kk + qid + 4];
                mma_tf32(acc[ni], a0, a1, a2, a3, b0, b1);
            }
        }
    }

    float i0 = 1.0f / l0, i1 = 1.0f / l1;
    float* O = obuf + (size_t)str * SZ_ND;
    int r0 = qb * 128 + w * 16 + grp;
#pragma unroll
    for (int ni = 0; ni < 4; ni++) {
        int col = head * 32 + ni * 8 + qid * 2;
        *reinterpret_cast<float2*>(O + (size_t)r0 * DM + col) =
            make_float2(qtf32(acc[ni][0] * i0), qtf32(acc[ni][1] * i0));
        *reinterpret_cast<float2*>(O + (size_t)(r0 + 8) * DM + col) =
            make_float2(qtf32(acc[ni][2] * i1), qtf32(acc[ni][3] * i1));
    }
}

// ---------------------------------------------------------------------------
// merged weight prep
// ---------------------------------------------------------------------------
__global__ void k_prep(const float* __restrict__ Wx, const float* __restrict__ Wy,
                       const float* __restrict__ Wo, const float* __restrict__ W1,
                       const float* __restrict__ W2,
                       const float* __restrict__ Wq, const float* __restrict__ Wk,
                       const float* __restrict__ Wv, const float* __restrict__ bq,
                       const float* __restrict__ bk, const float* __restrict__ bv,
                       float* __restrict__ base) {
    const int NWX = 1048576;
    size_t i = (size_t)blockIdx.x * 256 + threadIdx.x;
    size_t total = 2 * (size_t)NWX + 16384 + 65536 + 65536 + 49152 + 384;
    for (; i < total; i += (size_t)gridDim.x * 256) {
        size_t j = i;
        if (j < NWX) { base[OFF_WXQ + j] = qtf32(Wx[j]); continue; }
        j -= NWX;
        if (j < NWX) { base[OFF_WYQ + j] = qtf32(Wy[j]); continue; }
        j -= NWX;
        if (j < 16384) { base[OFF_WOQ + j] = qtf32(Wo[j]); continue; }
        j -= 16384;
        if (j < 65536) { base[OFF_W1Q + j] = qtf32(W1[j]); continue; }
        j -= 65536;
        if (j < 65536) { base[OFF_W2Q + j] = qtf32(W2[j]); continue; }
        j -= 65536;
        if (j < 49152) {
            float v = (j < 16384) ? Wq[j] : (j < 32768) ? Wk[j - 16384]
                                                        : Wv[j - 32768];
            base[OFF_WQKV + j] = qtf32(v);
            continue;
        }
        j -= 49152;
        float bvv = (j < 128) ? bq[j] : (j < 256) ? bk[j - 128] : bv[j - 256];
        base[OFF_WQKV + 384 * 128 + j] = bvv;
    }
}

// ---------------------------------------------------------------------------
// small kernels
// ---------------------------------------------------------------------------
__global__ void k_pos_stats(const float* __restrict__ pos, float* __restrict__ st) {
    __shared__ double ss[256], sq[256];
    int t = threadIdx.x;
    double a = 0.0, b = 0.0;
    for (int i = t; i < NP; i += 256) {
        double v = (double)pos[3 * i];
        a += v; b += v * v;
    }
    ss[t] = a; sq[t] = b;
    __syncthreads();
    for (int o = 128; o > 0; o >>= 1) {
        if (t < o) { ss[t] += ss[t + o]; sq[t] += sq[t + o]; }
        __syncthreads();
    }
    if (t == 0) {
        double mean = ss[0] / NP;
        double var  = (sq[0] - ss[0] * ss[0] / NP) / (NP - 1);
        st[0] = (float)mean;
        st[1] = (float)(1.0 / (sqrt(var) + 1e-8));
    }
}

__global__ void k_posenc(const float* __restrict__ pos, const float* __restrict__ st,
                         float* __restrict__ pe) {
    int n = blockIdx.x;
    int j = threadIdx.x;
    float px  = (pos[3 * n] - st[0]) * st[1];
    float dv  = expf((float)(2 * j) * (-9.210340371976184f / 128.0f));
    float ang = px * dv;
    float s, c;
    sincosf(ang, &s, &c);
    pe[(size_t)n * DM + 2 * j]     = s;
    pe[(size_t)n * DM + 2 * j + 1] = c;
}

__global__ void k_reduce8(const float* __restrict__ part, const float* __restrict__ bx,
                          const float* __restrict__ by, float* __restrict__ out) {
    size_t i = (size_t)blockIdx.x * 256 + threadIdx.x;
    int str = (int)(i / SZ_ND);
    const float* p = part + (size_t)str * 8 * SZ_ND + (i - (size_t)str * SZ_ND);
    float v = 0.0f;
#pragma unroll
    for (int j = 0; j < 8; j++) v += p[j * SZ_ND];
    const float* bias = str ? by : bx;
    out[i] = v + bias[i & 127];
}

__global__ void k_bn_stats(const float* __restrict__ h, float* __restrict__ st) {
    __shared__ float ss[256], sq[256];
    int c = blockIdx.x, str = blockIdx.y, t = threadIdx.x;
    const float* hs = h + (size_t)str * SZ_ND;
    float a = 0.f, b = 0.f;
    for (int n = t; n < NP; n += 256) {
        float v = hs[(size_t)n * DM + c];
        a += v; b += v * v;
    }
    ss[t] = a; sq[t] = b;
    __syncthreads();
    for (int o = 128; o > 0; o >>= 1) {
        if (t < o) { ss[t] += ss[t + o]; sq[t] += sq[t + o]; }
        __syncthreads();
    }
    if (t == 0) {
        float mean = ss[0] / NP;
        float var  = sq[0] / NP - mean * mean;
        st[str * 256 + c]       = mean;
        st[str * 256 + 128 + c] = rsqrtf(var + 1e-5f);
    }
}

__global__ void k_bn_apply(const float* __restrict__ conv, const float* __restrict__ st,
                           const float* __restrict__ gx, const float* __restrict__ bxp,
                           const float* __restrict__ gy, const float* __restrict__ byp,
                           const float* __restrict__ pe,
                           float* __restrict__ feat0, float* __restrict__ h) {
    size_t i = (size_t)blockIdx.x * 256 + threadIdx.x;
    int str = (int)(i / SZ_ND);
    size_t local = i - (size_t)str * SZ_ND;
    int c = (int)(i & 127);
    const float* g = str ? gy : gx;
    const float* b = str ? byp : bxp;
    const float* s = st + str * 256;
    float v = (conv[i] - s[c]) * s[128 + c] * g[c] + b[c];
    v = fmaxf(v, 0.0f);
    feat0[i] = v;
    h[i] = qtf32(v + pe[local]);
}

__global__ void k_ln(const float* __restrict__ a, const float* __restrict__ b,
                     const float* __restrict__ g, const float* __restrict__ beta,
                     float* __restrict__ out, int quant) {
    int r = blockIdx.x, t = threadIdx.x;
    float v = a[(size_t)r * DM + t] + b[(size_t)r * DM + t];
    float s = v, q = v * v;
#pragma unroll
    for (int o = 16; o > 0; o >>= 1) {
        s += __shfl_xor_sync(0xffffffffu, s, o);
        q += __shfl_xor_sync(0xffffffffu, q, o);
    }
    __shared__ float ws[4], wq[4];
    int w = t >> 5, lane = t & 31;
    if (lane == 0) { ws[w] = s; wq[w] = q; }
    __syncthreads();
    if (t == 0) {
        float S_ = ws[0] + ws[1] + ws[2] + ws[3];
        float Q_ = wq[0] + wq[1] + wq[2] + wq[3];
        float mean = S_ / 128.0f;
        float var  = Q_ / 128.0f - mean * mean;
        ws[0] = mean;
        wq[0] = rsqrtf(var + 1e-5f);
    }
    __syncthreads();
    float o = (v - ws[0]) * wq[0] * g[t] + beta[t];
    out[(size_t)r * DM + t] = quant ? qtf32(o) : o;
}

__global__ void k_combine(const float* __restrict__ x, const float* __restrict__ y,
                          const float* __restrict__ xf, const float* __restrict__ yf,
                          float* __restrict__ out) {
    int i = blockIdx.x * 256 + threadIdx.x;
    float z = xf[i] + yf[i];
    float s = 1.0f / (1.0f + expf(-z));
    out[i] = 2.0f * x[i] * s + 2.0f * y[i] * (1.0f - s);
}

// ---------------------------------------------------------------------------
// Launch
// ---------------------------------------------------------------------------
extern "C" void kernel_launch(void* const* d_in, const int* in_sizes, int n_in,
                              void* d_out, int out_size) {
    const float* x    = (const float*)d_in[0];
    const float* y    = (const float*)d_in[1];
    const float* pos  = (const float*)d_in[2];
    const int*   idx  = (const int*)d_in[3];
    const float* Wx   = (const float*)d_in[5];
    const float* bx   = (const float*)d_in[6];
    const float* bnxg = (const float*)d_in[7];
    const float* bnxb = (const float*)d_in[8];
    const float* Wy   = (const float*)d_in[9];
    const float* by   = (const float*)d_in[10];
    const float* bnyg = (const float*)d_in[11];
    const float* bnyb = (const float*)d_in[12];
    const float* Wq   = (const float*)d_in[13];
    const float* bq   = (const float*)d_in[14];
    const float* Wk   = (const float*)d_in[15];
    const float* bk   = (const float*)d_in[16];
    const float* Wv   = (const float*)d_in[17];
    const float* bv   = (const float*)d_in[18];
    const float* Wo   = (const float*)d_in[19];
    const float* bo   = (const float*)d_in[20];
    const float* ln1g = (const float*)d_in[21];
    const float* ln1b = (const float*)d_in[22];
    const float* W1   = (const float*)d_in[23];
    const float* b1   = (const float*)d_in[24];
    const float* W2   = (const float*)d_in[25];
    const float* b2   = (const float*)d_in[26];
    const float* ln2g = (const float*)d_in[27];
    const float* ln2b = (const float*)d_in[28];
    float* out = (float*)d_out;

    float* base = nullptr;
    cudaGetSymbolAddress((void**)&base, g_scratch);

    float* A    = base + OFF_A;
    float* pe   = base + OFF_PE;
    float* conv = base + OFF_CONV;
    float* f0   = base + OFF_F0;
    float* h    = base + OFF_H;
    float* qkv  = base + OFF_QKV;
    float* o    = base + OFF_O;
    float* tmp  = base + OFF_T;
    float* f1   = base + OFF_F1;
    float* ff   = base + OFF_FF;
    float* fo   = base + OFF_OUT;
    float* part = base + OFF_PART;
    float* Wqkv = base + OFF_WQKV;
    float* bqkv = base + OFF_WQKV + 384 * 128;
    float* Wxq  = base + OFF_WXQ;
    float* Wyq  = base + OFF_WYQ;
    float* Woq  = base + OFF_WOQ;
    float* W1q  = base + OFF_W1Q;
    float* W2q  = base + OFF_W2Q;
    float* st   = base + OFF_ST;

    constexpr int SMEM_NT = 2 * (128 * 36 + 128 * 36) * 4;
    constexpr int SMEM_T0 = 2 * (128 * 36 + 32 * 136) * 4;
    cudaFuncSetAttribute(k_mma<128, 128, 64, 32, 0, 0, 0>,
                         cudaFuncAttributeMaxDynamicSharedMemorySize, SMEM_T0);
    cudaFuncSetAttribute(k_mma<128, 128, 64, 32, 1, 0, 0>,
                         cudaFuncAttributeMaxDynamicSharedMemorySize, SMEM_NT);
    cudaFuncSetAttribute(k_mma<128, 128, 64, 32, 1, 0, 1>,
                         cudaFuncAttributeMaxDynamicSharedMemorySize, SMEM_NT);
    cudaFuncSetAttribute(k_mma<128, 128, 64, 32, 1, 1, 1>,
                         cudaFuncAttributeMaxDynamicSharedMemorySize, SMEM_NT);
    cudaFuncSetAttribute(k_convA,
                         cudaFuncAttributeMaxDynamicSharedMemorySize, CONVA_SMEM);
    cudaFuncSetAttribute(k_flash,
                         cudaFuncAttributeMaxDynamicSharedMemorySize, FLASH_SMEM);

    const float alphaS = 0.17677669529663687f;           // 1/sqrt(32)
    const float alpha2 = alphaS * 1.4426950408889634f;   // * log2(e)

    k_prep<<<2048, 256>>>(Wx, Wy, Wo, W1, W2, Wq, Wk, Wv, bq, bk, bv, base);
    k_pos_stats<<<1, 256>>>(pos, st + 512);
    k_posenc<<<NP, 64>>>(pos, st + 512, pe);
    k_convA<<<dim3(NP, 2), 256, CONVA_SMEM>>>(x, y, pos, idx, A);

    const float* Wcq[2] = {Wxq, Wyq};
    for (int s = 0; s < 2; s++) {
        k_mma<128, 128, 64, 32, 0, 0, 0><<<dim3(1, 32, 8), 256, SMEM_T0>>>(
            A + (size_t)s * SZ_A1, 8192, 1024,
            Wcq[s], 128, 1024LL * 128,
            part + (size_t)s * 8 * SZ_ND, 128, (long long)SZ_ND, nullptr,
            NP, 128, 1024, 1.0f);
    }
    k_reduce8<<<(2 * SZ_ND) / 256, 256>>>(part, bx, by, conv);
    k_bn_stats<<<dim3(128, 2), 256>>>(conv, st);
    k_bn_apply<<<(2 * SZ_ND) / 256, 256>>>(conv, st, bnxg, bnxb, bnyg, bnyb,
                                           pe, f0, h);

    k_mma<128, 128, 64, 32, 1, 0, 1><<<dim3(3, 32, 2), 256, SMEM_NT>>>(
        h, 128, (long long)SZ_ND, Wqkv, 128, 0,
        qkv, 384, (long long)SZ_QKV, bqkv, NP, 384, 128, 1.0f);

    k_flash<<<dim3(32, 4, 2), 256, FLASH_SMEM>>>(qkv, o, alpha2);

    k_mma<128, 128, 64, 32, 1, 0, 0><<<dim3(1, 32, 2), 256, SMEM_NT>>>(
        o, 128, (long long)SZ_ND, Woq, 128, 0,
        tmp, 128, (long long)SZ_ND, bo, NP, 128, 128, 1.0f);
    k_ln<<<2 * NP, 128>>>(f0, tmp, ln1g, ln1b, f1, 1);

    k_mma<128, 128, 64, 32, 1, 1, 1><<<dim3(4, 32, 2), 256, SMEM_NT>>>(
        f1, 128, (long long)SZ_ND, W1q, 128, 0,
        ff, FFD, (long long)NP * FFD, b1, NP, FFD, 128, 1.0f);
    k_mma<128, 128, 64, 32, 1, 0, 0><<<dim3(1, 32, 2), 256, SMEM_NT>>>(
        ff, FFD, (long long)NP * FFD, W2q, FFD, 0,
        tmp, 128, (long long)SZ_ND, b2, NP, 128, FFD, 1.0f);
    k_ln<<<2 * NP, 128>>>(f1, tmp, ln2g, ln2b, fo, 0);

    k_combine<<<(NP * DM) / 256, 256>>>(x, y, fo, fo + SZ_ND, out);
}

// round 12
// speedup vs baseline: 5.0456x; 1.0285x over previous
#include <cuda_runtime.h>
#include <math.h>
#include <stdint.h>

// ---------------------------------------------------------------------------
// Problem constants
// ---------------------------------------------------------------------------
#define NP 4096
#define KN 80
#define DM 128
#define FFD 512

static constexpr size_t SZ_ND  = (size_t)NP * DM;              // 524288
static constexpr size_t SZ_A1  = (size_t)NP * 8192;            // per-stream A
static constexpr size_t SZ_QKV = (size_t)NP * 384;

static constexpr size_t OFF_A    = 0;
static constexpr size_t OFF_PE   = OFF_A + 2 * SZ_A1;
static constexpr size_t OFF_CONV = OFF_PE + SZ_ND;
static constexpr size_t OFF_F0   = OFF_CONV + 2 * SZ_ND;
static constexpr size_t OFF_H    = OFF_F0 + 2 * SZ_ND;
static constexpr size_t OFF_QKV  = OFF_H + 2 * SZ_ND;
static constexpr size_t OFF_O    = OFF_QKV + 2 * SZ_QKV;
static constexpr size_t OFF_T    = OFF_O + 2 * SZ_ND;
static constexpr size_t OFF_F1   = OFF_T + 2 * SZ_ND;
static constexpr size_t OFF_FF   = OFF_F1 + 2 * SZ_ND;         // 2*NP*512
static constexpr size_t OFF_OUT  = OFF_FF + 2 * (size_t)NP * FFD;
static constexpr size_t OFF_PART = OFF_OUT + 2 * SZ_ND;        // 16 partials
static constexpr size_t OFF_WQKV = OFF_PART + 16 * SZ_ND;      // 384*128 + 512
static constexpr size_t OFF_WXQ  = OFF_WQKV + 384 * 128 + 512;
static constexpr size_t OFF_WYQ  = OFF_WXQ + (size_t)8192 * 128;
static constexpr size_t OFF_WOQ  = OFF_WYQ + (size_t)8192 * 128;
static constexpr size_t OFF_W1Q  = OFF_WOQ + 16384;
static constexpr size_t OFF_W2Q  = OFF_W1Q + 65536;
static constexpr size_t OFF_ST   = OFF_W2Q + 65536;
static constexpr size_t SCRATCH_TOTAL = OFF_ST + 1024;

__device__ float g_scratch[SCRATCH_TOTAL];

// ---------------------------------------------------------------------------
// helpers
// ---------------------------------------------------------------------------
__device__ __forceinline__ uint32_t f2tf32(float x) {
    float r;
    asm("cvt.rna.tf32.f32 %0, %1;" : "=f"(r) : "f"(x));
    return __float_as_uint(r);
}
__device__ __forceinline__ float qtf32(float x) {
    return __uint_as_float(f2tf32(x));
}

__device__ __forceinline__ void mma_tf32(float c[4],
                                         uint32_t a0, uint32_t a1, uint32_t a2, uint32_t a3,
                                         uint32_t b0, uint32_t b1) {
    asm volatile(
        "mma.sync.aligned.m16n8k8.row.col.f32.tf32.tf32.f32 "
        "{%0,%1,%2,%3}, {%4,%5,%6,%7}, {%8,%9}, {%0,%1,%2,%3};\n"
        : "+f"(c[0]), "+f"(c[1]), "+f"(c[2]), "+f"(c[3])
        : "r"(a0), "r"(a1), "r"(a2), "r"(a3), "r"(b0), "r"(b1));
}

// ldmatrix.x4 loading a 16x8 tf32 tile as 4 8x(4-word) submatrices.
// Caller passes the per-lane shared-space byte address:
//   addr(lane) = base + ((row0 + (lane&15)) * LD + kk + (lane>>4)*4) * 4
__device__ __forceinline__ void ldsm_x4(uint32_t& r0, uint32_t& r1,
                                        uint32_t& r2, uint32_t& r3, uint32_t saddr) {
    asm volatile(
        "ldmatrix.sync.aligned.m8n8.x4.shared.b16 {%0,%1,%2,%3}, [%4];\n"
        : "=r"(r0), "=r"(r1), "=r"(r2), "=r"(r3) : "r"(saddr));
}

__device__ __forceinline__ void cp16(uint32_t s, const void* g) {
    asm volatile("cp.async.ca.shared.global [%0], [%1], 16;\n" :: "r"(s), "l"(g));
}
__device__ __forceinline__ void cp_commit() {
    asm volatile("cp.async.commit_group;\n");
}
template <int N>
__device__ __forceinline__ void cp_wait() {
    asm volatile("cp.async.wait_group %0;\n" :: "n"(N));
}

// ---------------------------------------------------------------------------
// tf32 GEMM: cp.async double-buffered, ldmatrix A-fragments
// ---------------------------------------------------------------------------
template <int BM, int BN, int WM, int WN, int TRANSB, int ACT, int QUANT>
__global__ __launch_bounds__((BM / WM) * (BN / WN) * 32)
void k_mma(const float* __restrict__ A, int lda, long long strideA,
           const float* __restrict__ B, int ldb, long long strideB,
           float* __restrict__ C, int ldc, long long strideC,
           const float* __restrict__ bias,
           int M, int N, int K, float alpha) {
    constexpr int MI = WM / 16;
    constexpr int NI = WN / 8;
    constexpr int NWARP = (BM / WM) * (BN / WN);
    constexpr int NT = NWARP * 32;
    constexpr int LDA = 36;
    constexpr int LDB = TRANSB ? 36 : (BN + 8);
    constexpr int SA = BM * LDA;
    constexpr int SB = TRANSB ? (BN * LDB) : (32 * LDB);

    extern __shared__ uint32_t sm[];
    uint32_t* sBst[2] = {sm + SA, sm + SA + SB + SA};

    A += (size_t)blockIdx.z * strideA;
    B += (size_t)blockIdx.z * strideB;
    C += (size_t)blockIdx.z * strideC;

    const int n0 = blockIdx.x * BN;
    const int m0 = blockIdx.y * BM;
    const int tid = threadIdx.x;
    const int w = tid >> 5, lane = tid & 31;
    const int grp = lane >> 2, qid = lane & 3;
    const int wm = w % (BM / WM), wn = w / (BM / WM);

    const uint32_t smem_base = (uint32_t)__cvta_generic_to_shared(sm);
    // per-lane ldmatrix row address component (words) within the A tile
    const uint32_t aRowOff =
        (uint32_t)((wm * WM + (lane & 15)) * LDA + (lane >> 4) * 4);

    auto load_tile = [&](int st, int k0) {
        uint32_t aBase = smem_base + (uint32_t)(st * (SA + SB)) * 4u;
        uint32_t bBase = aBase + (uint32_t)SA * 4u;
#pragma unroll
        for (int i = tid; i < BM * 8; i += NT) {
            int r = i >> 3, c4 = (i & 7) * 4;
            cp16(aBase + (uint32_t)(r * LDA + c4) * 4u,
                 A + (size_t)(m0 + r) * lda + k0 + c4);
        }
        if (TRANSB == 1) {
#pragma unroll
            for (int i = tid; i < BN * 8; i += NT) {
                int r = i >> 3, c4 = (i & 7) * 4;
                cp16(bBase + (uint32_t)(r * LDB + c4) * 4u,
                     B + (size_t)(n0 + r) * ldb + k0 + c4);
            }
        } else {
#pragma unroll
            for (int i = tid; i < 32 * (BN / 4); i += NT) {
                int kr = i / (BN / 4);
                int n4 = (i % (BN / 4)) * 4;
                cp16(bBase + (uint32_t)(kr * LDB + n4) * 4u,
                     B + (size_t)(k0 + kr) * ldb + n0 + n4);
            }
        }
        cp_commit();
    };

    float acc[MI][NI][4];
#pragma unroll
    for (int i = 0; i < MI; i++)
#pragma unroll
        for (int j = 0; j < NI; j++)
#pragma unroll
            for (int q = 0; q < 4; q++) acc[i][j][q] = 0.0f;

    const int KT = K / 32;
    load_tile(0, 0);

    for (int kt = 0; kt < KT; kt++) {
        if (kt + 1 < KT) {
            load_tile((kt + 1) & 1, (kt + 1) * 32);
            cp_wait<1>();
        } else {
            cp_wait<0>();
        }
        __syncthreads();

        const uint32_t* sB = sBst[kt & 1];
        const uint32_t aStage =
            smem_base + (uint32_t)((kt & 1) * (SA + SB)) * 4u;

#pragma unroll
        for (int ks = 0; ks < 4; ks++) {
            const int kk = ks * 8;
            uint32_t af[MI][4], bf[NI][2];
#pragma unroll
            for (int mi = 0; mi < MI; mi++) {
                uint32_t saddr = aStage +
                    (aRowOff + (uint32_t)(mi * 16 * LDA + kk)) * 4u;
                ldsm_x4(af[mi][0], af[mi][1], af[mi][2], af[mi][3], saddr);
            }
#pragma unroll
            for (int ni = 0; ni < NI; ni++) {
                int c = wn * WN + ni * 8 + grp;
                if (TRANSB == 1) {
                    bf[ni][0] = sB[c * LDB + kk + qid];
                    bf[ni][1] = sB[c * LDB + kk + qid + 4];
                } else {
                    bf[ni][0] = sB[(kk + qid) * LDB + c];
                    bf[ni][1] = sB[(kk + qid + 4) * LDB + c];
                }
            }
#pragma unroll
            for (int mi = 0; mi < MI; mi++)
#pragma unroll
                for (int ni = 0; ni < NI; ni++)
                    mma_tf32(acc[mi][ni], af[mi][0], af[mi][1], af[mi][2], af[mi][3],
                             bf[ni][0], bf[ni][1]);
        }
        __syncthreads();
    }

#pragma unroll
    for (int mi = 0; mi < MI; mi++) {
#pragma unroll
        for (int ni = 0; ni < NI; ni++) {
            int r = m0 + wm * WM + mi * 16 + grp;
            int c = n0 + wn * WN + ni * 8 + qid * 2;
            float b0 = 0.f, b1 = 0.f;
            if (bias) { b0 = bias[c]; b1 = bias[c + 1]; }
            float v0 = acc[mi][ni][0] * alpha + b0;
            float v1 = acc[mi][ni][1] * alpha + b1;
            float v2 = acc[mi][ni][2] * alpha + b0;
            float v3 = acc[mi][ni][3] * alpha + b1;
            if (ACT) {
                v0 = fmaxf(v0, 0.f); v1 = fmaxf(v1, 0.f);
                v2 = fmaxf(v2, 0.f); v3 = fmaxf(v3, 0.f);
            }
            if (QUANT) {
                v0 = qtf32(v0); v1 = qtf32(v1);
                v2 = qtf32(v2); v3 = qtf32(v3);
            }
            *reinterpret_cast<float2*>(C + (size_t)r * ldc + c) = make_float2(v0, v1);
            *reinterpret_cast<float2*>(C + (size_t)(r + 8) * ldc + c) = make_float2(v2, v3);
        }
    }
}

// ---------------------------------------------------------------------------
// k_convA v5: ldmatrix wcell fragments, uint4 zeroing, cp.async F gather.
// Grid (4096, 2): one stream per CTA, 3 CTAs/SM.
// ---------------------------------------------------------------------------
static constexpr int LDW = 84;    // wcell row stride (words), 336B (16B mult)
static constexpr int LDC = 132;   // F row stride (words): [nbr][chan]
static constexpr int CONVA_SMEM = (64 * LDW + KN * LDC) * 4 + 256;  // ~62.3 KB

__global__ __launch_bounds__(256, 3)
void k_convA(const float* __restrict__ fx, const float* __restrict__ fy,
             const float* __restrict__ pos, const int* __restrict__ idx,
             float* __restrict__ Abuf) {
    extern __shared__ uint32_t dsm[];
    uint32_t* sWc = dsm;                     // [64][LDW]
    uint32_t* sF  = sWc + 64 * LDW;          // [80][LDC], raw fp32 bits

    const int n = blockIdx.x;
    const int s = blockIdx.y;
    const float* feat = s ? fy : fx;
    const int tid = threadIdx.x;
    const int w = tid >> 5, lane = tid & 31;
    const int grp = lane >> 2, qid = lane & 3;

    const uint32_t smem_base = (uint32_t)__cvta_generic_to_shared(dsm);
    const uint32_t sFbase = smem_base + (uint32_t)(64 * LDW) * 4u;

    // ---- gather F rows (coalesced, one warp per 512B row) ----
#pragma unroll
    for (int t = tid; t < KN * 32; t += 256) {
        int row = t >> 5, chunk = t & 31;
        int nb = idx[n * KN + row];
        cp16(sFbase + (uint32_t)(row * LDC + chunk * 4) * 4u,
             feat + (size_t)nb * DM + chunk * 4);
    }
    cp_commit();

    // ---- zero wcell tile with 128b stores (overlaps cp.async flight) ----
    {
        uint4* z = reinterpret_cast<uint4*>(sWc);
        for (int i = tid; i < 64 * LDW / 4; i += 256)
            z[i] = make_uint4(0u, 0u, 0u, 0u);
    }
    __syncthreads();

    // ---- geometry: one thread per neighbor ----
    if (tid < KN) {
        const float RAD  = 0.22499999403953552f * 0.5f;
        const float invR = 1.0f / RAD;
        float p0 = pos[3 * n], p1 = pos[3 * n + 1], p2 = pos[3 * n + 2];
        int nb = idx[n * KN + tid];
        if (nb != n) {
            float rx = (pos[3 * nb]     - p0) * invR;
            float ry = (pos[3 * nb + 1] - p1) * invR;
            float rz = (pos[3 * nb + 2] - p2) * invR;
            float r2 = rx * rx + ry * ry + rz * rz;
            float w1 = 1.0f - r2;
            float win = fminf(fmaxf(w1 * w1 * w1, 0.0f), 1.0f);
            if (win > 0.0f) {
                float nrm  = sqrtf(fmaxf(r2, 1e-12f));
                float linf = fmaxf(fmaxf(fabsf(rx), fabsf(ry)), fabsf(rz));
                linf = fmaxf(linf, 1e-9f);
                float sc = nrm / linf;
                float gx = fminf(fmaxf((rx * sc + 1.0f) * 1.5f, 0.0f), 3.0f);
                float gy = fminf(fmaxf((ry * sc + 1.0f) * 1.5f, 0.0f), 3.0f);
                float gz = fminf(fmaxf((rz * sc + 1.0f) * 1.5f, 0.0f), 3.0f);
                float f0x = fminf(floorf(gx), 2.0f);
                float f0y = fminf(floorf(gy), 2.0f);
                float f0z = fminf(floorf(gz), 2.0f);
                float tx = gx - f0x, ty = gy - f0y, tz = gz - f0z;
                int base = (int)f0x * 16 + (int)f0y * 4 + (int)f0z;
                float wx[2] = {1.0f - tx, tx};
                float wy[2] = {1.0f - ty, ty};
                float wz[2] = {1.0f - tz, tz};
#pragma unroll
                for (int dx = 0; dx < 2; dx++)
#pragma unroll
                    for (int dy = 0; dy < 2; dy++)
#pragma unroll
                        for (int dz = 0; dz < 2; dz++) {
                            int cell = base + dx * 16 + dy * 4 + dz;
                            sWc[cell * LDW + tid] =
                                f2tf32(win * wx[dx] * wy[dy] * wz[dz]);
                        }
            }
        }
    }
    cp_wait<0>();
    __syncthreads();

    // ---- mma: M=64 (cells), N=128 (channels), K=80; warp tile 32x32 ----
    const int wm = w & 1, wn = w >> 1;
    const uint32_t aRowOff =
        (uint32_t)((wm * 32 + (lane & 15)) * LDW + (lane >> 4) * 4);
    float acc[2][4][4];
#pragma unroll
    for (int mi = 0; mi < 2; mi++)
#pragma unroll
        for (int ni = 0; ni < 4; ni++)
#pragma unroll
            for (int q = 0; q < 4; q++) acc[mi][ni][q] = 0.0f;

#pragma unroll
    for (int ks = 0; ks < 10; ks++) {
        const int kk = ks * 8;
        uint32_t af[2][4], bf[4][2];
#pragma unroll
        for (int mi = 0; mi < 2; mi++) {
            uint32_t saddr = smem_base +
                (aRowOff + (uint32_t)(mi * 16 * LDW + kk)) * 4u;
            ldsm_x4(af[mi][0], af[mi][1], af[mi][2], af[mi][3], saddr);
        }
#pragma unroll
        for (int ni = 0; ni < 4; ni++) {
            int c = wn * 32 + ni * 8 + grp;
            bf[ni][0] = sF[(kk + qid) * LDC + c];
            bf[ni][1] = sF[(kk + qid + 4) * LDC + c];
        }
#pragma unroll
        for (int mi = 0; mi < 2; mi++)
#pragma unroll
            for (int ni = 0; ni < 4; ni++)
                mma_tf32(acc[mi][ni], af[mi][0], af[mi][1], af[mi][2], af[mi][3],
                         bf[ni][0], bf[ni][1]);
    }

    float* Aout = Abuf + (size_t)s * SZ_A1 + (size_t)n * 8192;
#pragma unroll
    for (int mi = 0; mi < 2; mi++) {
#pragma unroll
        for (int ni = 0; ni < 4; ni++) {
            int g = wm * 32 + mi * 16 + grp;
            int c = wn * 32 + ni * 8 + qid * 2;
            *reinterpret_cast<float2*>(Aout + (size_t)g * 128 + c) =
                make_float2(qtf32(acc[mi][ni][0]), qtf32(acc[mi][ni][1]));
            *reinterpret_cast<float2*>(Aout + (size_t)(g + 8) * 128 + c) =
                make_float2(qtf32(acc[mi][ni][2]), qtf32(acc[mi][ni][3]));
        }
    }
}

// ---------------------------------------------------------------------------
// Flash attention v3: log2-domain softmax, shfl-transposed P fragments.
// ---------------------------------------------------------------------------
static constexpr int FLASH_SMEM = (128 * 36 + 128 * 36 + 32 * 132) * 4;

__global__ __launch_bounds__(256, 2)
void k_flash(const float* __restrict__ qkvbuf, float* __restrict__ obuf,
             float alpha2 /* alphaS * log2(e) */) {
    constexpr int LDQ = 36, LDV = 132;
    extern __shared__ uint32_t smf[];
    uint32_t* sQ = smf;
    uint32_t* sK = sQ + 128 * LDQ;
    uint32_t* sV = sK + 128 * LDQ;

    const int qb = blockIdx.x, head = blockIdx.y, str = blockIdx.z;
    const float* Qg = qkvbuf + (size_t)str * SZ_QKV + head * 32;
    const float* Kg = Qg + 128;
    const float* Vg = Qg + 256;

    const int tid = threadIdx.x;
    const int w = tid >> 5, lane = tid & 31;
    const int grp = lane >> 2, qid = lane & 3;
    const unsigned FULL = 0xffffffffu;
    const int srcA = (lane & 28) | (qid >> 1);
    const int srcB = srcA + 2;
    const bool odd = (qid & 1);

    for (int i = tid; i < 1024; i += 256) {
        int r = i >> 3, c = (i & 7) * 4;
        float4 v = *reinterpret_cast<const float4*>(
            Qg + (size_t)(qb * 128 + r) * 384 + c);
        sQ[r * LDQ + c + 0] = f2tf32(v.x * alpha2);
        sQ[r * LDQ + c + 1] = f2tf32(v.y * alpha2);
        sQ[r * LDQ + c + 2] = f2tf32(v.z * alpha2);
        sQ[r * LDQ + c + 3] = f2tf32(v.w * alpha2);
    }

    float acc[4][4];
#pragma unroll
    for (int ni = 0; ni < 4; ni++)
#pragma unroll
        for (int q = 0; q < 4; q++) acc[ni][q] = 0.0f;
    float m0 = -1e30f, m1 = -1e30f, l0 = 0.0f, l1 = 0.0f;

    for (int kt = 0; kt < 32; kt++) {
        __syncthreads();
        for (int i = tid; i < 1024; i += 256) {
            int r = i >> 3, c = (i & 7) * 4;
            uint4 kv = *reinterpret_cast<const uint4*>(
                Kg + (size_t)(kt * 128 + r) * 384 + c);
            sK[r * LDQ + c + 0] = kv.x;
            sK[r * LDQ + c + 1] = kv.y;
            sK[r * LDQ + c + 2] = kv.z;
            sK[r * LDQ + c + 3] = kv.w;
            uint4 vv = *reinterpret_cast<const uint4*>(
                Vg + (size_t)(kt * 128 + r) * 384 + c);
            sV[(c + 0) * LDV + r] = vv.x;
            sV[(c + 1) * LDV + r] = vv.y;
            sV[(c + 2) * LDV + r] = vv.z;
            sV[(c + 3) * LDV + r] = vv.w;
        }
        __syncthreads();

        float s[16][4];
#pragma unroll
        for (int ni = 0; ni < 16; ni++)
#pragma unroll
            for (int q = 0; q < 4; q++) s[ni][q] = 0.0f;

#pragma unroll
        for (int ks = 0; ks < 4; ks++) {
            const int kk = ks * 8;
            const int r0 = w * 16 + grp;
            uint32_t a0 = sQ[r0 * LDQ + kk + qid];
            uint32_t a1 = sQ[(r0 + 8) * LDQ + kk + qid];
            uint32_t a2 = sQ[r0 * LDQ + kk + qid + 4];
            uint32_t a3 = sQ[(r0 + 8) * LDQ + kk + qid + 4];
#pragma unroll
            for (int ni = 0; ni < 16; ni++) {
                uint32_t b0 = sK[(ni * 8 + grp) * LDQ + kk + qid];
                uint32_t b1 = sK[(ni * 8 + grp) * LDQ + kk + qid + 4];
                mma_tf32(s[ni], a0, a1, a2, a3, b0, b1);
            }
        }

        float rm0 = -1e30f, rm1 = -1e30f;
#pragma unroll
        for (int ni = 0; ni < 16; ni++) {
            rm0 = fmaxf(rm0, fmaxf(s[ni][0], s[ni][1]));
            rm1 = fmaxf(rm1, fmaxf(s[ni][2], s[ni][3]));
        }
        rm0 = fmaxf(rm0, __shfl_xor_sync(FULL, rm0, 1));
        rm0 = fmaxf(rm0, __shfl_xor_sync(FULL, rm0, 2));
        rm1 = fmaxf(rm1, __shfl_xor_sync(FULL, rm1, 1));
        rm1 = fmaxf(rm1, __shfl_xor_sync(FULL, rm1, 2));

        float mn0 = fmaxf(m0, rm0), mn1 = fmaxf(m1, rm1);
        float c0 = exp2f(m0 - mn0), c1 = exp2f(m1 - mn1);
        float rs0 = 0.0f, rs1 = 0.0f;
#pragma unroll
        for (int ni = 0; ni < 16; ni++) {
            float p00 = exp2f(s[ni][0] - mn0);
            float p01 = exp2f(s[ni][1] - mn0);
            float p10 = exp2f(s[ni][2] - mn1);
            float p11 = exp2f(s[ni][3] - mn1);
            rs0 += p00 + p01;
            rs1 += p10 + p11;
            s[ni][0] = qtf32(p00);
            s[ni][1] = qtf32(p01);
            s[ni][2] = qtf32(p10);
            s[ni][3] = qtf32(p11);
        }
        rs0 += __shfl_xor_sync(FULL, rs0, 1);
        rs0 += __shfl_xor_sync(FULL, rs0, 2);
        rs1 += __shfl_xor_sync(FULL, rs1, 1);
        rs1 += __shfl_xor_sync(FULL, rs1, 2);

        l0 = l0 * c0 + rs0;
        l1 = l1 * c1 + rs1;
        m0 = mn0; m1 = mn1;
#pragma unroll
        for (int ni = 0; ni < 4; ni++) {
            acc[ni][0] *= c0; acc[ni][1] *= c0;
            acc[ni][2] *= c1; acc[ni][3] *= c1;
        }

#pragma unroll
        for (int ks = 0; ks < 16; ks++) {
            float v0 = __shfl_sync(FULL, s[ks][0], srcA);
            float v1 = __shfl_sync(FULL, s[ks][1], srcA);
            float v2 = __shfl_sync(FULL, s[ks][2], srcA);
            float v3 = __shfl_sync(FULL, s[ks][3], srcA);
            float w0 = __shfl_sync(FULL, s[ks][0], srcB);
            float w1 = __shfl_sync(FULL, s[ks][1], srcB);
            float w2 = __shfl_sync(FULL, s[ks][2], srcB);
            float w3 = __shfl_sync(FULL, s[ks][3], srcB);
            uint32_t a0 = __float_as_uint(odd ? v1 : v0);
            uint32_t a1 = __float_as_uint(odd ? v3 : v2);
            uint32_t a2 = __float_as_uint(odd ? w1 : w0);
            uint32_t a3 = __float_as_uint(odd ? w3 : w2);
            const int kk = ks * 8;
#pragma unroll
            for (int ni = 0; ni < 4; ni++) {
                uint32_t b0 = sV[(ni * 8 + grp) * LDV + kk + qid];
                uint32_t b1 = sV[(ni * 8 + grp) * LDV + kk + qid + 4];
                mma_tf32(acc[ni], a0, a1, a2, a3, b0, b1);
            }
        }
    }

    float i0 = 1.0f / l0, i1 = 1.0f / l1;
    float* O = obuf + (size_t)str * SZ_ND;
    int r0 = qb * 128 + w * 16 + grp;
#pragma unroll
    for (int ni = 0; ni < 4; ni++) {
        int col = head * 32 + ni * 8 + qid * 2;
        *reinterpret_cast<float2*>(O + (size_t)r0 * DM + col) =
            make_float2(qtf32(acc[ni][0] * i0), qtf32(acc[ni][1] * i0));
        *reinterpret_cast<float2*>(O + (size_t)(r0 + 8) * DM + col) =
            make_float2(qtf32(acc[ni][2] * i1), qtf32(acc[ni][3] * i1));
    }
}

// ---------------------------------------------------------------------------
// merged weight prep
// ---------------------------------------------------------------------------
__global__ void k_prep(const float* __restrict__ Wx, const float* __restrict__ Wy,
                       const float* __restrict__ Wo, const float* __restrict__ W1,
                       const float* __restrict__ W2,
                       const float* __restrict__ Wq, const float* __restrict__ Wk,
                       const float* __restrict__ Wv, const float* __restrict__ bq,
                       const float* __restrict__ bk, const float* __restrict__ bv,
                       float* __restrict__ base) {
    const int NWX = 1048576;
    size_t i = (size_t)blockIdx.x * 256 + threadIdx.x;
    size_t total = 2 * (size_t)NWX + 16384 + 65536 + 65536 + 49152 + 384;
    for (; i < total; i += (size_t)gridDim.x * 256) {
        size_t j = i;
        if (j < NWX) { base[OFF_WXQ + j] = qtf32(Wx[j]); continue; }
        j -= NWX;
        if (j < NWX) { base[OFF_WYQ + j] = qtf32(Wy[j]); continue; }
        j -= NWX;
        if (j < 16384) { base[OFF_WOQ + j] = qtf32(Wo[j]); continue; }
        j -= 16384;
        if (j < 65536) { base[OFF_W1Q + j] = qtf32(W1[j]); continue; }
        j -= 65536;
        if (j < 65536) { base[OFF_W2Q + j] = qtf32(W2[j]); continue; }
        j -= 65536;
        if (j < 49152) {
            float v = (j < 16384) ? Wq[j] : (j < 32768) ? Wk[j - 16384]
                                                        : Wv[j - 32768];
            base[OFF_WQKV + j] = qtf32(v);
            continue;
        }
        j -= 49152;
        float bvv = (j < 128) ? bq[j] : (j < 256) ? bk[j - 128] : bv[j - 256];
        base[OFF_WQKV + 384 * 128 + j] = bvv;
    }
}

// ---------------------------------------------------------------------------
// small kernels
// ---------------------------------------------------------------------------
__global__ void k_pos_stats(const float* __restrict__ pos, float* __restrict__ st) {
    __shared__ double ss[256], sq[256];
    int t = threadIdx.x;
    double a = 0.0, b = 0.0;
    for (int i = t; i < NP; i += 256) {
        double v = (double)pos[3 * i];
        a += v; b += v * v;
    }
    ss[t] = a; sq[t] = b;
    __syncthreads();
    for (int o = 128; o > 0; o >>= 1) {
        if (t < o) { ss[t] += ss[t + o]; sq[t] += sq[t + o]; }
        __syncthreads();
    }
    if (t == 0) {
        double mean = ss[0] / NP;
        double var  = (sq[0] - ss[0] * ss[0] / NP) / (NP - 1);
        st[0] = (float)mean;
        st[1] = (float)(1.0 / (sqrt(var) + 1e-8));
    }
}

__global__ void k_posenc(const float* __restrict__ pos, const float* __restrict__ st,
                         float* __restrict__ pe) {
    int n = blockIdx.x;
    int j = threadIdx.x;
    float px  = (pos[3 * n] - st[0]) * st[1];
    float dv  = expf((float)(2 * j) * (-9.210340371976184f / 128.0f));
    float ang = px * dv;
    float s, c;
    sincosf(ang, &s, &c);
    pe[(size_t)n * DM + 2 * j]     = s;
    pe[(size_t)n * DM + 2 * j + 1] = c;
}

__global__ void k_reduce8(const float* __restrict__ part, const float* __restrict__ bx,
                          const float* __restrict__ by, float* __restrict__ out) {
    size_t i = (size_t)blockIdx.x * 256 + threadIdx.x;
    int str = (int)(i / SZ_ND);
    const float* p = part + (size_t)str * 8 * SZ_ND + (i - (size_t)str * SZ_ND);
    float v = 0.0f;
#pragma unroll
    for (int j = 0; j < 8; j++) v += p[j * SZ_ND];
    const float* bias = str ? by : bx;
    out[i] = v + bias[i & 127];
}

__global__ void k_bn_stats(const float* __restrict__ h, float* __restrict__ st) {
    __shared__ float ss[256], sq[256];
    int c = blockIdx.x, str = blockIdx.y, t = threadIdx.x;
    const float* hs = h + (size_t)str * SZ_ND;
    float a = 0.f, b = 0.f;
    for (int n = t; n < NP; n += 256) {
        float v = hs[(size_t)n * DM + c];
        a += v; b += v * v;
    }
    ss[t] = a; sq[t] = b;
    __syncthreads();
    for (int o = 128; o > 0; o >>= 1) {
        if (t < o) { ss[t] += ss[t + o]; sq[t] += sq[t + o]; }
        __syncthreads();
    }
    if (t == 0) {
        float mean = ss[0] / NP;
        float var  = sq[0] / NP - mean * mean;
        st[str * 256 + c]       = mean;
        st[str * 256 + 128 + c] = rsqrtf(var + 1e-5f);
    }
}

__global__ void k_bn_apply(const float* __restrict__ conv, const float* __restrict__ st,
                           const float* __restrict__ gx, const float* __restrict__ bxp,
                           const float* __restrict__ gy, const float* __restrict__ byp,
                           const float* __restrict__ pe,
                           float* __restrict__ feat0, float* __restrict__ h) {
    size_t i = (size_t)blockIdx.x * 256 + threadIdx.x;
    int str = (int)(i / SZ_ND);
    size_t local = i - (size_t)str * SZ_ND;
    int c = (int)(i & 127);
    const float* g = str ? gy : gx;
    const float* b = str ? byp : bxp;
    const float* s = st + str * 256;
    float v = (conv[i] - s[c]) * s[128 + c] * g[c] + b[c];
    v = fmaxf(v, 0.0f);
    feat0[i] = v;
    h[i] = qtf32(v + pe[local]);
}

__global__ void k_ln(const float* __restrict__ a, const float* __restrict__ b,
                     const float* __restrict__ g, const float* __restrict__ beta,
                     float* __restrict__ out, int quant) {
    int r = blockIdx.x, t = threadIdx.x;
    float v = a[(size_t)r * DM + t] + b[(size_t)r * DM + t];
    float s = v, q = v * v;
#pragma unroll
    for (int o = 16; o > 0; o >>= 1) {
        s += __shfl_xor_sync(0xffffffffu, s, o);
        q += __shfl_xor_sync(0xffffffffu, q, o);
    }
    __shared__ float ws[4], wq[4];
    int w = t >> 5, lane = t & 31;
    if (lane == 0) { ws[w] = s; wq[w] = q; }
    __syncthreads();
    if (t == 0) {
        float S_ = ws[0] + ws[1] + ws[2] + ws[3];
        float Q_ = wq[0] + wq[1] + wq[2] + wq[3];
        float mean = S_ / 128.0f;
        float var  = Q_ / 128.0f - mean * mean;
        ws[0] = mean;
        wq[0] = rsqrtf(var + 1e-5f);
    }
    __syncthreads();
    float o = (v - ws[0]) * wq[0] * g[t] + beta[t];
    out[(size_t)r * DM + t] = quant ? qtf32(o) : o;
}

__global__ void k_combine(const float* __restrict__ x, const float* __restrict__ y,
                          const float* __restrict__ xf, const float* __restrict__ yf,
                          float* __restrict__ out) {
    int i = blockIdx.x * 256 + threadIdx.x;
    float z = xf[i] + yf[i];
    float s = 1.0f / (1.0f + expf(-z));
    out[i] = 2.0f * x[i] * s + 2.0f * y[i] * (1.0f - s);
}

// ---------------------------------------------------------------------------
// Launch
// ---------------------------------------------------------------------------
extern "C" void kernel_launch(void* const* d_in, const int* in_sizes, int n_in,
                              void* d_out, int out_size) {
    const float* x    = (const float*)d_in[0];
    const float* y    = (const float*)d_in[1];
    const float* pos  = (const float*)d_in[2];
    const int*   idx  = (const int*)d_in[3];
    const float* Wx   = (const float*)d_in[5];
    const float* bx   = (const float*)d_in[6];
    const float* bnxg = (const float*)d_in[7];
    const float* bnxb = (const float*)d_in[8];
    const float* Wy   = (const float*)d_in[9];
    const float* by   = (const float*)d_in[10];
    const float* bnyg = (const float*)d_in[11];
    const float* bnyb = (const float*)d_in[12];
    const float* Wq   = (const float*)d_in[13];
    const float* bq   = (const float*)d_in[14];
    const float* Wk   = (const float*)d_in[15];
    const float* bk   = (const float*)d_in[16];
    const float* Wv   = (const float*)d_in[17];
    const float* bv   = (const float*)d_in[18];
    const float* Wo   = (const float*)d_in[19];
    const float* bo   = (const float*)d_in[20];
    const float* ln1g = (const float*)d_in[21];
    const float* ln1b = (const float*)d_in[22];
    const float* W1   = (const float*)d_in[23];
    const float* b1   = (const float*)d_in[24];
    const float* W2   = (const float*)d_in[25];
    const float* b2   = (const float*)d_in[26];
    const float* ln2g = (const float*)d_in[27];
    const float* ln2b = (const float*)d_in[28];
    float* out = (float*)d_out;

    float* base = nullptr;
    cudaGetSymbolAddress((void**)&base, g_scratch);

    float* A    = base + OFF_A;
    float* pe   = base + OFF_PE;
    float* conv = base + OFF_CONV;
    float* f0   = base + OFF_F0;
    float* h    = base + OFF_H;
    float* qkv  = base + OFF_QKV;
    float* o    = base + OFF_O;
    float* tmp  = base + OFF_T;
    float* f1   = base + OFF_F1;
    float* ff   = base + OFF_FF;
    float* fo   = base + OFF_OUT;
    float* part = base + OFF_PART;
    float* Wqkv = base + OFF_WQKV;
    float* bqkv = base + OFF_WQKV + 384 * 128;
    float* Wxq  = base + OFF_WXQ;
    float* Wyq  = base + OFF_WYQ;
    float* Woq  = base + OFF_WOQ;
    float* W1q  = base + OFF_W1Q;
    float* W2q  = base + OFF_W2Q;
    float* st   = base + OFF_ST;

    constexpr int SMEM_NT = 2 * (128 * 36 + 128 * 36) * 4;
    constexpr int SMEM_T0 = 2 * (128 * 36 + 32 * 136) * 4;
    cudaFuncSetAttribute(k_mma<128, 128, 64, 32, 0, 0, 0>,
                         cudaFuncAttributeMaxDynamicSharedMemorySize, SMEM_T0);
    cudaFuncSetAttribute(k_mma<128, 128, 64, 32, 1, 0, 0>,
                         cudaFuncAttributeMaxDynamicSharedMemorySize, SMEM_NT);
    cudaFuncSetAttribute(k_mma<128, 128, 64, 32, 1, 0, 1>,
                         cudaFuncAttributeMaxDynamicSharedMemorySize, SMEM_NT);
    cudaFuncSetAttribute(k_mma<128, 128, 64, 32, 1, 1, 1>,
                         cudaFuncAttributeMaxDynamicSharedMemorySize, SMEM_NT);
    cudaFuncSetAttribute(k_convA,
                         cudaFuncAttributeMaxDynamicSharedMemorySize, CONVA_SMEM);
    cudaFuncSetAttribute(k_flash,
                         cudaFuncAttributeMaxDynamicSharedMemorySize, FLASH_SMEM);

    const float alphaS = 0.17677669529663687f;           // 1/sqrt(32)
    const float alpha2 = alphaS * 1.4426950408889634f;   // * log2(e)

    k_prep<<<2048, 256>>>(Wx, Wy, Wo, W1, W2, Wq, Wk, Wv, bq, bk, bv, base);
    k_pos_stats<<<1, 256>>>(pos, st + 512);
    k_posenc<<<NP, 64>>>(pos, st + 512, pe);
    k_convA<<<dim3(NP, 2), 256, CONVA_SMEM>>>(x, y, pos, idx, A);

    const float* Wcq[2] = {Wxq, Wyq};
    for (int s = 0; s < 2; s++) {
        k_mma<128, 128, 64, 32, 0, 0, 0><<<dim3(1, 32, 8), 256, SMEM_T0>>>(
            A + (size_t)s * SZ_A1, 8192, 1024,
            Wcq[s], 128, 1024LL * 128,
            part + (size_t)s * 8 * SZ_ND, 128, (long long)SZ_ND, nullptr,
            NP, 128, 1024, 1.0f);
    }
    k_reduce8<<<(2 * SZ_ND) / 256, 256>>>(part, bx, by, conv);
    k_bn_stats<<<dim3(128, 2), 256>>>(conv, st);
    k_bn_apply<<<(2 * SZ_ND) / 256, 256>>>(conv, st, bnxg, bnxb, bnyg, bnyb,
                                           pe, f0, h);

    k_mma<128, 128, 64, 32, 1, 0, 1><<<dim3(3, 32, 2), 256, SMEM_NT>>>(
        h, 128, (long long)SZ_ND, Wqkv, 128, 0,
        qkv, 384, (long long)SZ_QKV, bqkv, NP, 384, 128, 1.0f);

    k_flash<<<dim3(32, 4, 2), 256, FLASH_SMEM>>>(qkv, o, alpha2);

    k_mma<128, 128, 64, 32, 1, 0, 0><<<dim3(1, 32, 2), 256, SMEM_NT>>>(
        o, 128, (long long)SZ_ND, Woq, 128, 0,
        tmp, 128, (long long)SZ_ND, bo, NP, 128, 128, 1.0f);
    k_ln<<<2 * NP, 128>>>(f0, tmp, ln1g, ln1b, f1, 1);

    k_mma<128, 128, 64, 32, 1, 1, 1><<<dim3(4, 32, 2), 256, SMEM_NT>>>(
        f1, 128, (long long)SZ_ND, W1q, 128, 0,
        ff, FFD, (long long)NP * FFD, b1, NP, FFD, 128, 1.0f);
    k_mma<128, 128, 64, 32, 1, 0, 0><<<dim3(1, 32, 2), 256, SMEM_NT>>>(
        ff, FFD, (long long)NP * FFD, W2q, FFD, 0,
        tmp, 128, (long long)SZ_ND, b2, NP, 128, FFD, 1.0f);
    k_ln<<<2 * NP, 128>>>(f1, tmp, ln2g, ln2b, fo, 0);

    k_combine<<<(NP * DM) / 256, 256>>>(x, y, fo, fo + SZ_ND, out);
}

// round 14
// speedup vs baseline: 6.2206x; 1.2329x over previous
#include <cuda_runtime.h>
#include <cuda_fp16.h>
#include <math.h>
#include <stdint.h>

// ---------------------------------------------------------------------------
// Problem constants
// ---------------------------------------------------------------------------
#define NP 4096
#define KN 80
#define DM 128
#define FFD 512

static constexpr size_t SZ_ND  = (size_t)NP * DM;              // 524288
static constexpr size_t SZ_A1  = (size_t)NP * 8192;            // per-stream A (halfs)
static constexpr size_t SZ_QKV = (size_t)NP * 384;

static constexpr size_t OFF_A    = 0;                          // as half[2*SZ_A1]
static constexpr size_t OFF_PE   = OFF_A + 2 * SZ_A1;          // (floats; A fits)
static constexpr size_t OFF_CONV = OFF_PE + SZ_ND;
static constexpr size_t OFF_F0   = OFF_CONV + 2 * SZ_ND;
static constexpr size_t OFF_H    = OFF_F0 + 2 * SZ_ND;
static constexpr size_t OFF_QKV  = OFF_H + 2 * SZ_ND;
static constexpr size_t OFF_O    = OFF_QKV + 2 * SZ_QKV;
static constexpr size_t OFF_T    = OFF_O + 2 * SZ_ND;
static constexpr size_t OFF_F1   = OFF_T + 2 * SZ_ND;
static constexpr size_t OFF_FF   = OFF_F1 + 2 * SZ_ND;         // 2*NP*512
static constexpr size_t OFF_OUT  = OFF_FF + 2 * (size_t)NP * FFD;
static constexpr size_t OFF_PART = OFF_OUT + 2 * SZ_ND;        // 16 partials
static constexpr size_t OFF_WQKV = OFF_PART + 16 * SZ_ND;      // 384*128 + 512
static constexpr size_t OFF_WXT  = OFF_WQKV + 384 * 128 + 512; // half[1M] (region 1M floats)
static constexpr size_t OFF_WYT  = OFF_WXT + (size_t)8192 * 128;
static constexpr size_t OFF_WOQ  = OFF_WYT + (size_t)8192 * 128;
static constexpr size_t OFF_W1Q  = OFF_WOQ + 16384;
static constexpr size_t OFF_W2Q  = OFF_W1Q + 65536;
static constexpr size_t OFF_ST   = OFF_W2Q + 65536;
static constexpr size_t OFF_FH   = OFF_ST + 1024;              // half[2*SZ_ND] in 1M floats
static constexpr size_t SCRATCH_TOTAL = OFF_FH + 2 * SZ_ND / 2 + 256;

__device__ float g_scratch[SCRATCH_TOTAL];

// ---------------------------------------------------------------------------
// helpers
// ---------------------------------------------------------------------------
__device__ __forceinline__ uint32_t f2tf32(float x) {
    float r;
    asm("cvt.rna.tf32.f32 %0, %1;" : "=f"(r) : "f"(x));
    return __float_as_uint(r);
}
__device__ __forceinline__ float qtf32(float x) {
    return __uint_as_float(f2tf32(x));
}

__device__ __forceinline__ void mma_tf32(float c[4],
                                         uint32_t a0, uint32_t a1, uint32_t a2, uint32_t a3,
                                         uint32_t b0, uint32_t b1) {
    asm volatile(
        "mma.sync.aligned.m16n8k8.row.col.f32.tf32.tf32.f32 "
        "{%0,%1,%2,%3}, {%4,%5,%6,%7}, {%8,%9}, {%0,%1,%2,%3};\n"
        : "+f"(c[0]), "+f"(c[1]), "+f"(c[2]), "+f"(c[3])
        : "r"(a0), "r"(a1), "r"(a2), "r"(a3), "r"(b0), "r"(b1));
}

__device__ __forceinline__ void mma_f16(float c[4],
                                        uint32_t a0, uint32_t a1, uint32_t a2, uint32_t a3,
                                        uint32_t b0, uint32_t b1) {
    asm volatile(
        "mma.sync.aligned.m16n8k16.row.col.f32.f16.f16.f32 "
        "{%0,%1,%2,%3}, {%4,%5,%6,%7}, {%8,%9}, {%0,%1,%2,%3};\n"
        : "+f"(c[0]), "+f"(c[1]), "+f"(c[2]), "+f"(c[3])
        : "r"(a0), "r"(a1), "r"(a2), "r"(a3), "r"(b0), "r"(b1));
}

__device__ __forceinline__ void ldsm_x4(uint32_t& r0, uint32_t& r1,
                                        uint32_t& r2, uint32_t& r3, uint32_t saddr) {
    asm volatile(
        "ldmatrix.sync.aligned.m8n8.x4.shared.b16 {%0,%1,%2,%3}, [%4];\n"
        : "=r"(r0), "=r"(r1), "=r"(r2), "=r"(r3) : "r"(saddr));
}
__device__ __forceinline__ void ldsm_x4_t(uint32_t& r0, uint32_t& r1,
                                          uint32_t& r2, uint32_t& r3, uint32_t saddr) {
    asm volatile(
        "ldmatrix.sync.aligned.m8n8.x4.trans.shared.b16 {%0,%1,%2,%3}, [%4];\n"
        : "=r"(r0), "=r"(r1), "=r"(r2), "=r"(r3) : "r"(saddr));
}

__device__ __forceinline__ void cp16(uint32_t s, const void* g) {
    asm volatile("cp.async.ca.shared.global [%0], [%1], 16;\n" :: "r"(s), "l"(g));
}
__device__ __forceinline__ void cp_commit() {
    asm volatile("cp.async.commit_group;\n");
}
template <int N>
__device__ __forceinline__ void cp_wait() {
    asm volatile("cp.async.wait_group %0;\n" :: "n"(N));
}

// ---------------------------------------------------------------------------
// tf32 GEMM (TRANSB=1 only now): cp.async double-buffered, ldmatrix A-frags
// ---------------------------------------------------------------------------
template <int BM, int BN, int WM, int WN, int ACT, int QUANT>
__global__ __launch_bounds__((BM / WM) * (BN / WN) * 32)
void k_mma(const float* __restrict__ A, int lda, long long strideA,
           const float* __restrict__ B, int ldb, long long strideB,
           float* __restrict__ C, int ldc, long long strideC,
           const float* __restrict__ bias,
           int M, int N, int K, float alpha) {
    constexpr int MI = WM / 16;
    constexpr int NI = WN / 8;
    constexpr int NWARP = (BM / WM) * (BN / WN);
    constexpr int NT = NWARP * 32;
    constexpr int LDA = 36;
    constexpr int LDB = 36;
    constexpr int SA = BM * LDA;
    constexpr int SB = BN * LDB;

    extern __shared__ uint32_t sm[];
    uint32_t* sBst[2] = {sm + SA, sm + SA + SB + SA};

    A += (size_t)blockIdx.z * strideA;
    B += (size_t)blockIdx.z * strideB;
    C += (size_t)blockIdx.z * strideC;

    const int n0 = blockIdx.x * BN;
    const int m0 = blockIdx.y * BM;
    const int tid = threadIdx.x;
    const int w = tid >> 5, lane = tid & 31;
    const int grp = lane >> 2, qid = lane & 3;
    const int wm = w % (BM / WM), wn = w / (BM / WM);

    const uint32_t smem_base = (uint32_t)__cvta_generic_to_shared(sm);
    const uint32_t aRowOff =
        (uint32_t)((wm * WM + (lane & 15)) * LDA + (lane >> 4) * 4);

    auto load_tile = [&](int st, int k0) {
        uint32_t aBase = smem_base + (uint32_t)(st * (SA + SB)) * 4u;
        uint32_t bBase = aBase + (uint32_t)SA * 4u;
#pragma unroll
        for (int i = tid; i < BM * 8; i += NT) {
            int r = i >> 3, c4 = (i & 7) * 4;
            cp16(aBase + (uint32_t)(r * LDA + c4) * 4u,
                 A + (size_t)(m0 + r) * lda + k0 + c4);
        }
#pragma unroll
        for (int i = tid; i < BN * 8; i += NT) {
            int r = i >> 3, c4 = (i & 7) * 4;
            cp16(bBase + (uint32_t)(r * LDB + c4) * 4u,
                 B + (size_t)(n0 + r) * ldb + k0 + c4);
        }
        cp_commit();
    };

    float acc[MI][NI][4];
#pragma unroll
    for (int i = 0; i < MI; i++)
#pragma unroll
        for (int j = 0; j < NI; j++)
#pragma unroll
            for (int q = 0; q < 4; q++) acc[i][j][q] = 0.0f;

    const int KT = K / 32;
    load_tile(0, 0);

    for (int kt = 0; kt < KT; kt++) {
        if (kt + 1 < KT) {
            load_tile((kt + 1) & 1, (kt + 1) * 32);
            cp_wait<1>();
        } else {
            cp_wait<0>();
        }
        __syncthreads();

        const uint32_t* sB = sBst[kt & 1];
        const uint32_t aStage =
            smem_base + (uint32_t)((kt & 1) * (SA + SB)) * 4u;

#pragma unroll
        for (int ks = 0; ks < 4; ks++) {
            const int kk = ks * 8;
            uint32_t af[MI][4], bf[NI][2];
#pragma unroll
            for (int mi = 0; mi < MI; mi++) {
                uint32_t saddr = aStage +
                    (aRowOff + (uint32_t)(mi * 16 * LDA + kk)) * 4u;
                ldsm_x4(af[mi][0], af[mi][1], af[mi][2], af[mi][3], saddr);
            }
#pragma unroll
            for (int ni = 0; ni < NI; ni++) {
                int c = wn * WN + ni * 8 + grp;
                bf[ni][0] = sB[c * LDB + kk + qid];
                bf[ni][1] = sB[c * LDB + kk + qid + 4];
            }
#pragma unroll
            for (int mi = 0; mi < MI; mi++)
#pragma unroll
                for (int ni = 0; ni < NI; ni++)
                    mma_tf32(acc[mi][ni], af[mi][0], af[mi][1], af[mi][2], af[mi][3],
                             bf[ni][0], bf[ni][1]);
        }
        __syncthreads();
    }

#pragma unroll
    for (int mi = 0; mi < MI; mi++) {
#pragma unroll
        for (int ni = 0; ni < NI; ni++) {
            int r = m0 + wm * WM + mi * 16 + grp;
            int c = n0 + wn * WN + ni * 8 + qid * 2;
            float b0 = 0.f, b1 = 0.f;
            if (bias) { b0 = bias[c]; b1 = bias[c + 1]; }
            float v0 = acc[mi][ni][0] * alpha + b0;
            float v1 = acc[mi][ni][1] * alpha + b1;
            float v2 = acc[mi][ni][2] * alpha + b0;
            float v3 = acc[mi][ni][3] * alpha + b1;
            if (ACT) {
                v0 = fmaxf(v0, 0.f); v1 = fmaxf(v1, 0.f);
                v2 = fmaxf(v2, 0.f); v3 = fmaxf(v3, 0.f);
            }
            if (QUANT) {
                v0 = qtf32(v0); v1 = qtf32(v1);
                v2 = qtf32(v2); v3 = qtf32(v3);
            }
            *reinterpret_cast<float2*>(C + (size_t)r * ldc + c) = make_float2(v0, v1);
            *reinterpret_cast<float2*>(C + (size_t)(r + 8) * ldc + c) = make_float2(v2, v3);
        }
    }
}

// ---------------------------------------------------------------------------
// fp16 GEMM for conv: A [M][K] fp16 row-major, B = W^T [N][K] fp16 row-major.
// C fp32 partials (split-K via blockIdx.z). BM=BN=128, WM=64, WN=32, BK=32.
// ---------------------------------------------------------------------------
static constexpr int GH_LDA = 40;   // halfs (80B)
static constexpr int GH_SA  = 128 * GH_LDA;  // halfs
static constexpr int GH_SMEM = 2 * (GH_SA + GH_SA) * 2;  // bytes = 40960

__global__ __launch_bounds__(256)
void k_gemm_h(const __half* __restrict__ A, int lda, long long strideA,
              const __half* __restrict__ B, int ldb, long long strideB,
              float* __restrict__ C, int ldc, long long strideC,
              int M, int K) {
    extern __shared__ __half smh[];

    A += (size_t)blockIdx.z * strideA;
    B += (size_t)blockIdx.z * strideB;
    C += (size_t)blockIdx.z * strideC;

    const int m0 = blockIdx.y * 128;
    const int tid = threadIdx.x;
    const int w = tid >> 5, lane = tid & 31;
    const int grp = lane >> 2, qid = lane & 3;
    const int wm = w & 1, wn = w >> 1;    // 2 x 4 warps -> 64x32 tiles

    const uint32_t smem_base = (uint32_t)__cvta_generic_to_shared(smh);
    const uint32_t aRowOff =
        (uint32_t)((wm * 64 + (lane & 15)) * GH_LDA + (lane >> 4) * 8);

    auto load_tile = [&](int st, int k0) {
        uint32_t aBase = smem_base + (uint32_t)(st * 2 * GH_SA) * 2u;
        uint32_t bBase = aBase + (uint32_t)GH_SA * 2u;
#pragma unroll
        for (int i = tid; i < 512; i += 256) {
            int r = i >> 2, c8 = (i & 3) * 8;
            cp16(aBase + (uint32_t)(r * GH_LDA + c8) * 2u,
                 A + (size_t)(m0 + r) * lda + k0 + c8);
        }
#pragma unroll
        for (int i = tid; i < 512; i += 256) {
            int r = i >> 2, c8 = (i & 3) * 8;
            cp16(bBase + (uint32_t)(r * GH_LDA + c8) * 2u,
                 B + (size_t)r * ldb + k0 + c8);
        }
        cp_commit();
    };

    float acc[4][4][4];
#pragma unroll
    for (int i = 0; i < 4; i++)
#pragma unroll
        for (int j = 0; j < 4; j++)
#pragma unroll
            for (int q = 0; q < 4; q++) acc[i][j][q] = 0.0f;

    const int KT = K / 32;
    load_tile(0, 0);

    for (int kt = 0; kt < KT; kt++) {
        if (kt + 1 < KT) {
            load_tile((kt + 1) & 1, (kt + 1) * 32);
            cp_wait<1>();
        } else {
            cp_wait<0>();
        }
        __syncthreads();

        const uint32_t aStage = smem_base + (uint32_t)((kt & 1) * 2 * GH_SA) * 2u;
        const __half* sB = smh + (kt & 1) * 2 * GH_SA + GH_SA;

#pragma unroll
        for (int ks = 0; ks < 2; ks++) {
            const int kk = ks * 16;
            uint32_t af[4][4], bf[4][2];
#pragma unroll
            for (int mi = 0; mi < 4; mi++) {
                uint32_t saddr = aStage +
                    (aRowOff + (uint32_t)(mi * 16 * GH_LDA + kk)) * 2u;
                ldsm_x4(af[mi][0], af[mi][1], af[mi][2], af[mi][3], saddr);
            }
#pragma unroll
            for (int ni = 0; ni < 4; ni++) {
                int c = wn * 32 + ni * 8 + grp;
                bf[ni][0] = *reinterpret_cast<const uint32_t*>(
                    sB + c * GH_LDA + kk + 2 * qid);
                bf[ni][1] = *reinterpret_cast<const uint32_t*>(
                    sB + c * GH_LDA + kk + 2 * qid + 8);
            }
#pragma unroll
            for (int mi = 0; mi < 4; mi++)
#pragma unroll
                for (int ni = 0; ni < 4; ni++)
                    mma_f16(acc[mi][ni], af[mi][0], af[mi][1], af[mi][2], af[mi][3],
                            bf[ni][0], bf[ni][1]);
        }
        __syncthreads();
    }

#pragma unroll
    for (int mi = 0; mi < 4; mi++) {
#pragma unroll
        for (int ni = 0; ni < 4; ni++) {
            int r = m0 + wm * 64 + mi * 16 + grp;
            int c = wn * 32 + ni * 8 + qid * 2;
            *reinterpret_cast<float2*>(C + (size_t)r * ldc + c) =
                make_float2(acc[mi][ni][0], acc[mi][ni][1]);
            *reinterpret_cast<float2*>(C + (size_t)(r + 8) * ldc + c) =
                make_float2(acc[mi][ni][2], acc[mi][ni][3]);
        }
    }
}

// ---------------------------------------------------------------------------
// k_convA v6 (fp16): gather fp16 features (1280 cp16/CTA), fp16 wcell,
// m16n8k16 mma with ldmatrix (+trans for B), fp16 A output.
// ---------------------------------------------------------------------------
static constexpr int LDWH = 88;    // wcell row stride in halfs (176B)
static constexpr int LDCH = 136;   // F row stride in halfs (272B)
static constexpr int CONVA_SMEM = (64 * LDWH + KN * LDCH) * 2 + 256;

__global__ __launch_bounds__(256, 3)
void k_convA(const __half* __restrict__ fH,
             const float* __restrict__ pos, const int* __restrict__ idx,
             __half* __restrict__ Ah) {
    extern __shared__ __half dsmh[];
    __half* sWc = dsmh;                      // [64][LDWH]
    __half* sF  = sWc + 64 * LDWH;           // [80][LDCH]

    const int n = blockIdx.x;
    const int s = blockIdx.y;
    const __half* feat = fH + (size_t)s * SZ_ND;
    const int tid = threadIdx.x;
    const int w = tid >> 5, lane = tid & 31;
    const int grp = lane >> 2, qid = lane & 3;

    const uint32_t smem_base = (uint32_t)__cvta_generic_to_shared(dsmh);
    const uint32_t sFbase = smem_base + (uint32_t)(64 * LDWH) * 2u;

    // ---- gather F rows: 80 rows x 256B = 16 cp16 each ----
#pragma unroll
    for (int t = tid; t < KN * 16; t += 256) {
        int row = t >> 4, chunk = t & 15;
        int nb = idx[n * KN + row];
        cp16(sFbase + (uint32_t)(row * LDCH + chunk * 8) * 2u,
             feat + (size_t)nb * DM + chunk * 8);
    }
    cp_commit();

    // ---- zero wcell tile (uint4) ----
    {
        uint4* z = reinterpret_cast<uint4*>(sWc);
        for (int i = tid; i < 64 * LDWH / 8; i += 256)
            z[i] = make_uint4(0u, 0u, 0u, 0u);
    }
    __syncthreads();

    // ---- geometry: one thread per neighbor ----
    if (tid < KN) {
        const float RAD  = 0.22499999403953552f * 0.5f;
        const float invR = 1.0f / RAD;
        float p0 = pos[3 * n], p1 = pos[3 * n + 1], p2 = pos[3 * n + 2];
        int nb = idx[n * KN + tid];
        if (nb != n) {
            float rx = (pos[3 * nb]     - p0) * invR;
            float ry = (pos[3 * nb + 1] - p1) * invR;
            float rz = (pos[3 * nb + 2] - p2) * invR;
            float r2 = rx * rx + ry * ry + rz * rz;
            float w1 = 1.0f - r2;
            float win = fminf(fmaxf(w1 * w1 * w1, 0.0f), 1.0f);
            if (win > 0.0f) {
                float nrm  = sqrtf(fmaxf(r2, 1e-12f));
                float linf = fmaxf(fmaxf(fabsf(rx), fabsf(ry)), fabsf(rz));
                linf = fmaxf(linf, 1e-9f);
                float sc = nrm / linf;
                float gx = fminf(fmaxf((rx * sc + 1.0f) * 1.5f, 0.0f), 3.0f);
                float gy = fminf(fmaxf((ry * sc + 1.0f) * 1.5f, 0.0f), 3.0f);
                float gz = fminf(fmaxf((rz * sc + 1.0f) * 1.5f, 0.0f), 3.0f);
                float f0x = fminf(floorf(gx), 2.0f);
                float f0y = fminf(floorf(gy), 2.0f);
                float f0z = fminf(floorf(gz), 2.0f);
                float tx = gx - f0x, ty = gy - f0y, tz = gz - f0z;
                int base = (int)f0x * 16 + (int)f0y * 4 + (int)f0z;
                float wx[2] = {1.0f - tx, tx};
                float wy[2] = {1.0f - ty, ty};
                float wz[2] = {1.0f - tz, tz};
#pragma unroll
                for (int dx = 0; dx < 2; dx++)
#pragma unroll
                    for (int dy = 0; dy < 2; dy++)
#pragma unroll
                        for (int dz = 0; dz < 2; dz++) {
                            int cell = base + dx * 16 + dy * 4 + dz;
                            sWc[cell * LDWH + tid] =
                                __float2half_rn(win * wx[dx] * wy[dy] * wz[dz]);
                        }
            }
        }
    }
    cp_wait<0>();
    __syncthreads();

    // ---- mma: M=64 (cells), N=128 (channels), K=80; 5 k16 steps ----
    const int wm = w & 1, wn = w >> 1;
    const uint32_t aRowOff =
        (uint32_t)((wm * 32 + (lane & 15)) * LDWH + (lane >> 4) * 8);
    const uint32_t bRowOff =
        (uint32_t)((lane & 15) * LDCH + (lane >> 4) * 8);
    float acc[2][4][4];
#pragma unroll
    for (int mi = 0; mi < 2; mi++)
#pragma unroll
        for (int ni = 0; ni < 4; ni++)
#pragma unroll
            for (int q = 0; q < 4; q++) acc[mi][ni][q] = 0.0f;

#pragma unroll
    for (int ks = 0; ks < 5; ks++) {
        const int kk = ks * 16;
        uint32_t af[2][4], bf[4][2];
#pragma unroll
        for (int mi = 0; mi < 2; mi++) {
            uint32_t saddr = smem_base +
                (aRowOff + (uint32_t)(mi * 16 * LDWH + kk)) * 2u;
            ldsm_x4(af[mi][0], af[mi][1], af[mi][2], af[mi][3], saddr);
        }
#pragma unroll
        for (int p = 0; p < 2; p++) {
            uint32_t saddr = sFbase +
                (bRowOff + (uint32_t)(kk * LDCH + wn * 32 + p * 16)) * 2u;
            ldsm_x4_t(bf[2 * p][0], bf[2 * p][1], bf[2 * p + 1][0], bf[2 * p + 1][1],
                      saddr);
        }
#pragma unroll
        for (int mi = 0; mi < 2; mi++)
#pragma unroll
            for (int ni = 0; ni < 4; ni++)
                mma_f16(acc[mi][ni], af[mi][0], af[mi][1], af[mi][2], af[mi][3],
                        bf[ni][0], bf[ni][1]);
    }

    __half* Aout = Ah + (size_t)s * SZ_A1 + (size_t)n * 8192;
#pragma unroll
    for (int mi = 0; mi < 2; mi++) {
#pragma unroll
        for (int ni = 0; ni < 4; ni++) {
            int g = wm * 32 + mi * 16 + grp;
            int c = wn * 32 + ni * 8 + qid * 2;
            *reinterpret_cast<__half2*>(Aout + (size_t)g * 128 + c) =
                __floats2half2_rn(acc[mi][ni][0], acc[mi][ni][1]);
            *reinterpret_cast<__half2*>(Aout + (size_t)(g + 8) * 128 + c) =
                __floats2half2_rn(acc[mi][ni][2], acc[mi][ni][3]);
        }
    }
}

// ---------------------------------------------------------------------------
// Flash attention (unchanged, validated)
// ---------------------------------------------------------------------------
static constexpr int FLASH_SMEM = (128 * 36 + 128 * 36 + 32 * 132) * 4;

__global__ __launch_bounds__(256, 2)
void k_flash(const float* __restrict__ qkvbuf, float* __restrict__ obuf,
             float alpha2) {
    constexpr int LDQ = 36, LDV = 132;
    extern __shared__ uint32_t smf[];
    uint32_t* sQ = smf;
    uint32_t* sK = sQ + 128 * LDQ;
    uint32_t* sV = sK + 128 * LDQ;

    const int qb = blockIdx.x, head = blockIdx.y, str = blockIdx.z;
    const float* Qg = qkvbuf + (size_t)str * SZ_QKV + head * 32;
    const float* Kg = Qg + 128;
    const float* Vg = Qg + 256;

    const int tid = threadIdx.x;
    const int w = tid >> 5, lane = tid & 31;
    const int grp = lane >> 2, qid = lane & 3;
    const unsigned FULL = 0xffffffffu;
    const int srcA = (lane & 28) | (qid >> 1);
    const int srcB = srcA + 2;
    const bool odd = (qid & 1);

    for (int i = tid; i < 1024; i += 256) {
        int r = i >> 3, c = (i & 7) * 4;
        float4 v = *reinterpret_cast<const float4*>(
            Qg + (size_t)(qb * 128 + r) * 384 + c);
        sQ[r * LDQ + c + 0] = f2tf32(v.x * alpha2);
        sQ[r * LDQ + c + 1] = f2tf32(v.y * alpha2);
        sQ[r * LDQ + c + 2] = f2tf32(v.z * alpha2);
        sQ[r * LDQ + c + 3] = f2tf32(v.w * alpha2);
    }

    float acc[4][4];
#pragma unroll
    for (int ni = 0; ni < 4; ni++)
#pragma unroll
        for (int q = 0; q < 4; q++) acc[ni][q] = 0.0f;
    float m0 = -1e30f, m1 = -1e30f, l0 = 0.0f, l1 = 0.0f;

    for (int kt = 0; kt < 32; kt++) {
        __syncthreads();
        for (int i = tid; i < 1024; i += 256) {
            int r = i >> 3, c = (i & 7) * 4;
            uint4 kv = *reinterpret_cast<const uint4*>(
                Kg + (size_t)(kt * 128 + r) * 384 + c);
            sK[r * LDQ + c + 0] = kv.x;
            sK[r * LDQ + c + 1] = kv.y;
            sK[r * LDQ + c + 2] = kv.z;
            sK[r * LDQ + c + 3] = kv.w;
            uint4 vv = *reinterpret_cast<const uint4*>(
                Vg + (size_t)(kt * 128 + r) * 384 + c);
            sV[(c + 0) * LDV + r] = vv.x;
            sV[(c + 1) * LDV + r] = vv.y;
            sV[(c + 2) * LDV + r] = vv.z;
            sV[(c + 3) * LDV + r] = vv.w;
        }
        __syncthreads();

        float s[16][4];
#pragma unroll
        for (int ni = 0; ni < 16; ni++)
#pragma unroll
            for (int q = 0; q < 4; q++) s[ni][q] = 0.0f;

#pragma unroll
        for (int ks = 0; ks < 4; ks++) {
            const int kk = ks * 8;
            const int r0 = w * 16 + grp;
            uint32_t a0 = sQ[r0 * LDQ + kk + qid];
            uint32_t a1 = sQ[(r0 + 8) * LDQ + kk + qid];
            uint32_t a2 = sQ[r0 * LDQ + kk + qid + 4];
            uint32_t a3 = sQ[(r0 + 8) * LDQ + kk + qid + 4];
#pragma unroll
            for (int ni = 0; ni < 16; ni++) {
                uint32_t b0 = sK[(ni * 8 + grp) * LDQ + kk + qid];
                uint32_t b1 = sK[(ni * 8 + grp) * LDQ + kk + qid + 4];
                mma_tf32(s[ni], a0, a1, a2, a3, b0, b1);
            }
        }

        float rm0 = -1e30f, rm1 = -1e30f;
#pragma unroll
        for (int ni = 0; ni < 16; ni++) {
            rm0 = fmaxf(rm0, fmaxf(s[ni][0], s[ni][1]));
            rm1 = fmaxf(rm1, fmaxf(s[ni][2], s[ni][3]));
        }
        rm0 = fmaxf(rm0, __shfl_xor_sync(FULL, rm0, 1));
        rm0 = fmaxf(rm0, __shfl_xor_sync(FULL, rm0, 2));
        rm1 = fmaxf(rm1, __shfl_xor_sync(FULL, rm1, 1));
        rm1 = fmaxf(rm1, __shfl_xor_sync(FULL, rm1, 2));

        float mn0 = fmaxf(m0, rm0), mn1 = fmaxf(m1, rm1);
        float c0 = exp2f(m0 - mn0), c1 = exp2f(m1 - mn1);
        float rs0 = 0.0f, rs1 = 0.0f;
#pragma unroll
        for (int ni = 0; ni < 16; ni++) {
            float p00 = exp2f(s[ni][0] - mn0);
            float p01 = exp2f(s[ni][1] - mn0);
            float p10 = exp2f(s[ni][2] - mn1);
            float p11 = exp2f(s[ni][3] - mn1);
            rs0 += p00 + p01;
            rs1 += p10 + p11;
            s[ni][0] = qtf32(p00);
            s[ni][1] = qtf32(p01);
            s[ni][2] = qtf32(p10);
            s[ni][3] = qtf32(p11);
        }
        rs0 += __shfl_xor_sync(FULL, rs0, 1);
        rs0 += __shfl_xor_sync(FULL, rs0, 2);
        rs1 += __shfl_xor_sync(FULL, rs1, 1);
        rs1 += __shfl_xor_sync(FULL, rs1, 2);

        l0 = l0 * c0 + rs0;
        l1 = l1 * c1 + rs1;
        m0 = mn0; m1 = mn1;
#pragma unroll
        for (int ni = 0; ni < 4; ni++) {
            acc[ni][0] *= c0; acc[ni][1] *= c0;
            acc[ni][2] *= c1; acc[ni][3] *= c1;
        }

#pragma unroll
        for (int ks = 0; ks < 16; ks++) {
            float v0 = __shfl_sync(FULL, s[ks][0], srcA);
            float v1 = __shfl_sync(FULL, s[ks][1], srcA);
            float v2 = __shfl_sync(FULL, s[ks][2], srcA);
            float v3 = __shfl_sync(FULL, s[ks][3], srcA);
            float w0 = __shfl_sync(FULL, s[ks][0], srcB);
            float w1 = __shfl_sync(FULL, s[ks][1], srcB);
            float w2 = __shfl_sync(FULL, s[ks][2], srcB);
            float w3 = __shfl_sync(FULL, s[ks][3], srcB);
            uint32_t a0 = __float_as_uint(odd ? v1 : v0);
            uint32_t a1 = __float_as_uint(odd ? v3 : v2);
            uint32_t a2 = __float_as_uint(odd ? w1 : w0);
            uint32_t a3 = __float_as_uint(odd ? w3 : w2);
            const int kk = ks * 8;
#pragma unroll
            for (int ni = 0; ni < 4; ni++) {
                uint32_t b0 = sV[(ni * 8 + grp) * LDV + kk + qid];
                uint32_t b1 = sV[(ni * 8 + grp) * LDV + kk + qid + 4];
                mma_tf32(acc[ni], a0, a1, a2, a3, b0, b1);
            }
        }
    }

    float i0 = 1.0f / l0, i1 = 1.0f / l1;
    float* O = obuf + (size_t)str * SZ_ND;
    int r0 = qb * 128 + w * 16 + grp;
#pragma unroll
    for (int ni = 0; ni < 4; ni++) {
        int col = head * 32 + ni * 8 + qid * 2;
        *reinterpret_cast<float2*>(O + (size_t)r0 * DM + col) =
            make_float2(qtf32(acc[ni][0] * i0), qtf32(acc[ni][1] * i0));
        *reinterpret_cast<float2*>(O + (size_t)(r0 + 8) * DM + col) =
            make_float2(qtf32(acc[ni][2] * i1), qtf32(acc[ni][3] * i1));
    }
}

// ---------------------------------------------------------------------------
// prep: feats -> fp16; Wo/W1/W2/Wqkv -> tf32 copies; biases
// ---------------------------------------------------------------------------
__global__ void k_prep(const float* __restrict__ x, const float* __restrict__ y,
                       const float* __restrict__ Wo, const float* __restrict__ W1,
                       const float* __restrict__ W2,
                       const float* __restrict__ Wq, const float* __restrict__ Wk,
                       const float* __restrict__ Wv, const float* __restrict__ bq,
                       const float* __restrict__ bk, const float* __restrict__ bv,
                       float* __restrict__ base) {
    __half* fH = reinterpret_cast<__half*>(base + OFF_FH);
    const size_t NF = SZ_ND;  // per stream
    size_t i = (size_t)blockIdx.x * 256 + threadIdx.x;
    size_t total = 2 * NF + 16384 + 65536 + 65536 + 49152 + 384;
    for (; i < total; i += (size_t)gridDim.x * 256) {
        size_t j = i;
        if (j < NF) { fH[j] = __float2half_rn(x[j]); continue; }
        j -= NF;
        if (j < NF) { fH[NF + j] = __float2half_rn(y[j]); continue; }
        j -= NF;
        if (j < 16384) { base[OFF_WOQ + j] = qtf32(Wo[j]); continue; }
        j -= 16384;
        if (j < 65536) { base[OFF_W1Q + j] = qtf32(W1[j]); continue; }
        j -= 65536;
        if (j < 65536) { base[OFF_W2Q + j] = qtf32(W2[j]); continue; }
        j -= 65536;
        if (j < 49152) {
            float v = (j < 16384) ? Wq[j] : (j < 32768) ? Wk[j - 16384]
                                                        : Wv[j - 32768];
            base[OFF_WQKV + j] = qtf32(v);
            continue;
        }
        j -= 49152;
        float bvv = (j < 128) ? bq[j] : (j < 256) ? bk[j - 128] : bv[j - 256];
        base[OFF_WQKV + 384 * 128 + j] = bvv;
    }
}

// transpose-convert Wx/Wy [8192][128] f32 -> WT [128][8192] fp16
__global__ void k_prepT(const float* __restrict__ Wx, const float* __restrict__ Wy,
                        float* __restrict__ base) {
    __shared__ float t[32][33];
    const float* W = blockIdx.z ? Wy : Wx;
    __half* WT = reinterpret_cast<__half*>(base + (blockIdx.z ? OFF_WYT : OFF_WXT));
    int k0 = blockIdx.x * 32, o0 = blockIdx.y * 32;
    int tx = threadIdx.x, ty = threadIdx.y;    // 32 x 8
    for (int i = ty; i < 32; i += 8)
        t[i][tx] = W[(size_t)(k0 + i) * 128 + o0 + tx];
    __syncthreads();
    for (int i = ty; i < 32; i += 8)
        WT[(size_t)(o0 + i) * 8192 + k0 + tx] = __float2half_rn(t[tx][i]);
}

// ---------------------------------------------------------------------------
// small kernels
// ---------------------------------------------------------------------------
__global__ void k_pos_stats(const float* __restrict__ pos, float* __restrict__ st) {
    __shared__ double ss[256], sq[256];
    int t = threadIdx.x;
    double a = 0.0, b = 0.0;
    for (int i = t; i < NP; i += 256) {
        double v = (double)pos[3 * i];
        a += v; b += v * v;
    }
    ss[t] = a; sq[t] = b;
    __syncthreads();
    for (int o = 128; o > 0; o >>= 1) {
        if (t < o) { ss[t] += ss[t + o]; sq[t] += sq[t + o]; }
        __syncthreads();
    }
    if (t == 0) {
        double mean = ss[0] / NP;
        double var  = (sq[0] - ss[0] * ss[0] / NP) / (NP - 1);
        st[0] = (float)mean;
        st[1] = (float)(1.0 / (sqrt(var) + 1e-8));
    }
}

__global__ void k_posenc(const float* __restrict__ pos, const float* __restrict__ st,
                         float* __restrict__ pe) {
    int n = blockIdx.x;
    int j = threadIdx.x;
    float px  = (pos[3 * n] - st[0]) * st[1];
    float dv  = expf((float)(2 * j) * (-9.210340371976184f / 128.0f));
    float ang = px * dv;
    float s, c;
    sincosf(ang, &s, &c);
    pe[(size_t)n * DM + 2 * j]     = s;
    pe[(size_t)n * DM + 2 * j + 1] = c;
}

__global__ void k_reduce8(const float* __restrict__ part, const float* __restrict__ bx,
                          const float* __restrict__ by, float* __restrict__ out) {
    size_t i = (size_t)blockIdx.x * 256 + threadIdx.x;
    int str = (int)(i / SZ_ND);
    const float* p = part + (size_t)str * 8 * SZ_ND + (i - (size_t)str * SZ_ND);
    float v = 0.0f;
#pragma unroll
    for (int j = 0; j < 8; j++) v += p[j * SZ_ND];
    const float* bias = str ? by : bx;
    out[i] = v + bias[i & 127];
}

__global__ void k_bn_stats(const float* __restrict__ h, float* __restrict__ st) {
    __shared__ float ss[256], sq[256];
    int c = blockIdx.x, str = blockIdx.y, t = threadIdx.x;
    const float* hs = h + (size_t)str * SZ_ND;
    float a = 0.f, b = 0.f;
    for (int n = t; n < NP; n += 256) {
        float v = hs[(size_t)n * DM + c];
        a += v; b += v * v;
    }
    ss[t] = a; sq[t] = b;
    __syncthreads();
    for (int o = 128; o > 0; o >>= 1) {
        if (t < o) { ss[t] += ss[t + o]; sq[t] += sq[t + o]; }
        __syncthreads();
    }
    if (t == 0) {
        float mean = ss[0] / NP;
        float var  = sq[0] / NP - mean * mean;
        st[str * 256 + c]       = mean;
        st[str * 256 + 128 + c] = rsqrtf(var + 1e-5f);
    }
}

__global__ void k_bn_apply(const float* __restrict__ conv, const float* __restrict__ st,
                           const float* __restrict__ gx, const float* __restrict__ bxp,
                           const float* __restrict__ gy, const float* __restrict__ byp,
                           const float* __restrict__ pe,
                           float* __restrict__ feat0, float* __restrict__ h) {
    size_t i = (size_t)blockIdx.x * 256 + threadIdx.x;
    int str = (int)(i / SZ_ND);
    size_t local = i - (size_t)str * SZ_ND;
    int c = (int)(i & 127);
    const float* g = str ? gy : gx;
    const float* b = str ? byp : bxp;
    const float* s = st + str * 256;
    float v = (conv[i] - s[c]) * s[128 + c] * g[c] + b[c];
    v = fmaxf(v, 0.0f);
    feat0[i] = v;
    h[i] = qtf32(v + pe[local]);
}

__global__ void k_ln(const float* __restrict__ a, const float* __restrict__ b,
                     const float* __restrict__ g, const float* __restrict__ beta,
                     float* __restrict__ out, int quant) {
    int r = blockIdx.x, t = threadIdx.x;
    float v = a[(size_t)r * DM + t] + b[(size_t)r * DM + t];
    float s = v, q = v * v;
#pragma unroll
    for (int o = 16; o > 0; o >>= 1) {
        s += __shfl_xor_sync(0xffffffffu, s, o);
        q += __shfl_xor_sync(0xffffffffu, q, o);
    }
    __shared__ float ws[4], wq[4];
    int w = t >> 5, lane = t & 31;
    if (lane == 0) { ws[w] = s; wq[w] = q; }
    __syncthreads();
    if (t == 0) {
        float S_ = ws[0] + ws[1] + ws[2] + ws[3];
        float Q_ = wq[0] + wq[1] + wq[2] + wq[3];
        float mean = S_ / 128.0f;
        float var  = Q_ / 128.0f - mean * mean;
        ws[0] = mean;
        wq[0] = rsqrtf(var + 1e-5f);
    }
    __syncthreads();
    float o = (v - ws[0]) * wq[0] * g[t] + beta[t];
    out[(size_t)r * DM + t] = quant ? qtf32(o) : o;
}

__global__ void k_combine(const float* __restrict__ x, const float* __restrict__ y,
                          const float* __restrict__ xf, const float* __restrict__ yf,
                          float* __restrict__ out) {
    int i = blockIdx.x * 256 + threadIdx.x;
    float z = xf[i] + yf[i];
    float s = 1.0f / (1.0f + expf(-z));
    out[i] = 2.0f * x[i] * s + 2.0f * y[i] * (1.0f - s);
}

// ---------------------------------------------------------------------------
// Launch
// ---------------------------------------------------------------------------
extern "C" void kernel_launch(void* const* d_in, const int* in_sizes, int n_in,
                              void* d_out, int out_size) {
    const float* x    = (const float*)d_in[0];
    const float* y    = (const float*)d_in[1];
    const float* pos  = (const float*)d_in[2];
    const int*   idx  = (const int*)d_in[3];
    const float* Wx   = (const float*)d_in[5];
    const float* bx   = (const float*)d_in[6];
    const float* bnxg = (const float*)d_in[7];
    const float* bnxb = (const float*)d_in[8];
    const float* Wy   = (const float*)d_in[9];
    const float* by   = (const float*)d_in[10];
    const float* bnyg = (const float*)d_in[11];
    const float* bnyb = (const float*)d_in[12];
    const float* Wq   = (const float*)d_in[13];
    const float* bq   = (const float*)d_in[14];
    const float* Wk   = (const float*)d_in[15];
    const float* bk   = (const float*)d_in[16];
    const float* Wv   = (const float*)d_in[17];
    const float* bv   = (const float*)d_in[18];
    const float* Wo   = (const float*)d_in[19];
    const float* bo   = (const float*)d_in[20];
    const float* ln1g = (const float*)d_in[21];
    const float* ln1b = (const float*)d_in[22];
    const float* W1   = (const float*)d_in[23];
    const float* b1   = (const float*)d_in[24];
    const float* W2   = (const float*)d_in[25];
    const float* b2   = (const float*)d_in[26];
    const float* ln2g = (const float*)d_in[27];
    const float* ln2b = (const float*)d_in[28];
    float* out = (float*)d_out;

    float* base = nullptr;
    cudaGetSymbolAddress((void**)&base, g_scratch);

    __half* Ah  = reinterpret_cast<__half*>(base + OFF_A);
    __half* fH  = reinterpret_cast<__half*>(base + OFF_FH);
    __half* WxT = reinterpret_cast<__half*>(base + OFF_WXT);
    __half* WyT = reinterpret_cast<__half*>(base + OFF_WYT);
    float* pe   = base + OFF_PE;
    float* conv = base + OFF_CONV;
    float* f0   = base + OFF_F0;
    float* h    = base + OFF_H;
    float* qkv  = base + OFF_QKV;
    float* o    = base + OFF_O;
    float* tmp  = base + OFF_T;
    float* f1   = base + OFF_F1;
    float* ff   = base + OFF_FF;
    float* fo   = base + OFF_OUT;
    float* part = base + OFF_PART;
    float* Wqkv = base + OFF_WQKV;
    float* bqkv = base + OFF_WQKV + 384 * 128;
    float* Woq  = base + OFF_WOQ;
    float* W1q  = base + OFF_W1Q;
    float* W2q  = base + OFF_W2Q;
    float* st   = base + OFF_ST;

    constexpr int SMEM_NT = 2 * (128 * 36 + 128 * 36) * 4;
    cudaFuncSetAttribute(k_mma<128, 128, 64, 32, 0, 0>,
                         cudaFuncAttributeMaxDynamicSharedMemorySize, SMEM_NT);
    cudaFuncSetAttribute(k_mma<128, 128, 64, 32, 0, 1>,
                         cudaFuncAttributeMaxDynamicSharedMemorySize, SMEM_NT);
    cudaFuncSetAttribute(k_mma<128, 128, 64, 32, 1, 1>,
                         cudaFuncAttributeMaxDynamicSharedMemorySize, SMEM_NT);
    cudaFuncSetAttribute(k_gemm_h,
                         cudaFuncAttributeMaxDynamicSharedMemorySize, GH_SMEM);
    cudaFuncSetAttribute(k_convA,
                         cudaFuncAttributeMaxDynamicSharedMemorySize, CONVA_SMEM);
    cudaFuncSetAttribute(k_flash,
                         cudaFuncAttributeMaxDynamicSharedMemorySize, FLASH_SMEM);

    const float alphaS = 0.17677669529663687f;           // 1/sqrt(32)
    const float alpha2 = alphaS * 1.4426950408889634f;   // * log2(e)

    k_prep<<<2048, 256>>>(x, y, Wo, W1, W2, Wq, Wk, Wv, bq, bk, bv, base);
    k_prepT<<<dim3(256, 4, 2), dim3(32, 8)>>>(Wx, Wy, base);
    k_pos_stats<<<1, 256>>>(pos, st + 512);
    k_posenc<<<NP, 64>>>(pos, st + 512, pe);
    k_convA<<<dim3(NP, 2), 256, CONVA_SMEM>>>(fH, pos, idx, Ah);

    // conv GEMMs (fp16): split-K=8 slices of 1024 halfs
    const __half* WT[2] = {WxT, WyT};
    for (int s = 0; s < 2; s++) {
        k_gemm_h<<<dim3(1, 32, 8), 256, GH_SMEM>>>(
            Ah + (size_t)s * SZ_A1, 8192, 1024,
            WT[s], 8192, 1024,
            part + (size_t)s * 8 * SZ_ND, 128, (long long)SZ_ND,
            NP, 1024);
    }
    k_reduce8<<<(2 * SZ_ND) / 256, 256>>>(part, bx, by, conv);
    k_bn_stats<<<dim3(128, 2), 256>>>(conv, st);
    k_bn_apply<<<(2 * SZ_ND) / 256, 256>>>(conv, st, bnxg, bnxb, bnyg, bnyb,
                                           pe, f0, h);

    k_mma<128, 128, 64, 32, 0, 1><<<dim3(3, 32, 2), 256, SMEM_NT>>>(
        h, 128, (long long)SZ_ND, Wqkv, 128, 0,
        qkv, 384, (long long)SZ_QKV, bqkv, NP, 384, 128, 1.0f);

    k_flash<<<dim3(32, 4, 2), 256, FLASH_SMEM>>>(qkv, o, alpha2);

    k_mma<128, 128, 64, 32, 0, 0><<<dim3(1, 32, 2), 256, SMEM_NT>>>(
        o, 128, (long long)SZ_ND, Woq, 128, 0,
        tmp, 128, (long long)SZ_ND, bo, NP, 128, 128, 1.0f);
    k_ln<<<2 * NP, 128>>>(f0, tmp, ln1g, ln1b, f1, 1);

    k_mma<128, 128, 64, 32, 1, 1><<<dim3(4, 32, 2), 256, SMEM_NT>>>(
        f1, 128, (long long)SZ_ND, W1q, 128, 0,
        ff, FFD, (long long)NP * FFD, b1, NP, FFD, 128, 1.0f);
    k_mma<128, 128, 64, 32, 0, 0><<<dim3(1, 32, 2), 256, SMEM_NT>>>(
        ff, FFD, (long long)NP * FFD, W2q, FFD, 0,
        tmp, 128, (long long)SZ_ND, b2, NP, 128, FFD, 1.0f);
    k_ln<<<2 * NP, 128>>>(f1, tmp, ln2g, ln2b, fo, 0);

    k_combine<<<(NP * DM) / 256, 256>>>(x, y, fo, fo + SZ_ND, out);
}

// round 17
// speedup vs baseline: 7.8907x; 1.2685x over previous
#include <cuda_runtime.h>
#include <cuda_fp16.h>
#include <math.h>
#include <stdint.h>

// ---------------------------------------------------------------------------
// Problem constants
// ---------------------------------------------------------------------------
#define NP 4096
#define KN 80
#define DM 128
#define FFD 512

static constexpr size_t SZ_ND  = (size_t)NP * DM;              // 524288
static constexpr size_t SZ_A1  = (size_t)NP * 8192;            // per-stream A (halfs)
static constexpr size_t SZ_QKV = (size_t)NP * 384;

static constexpr size_t OFF_A    = 0;                          // half[2*SZ_A1]
static constexpr size_t OFF_PE   = OFF_A + 2 * SZ_A1;
static constexpr size_t OFF_CONV = OFF_PE + SZ_ND;
static constexpr size_t OFF_F0   = OFF_CONV + 2 * SZ_ND;
static constexpr size_t OFF_H    = OFF_F0 + 2 * SZ_ND;         // half[2*SZ_ND] used
static constexpr size_t OFF_QKV  = OFF_H + 2 * SZ_ND;          // half[2*SZ_QKV] used
static constexpr size_t OFF_O    = OFF_QKV + 2 * SZ_QKV;
static constexpr size_t OFF_T    = OFF_O + 2 * SZ_ND;
static constexpr size_t OFF_F1   = OFF_T + 2 * SZ_ND;
static constexpr size_t OFF_FF   = OFF_F1 + 2 * SZ_ND;         // 2*NP*512
static constexpr size_t OFF_OUT  = OFF_FF + 2 * (size_t)NP * FFD;
static constexpr size_t OFF_PART = OFF_OUT + 2 * SZ_ND;        // 16 partials
static constexpr size_t OFF_WQKV = OFF_PART + 16 * SZ_ND;      // half[384*128] + f32 bias[384+pad]
static constexpr size_t OFF_WXT  = OFF_WQKV + 384 * 128 + 512;
static constexpr size_t OFF_WYT  = OFF_WXT + (size_t)8192 * 128;
static constexpr size_t OFF_WOQ  = OFF_WYT + (size_t)8192 * 128;
static constexpr size_t OFF_W1Q  = OFF_WOQ + 16384;
static constexpr size_t OFF_W2Q  = OFF_W1Q + 65536;
static constexpr size_t OFF_ST   = OFF_W2Q + 65536;
static constexpr size_t OFF_FH   = OFF_ST + 1024;              // half[2*SZ_ND]
static constexpr size_t SCRATCH_TOTAL = OFF_FH + 2 * SZ_ND / 2 + 256;

__device__ float g_scratch[SCRATCH_TOTAL];

// ---------------------------------------------------------------------------
// helpers
// ---------------------------------------------------------------------------
__device__ __forceinline__ uint32_t f2tf32(float x) {
    float r;
    asm("cvt.rna.tf32.f32 %0, %1;" : "=f"(r) : "f"(x));
    return __float_as_uint(r);
}
__device__ __forceinline__ float qtf32(float x) {
    return __uint_as_float(f2tf32(x));
}

__device__ __forceinline__ void mma_tf32(float c[4],
                                         uint32_t a0, uint32_t a1, uint32_t a2, uint32_t a3,
                                         uint32_t b0, uint32_t b1) {
    asm volatile(
        "mma.sync.aligned.m16n8k8.row.col.f32.tf32.tf32.f32 "
        "{%0,%1,%2,%3}, {%4,%5,%6,%7}, {%8,%9}, {%0,%1,%2,%3};\n"
        : "+f"(c[0]), "+f"(c[1]), "+f"(c[2]), "+f"(c[3])
        : "r"(a0), "r"(a1), "r"(a2), "r"(a3), "r"(b0), "r"(b1));
}

__device__ __forceinline__ void mma_f16(float c[4],
                                        uint32_t a0, uint32_t a1, uint32_t a2, uint32_t a3,
                                        uint32_t b0, uint32_t b1) {
    asm volatile(
        "mma.sync.aligned.m16n8k16.row.col.f32.f16.f16.f32 "
        "{%0,%1,%2,%3}, {%4,%5,%6,%7}, {%8,%9}, {%0,%1,%2,%3};\n"
        : "+f"(c[0]), "+f"(c[1]), "+f"(c[2]), "+f"(c[3])
        : "r"(a0), "r"(a1), "r"(a2), "r"(a3), "r"(b0), "r"(b1));
}

__device__ __forceinline__ void ldsm_x4(uint32_t& r0, uint32_t& r1,
                                        uint32_t& r2, uint32_t& r3, uint32_t saddr) {
    asm volatile(
        "ldmatrix.sync.aligned.m8n8.x4.shared.b16 {%0,%1,%2,%3}, [%4];\n"
        : "=r"(r0), "=r"(r1), "=r"(r2), "=r"(r3) : "r"(saddr));
}
__device__ __forceinline__ void ldsm_x4_t(uint32_t& r0, uint32_t& r1,
                                          uint32_t& r2, uint32_t& r3, uint32_t saddr) {
    asm volatile(
        "ldmatrix.sync.aligned.m8n8.x4.trans.shared.b16 {%0,%1,%2,%3}, [%4];\n"
        : "=r"(r0), "=r"(r1), "=r"(r2), "=r"(r3) : "r"(saddr));
}

__device__ __forceinline__ uint32_t pack_h2(float a, float b) {
    __half2 h = __floats2half2_rn(a, b);
    return *reinterpret_cast<uint32_t*>(&h);
}

__device__ __forceinline__ void cp16(uint32_t s, const void* g) {
    asm volatile("cp.async.ca.shared.global [%0], [%1], 16;\n" :: "r"(s), "l"(g));
}
__device__ __forceinline__ void cp_commit() {
    asm volatile("cp.async.commit_group;\n");
}
template <int N>
__device__ __forceinline__ void cp_wait() {
    asm volatile("cp.async.wait_group %0;\n" :: "n"(N));
}

// ---------------------------------------------------------------------------
// tf32 GEMM (TRANSB): cp.async double-buffered, ldmatrix A-frags (validated)
// ---------------------------------------------------------------------------
template <int BM, int BN, int WM, int WN, int ACT, int QUANT>
__global__ __launch_bounds__((BM / WM) * (BN / WN) * 32)
void k_mma(const float* __restrict__ A, int lda, long long strideA,
           const float* __restrict__ B, int ldb, long long strideB,
           float* __restrict__ C, int ldc, long long strideC,
           const float* __restrict__ bias,
           int M, int N, int K, float alpha) {
    constexpr int MI = WM / 16;
    constexpr int NI = WN / 8;
    constexpr int NWARP = (BM / WM) * (BN / WN);
    constexpr int NT = NWARP * 32;
    constexpr int LDA = 36;
    constexpr int LDB = 36;
    constexpr int SA = BM * LDA;
    constexpr int SB = BN * LDB;

    extern __shared__ uint32_t sm[];
    uint32_t* sBst[2] = {sm + SA, sm + SA + SB + SA};

    A += (size_t)blockIdx.z * strideA;
    B += (size_t)blockIdx.z * strideB;
    C += (size_t)blockIdx.z * strideC;

    const int n0 = blockIdx.x * BN;
    const int m0 = blockIdx.y * BM;
    const int tid = threadIdx.x;
    const int w = tid >> 5, lane = tid & 31;
    const int grp = lane >> 2, qid = lane & 3;
    const int wm = w % (BM / WM), wn = w / (BM / WM);

    const uint32_t smem_base = (uint32_t)__cvta_generic_to_shared(sm);
    const uint32_t aRowOff =
        (uint32_t)((wm * WM + (lane & 15)) * LDA + (lane >> 4) * 4);

    auto load_tile = [&](int st, int k0) {
        uint32_t aBase = smem_base + (uint32_t)(st * (SA + SB)) * 4u;
        uint32_t bBase = aBase + (uint32_t)SA * 4u;
#pragma unroll
        for (int i = tid; i < BM * 8; i += NT) {
            int r = i >> 3, c4 = (i & 7) * 4;
            cp16(aBase + (uint32_t)(r * LDA + c4) * 4u,
                 A + (size_t)(m0 + r) * lda + k0 + c4);
        }
#pragma unroll
        for (int i = tid; i < BN * 8; i += NT) {
            int r = i >> 3, c4 = (i & 7) * 4;
            cp16(bBase + (uint32_t)(r * LDB + c4) * 4u,
                 B + (size_t)(n0 + r) * ldb + k0 + c4);
        }
        cp_commit();
    };

    float acc[MI][NI][4];
#pragma unroll
    for (int i = 0; i < MI; i++)
#pragma unroll
        for (int j = 0; j < NI; j++)
#pragma unroll
            for (int q = 0; q < 4; q++) acc[i][j][q] = 0.0f;

    const int KT = K / 32;
    load_tile(0, 0);

    for (int kt = 0; kt < KT; kt++) {
        if (kt + 1 < KT) {
            load_tile((kt + 1) & 1, (kt + 1) * 32);
            cp_wait<1>();
        } else {
            cp_wait<0>();
        }
        __syncthreads();

        const uint32_t* sB = sBst[kt & 1];
        const uint32_t aStage =
            smem_base + (uint32_t)((kt & 1) * (SA + SB)) * 4u;

#pragma unroll
        for (int ks = 0; ks < 4; ks++) {
            const int kk = ks * 8;
            uint32_t af[MI][4], bf[NI][2];
#pragma unroll
            for (int mi = 0; mi < MI; mi++) {
                uint32_t saddr = aStage +
                    (aRowOff + (uint32_t)(mi * 16 * LDA + kk)) * 4u;
                ldsm_x4(af[mi][0], af[mi][1], af[mi][2], af[mi][3], saddr);
            }
#pragma unroll
            for (int ni = 0; ni < NI; ni++) {
                int c = wn * WN + ni * 8 + grp;
                bf[ni][0] = sB[c * LDB + kk + qid];
                bf[ni][1] = sB[c * LDB + kk + qid + 4];
            }
#pragma unroll
            for (int mi = 0; mi < MI; mi++)
#pragma unroll
                for (int ni = 0; ni < NI; ni++)
                    mma_tf32(acc[mi][ni], af[mi][0], af[mi][1], af[mi][2], af[mi][3],
                             bf[ni][0], bf[ni][1]);
        }
        __syncthreads();
    }

#pragma unroll
    for (int mi = 0; mi < MI; mi++) {
#pragma unroll
        for (int ni = 0; ni < NI; ni++) {
            int r = m0 + wm * WM + mi * 16 + grp;
            int c = n0 + wn * WN + ni * 8 + qid * 2;
            float b0 = 0.f, b1 = 0.f;
            if (bias) { b0 = bias[c]; b1 = bias[c + 1]; }
            float v0 = acc[mi][ni][0] * alpha + b0;
            float v1 = acc[mi][ni][1] * alpha + b1;
            float v2 = acc[mi][ni][2] * alpha + b0;
            float v3 = acc[mi][ni][3] * alpha + b1;
            if (ACT) {
                v0 = fmaxf(v0, 0.f); v1 = fmaxf(v1, 0.f);
                v2 = fmaxf(v2, 0.f); v3 = fmaxf(v3, 0.f);
            }
            if (QUANT) {
                v0 = qtf32(v0); v1 = qtf32(v1);
                v2 = qtf32(v2); v3 = qtf32(v3);
            }
            *reinterpret_cast<float2*>(C + (size_t)r * ldc + c) = make_float2(v0, v1);
            *reinterpret_cast<float2*>(C + (size_t)(r + 8) * ldc + c) = make_float2(v2, v3);
        }
    }
}

// ---------------------------------------------------------------------------
// fp16 GEMM for conv (validated): A[M][K]h, B=W^T[N=128][K]h, fp32 partials
// ---------------------------------------------------------------------------
static constexpr int GH_LDA = 40;
static constexpr int GH_SA  = 128 * GH_LDA;
static constexpr int GH_SMEM = 2 * (GH_SA + GH_SA) * 2;

__global__ __launch_bounds__(256)
void k_gemm_h(const __half* __restrict__ A, int lda, long long strideA,
              const __half* __restrict__ B, int ldb, long long strideB,
              float* __restrict__ C, int ldc, long long strideC,
              int M, int K) {
    extern __shared__ __half smh[];

    A += (size_t)blockIdx.z * strideA;
    B += (size_t)blockIdx.z * strideB;
    C += (size_t)blockIdx.z * strideC;

    const int m0 = blockIdx.y * 128;
    const int tid = threadIdx.x;
    const int w = tid >> 5, lane = tid & 31;
    const int grp = lane >> 2, qid = lane & 3;
    const int wm = w & 1, wn = w >> 1;

    const uint32_t smem_base = (uint32_t)__cvta_generic_to_shared(smh);
    const uint32_t aRowOff =
        (uint32_t)((wm * 64 + (lane & 15)) * GH_LDA + (lane >> 4) * 8);

    auto load_tile = [&](int st, int k0) {
        uint32_t aBase = smem_base + (uint32_t)(st * 2 * GH_SA) * 2u;
        uint32_t bBase = aBase + (uint32_t)GH_SA * 2u;
#pragma unroll
        for (int i = tid; i < 512; i += 256) {
            int r = i >> 2, c8 = (i & 3) * 8;
            cp16(aBase + (uint32_t)(r * GH_LDA + c8) * 2u,
                 A + (size_t)(m0 + r) * lda + k0 + c8);
        }
#pragma unroll
        for (int i = tid; i < 512; i += 256) {
            int r = i >> 2, c8 = (i & 3) * 8;
            cp16(bBase + (uint32_t)(r * GH_LDA + c8) * 2u,
                 B + (size_t)r * ldb + k0 + c8);
        }
        cp_commit();
    };

    float acc[4][4][4];
#pragma unroll
    for (int i = 0; i < 4; i++)
#pragma unroll
        for (int j = 0; j < 4; j++)
#pragma unroll
            for (int q = 0; q < 4; q++) acc[i][j][q] = 0.0f;

    const int KT = K / 32;
    load_tile(0, 0);

    for (int kt = 0; kt < KT; kt++) {
        if (kt + 1 < KT) {
            load_tile((kt + 1) & 1, (kt + 1) * 32);
            cp_wait<1>();
        } else {
            cp_wait<0>();
        }
        __syncthreads();

        const uint32_t aStage = smem_base + (uint32_t)((kt & 1) * 2 * GH_SA) * 2u;
        const __half* sB = smh + (kt & 1) * 2 * GH_SA + GH_SA;

#pragma unroll
        for (int ks = 0; ks < 2; ks++) {
            const int kk = ks * 16;
            uint32_t af[4][4], bf[4][2];
#pragma unroll
            for (int mi = 0; mi < 4; mi++) {
                uint32_t saddr = aStage +
                    (aRowOff + (uint32_t)(mi * 16 * GH_LDA + kk)) * 2u;
                ldsm_x4(af[mi][0], af[mi][1], af[mi][2], af[mi][3], saddr);
            }
#pragma unroll
            for (int ni = 0; ni < 4; ni++) {
                int c = wn * 32 + ni * 8 + grp;
                bf[ni][0] = *reinterpret_cast<const uint32_t*>(
                    sB + c * GH_LDA + kk + 2 * qid);
                bf[ni][1] = *reinterpret_cast<const uint32_t*>(
                    sB + c * GH_LDA + kk + 2 * qid + 8);
            }
#pragma unroll
            for (int mi = 0; mi < 4; mi++)
#pragma unroll
                for (int ni = 0; ni < 4; ni++)
                    mma_f16(acc[mi][ni], af[mi][0], af[mi][1], af[mi][2], af[mi][3],
                            bf[ni][0], bf[ni][1]);
        }
        __syncthreads();
    }

#pragma unroll
    for (int mi = 0; mi < 4; mi++) {
#pragma unroll
        for (int ni = 0; ni < 4; ni++) {
            int r = m0 + wm * 64 + mi * 16 + grp;
            int c = wn * 32 + ni * 8 + qid * 2;
            *reinterpret_cast<float2*>(C + (size_t)r * ldc + c) =
                make_float2(acc[mi][ni][0], acc[mi][ni][1]);
            *reinterpret_cast<float2*>(C + (size_t)(r + 8) * ldc + c) =
                make_float2(acc[mi][ni][2], acc[mi][ni][3]);
        }
    }
}

// ---------------------------------------------------------------------------
// fp16 QKV GEMM: A=hH [4096][128]h, B=WqkvH [384][128]h, bias f32, out half
// ---------------------------------------------------------------------------
__global__ __launch_bounds__(256)
void k_gh_qkv(const __half* __restrict__ A, long long strideA,
              const __half* __restrict__ B,
              __half* __restrict__ C, long long strideC,
              const float* __restrict__ bias) {
    extern __shared__ __half smh[];

    A += (size_t)blockIdx.z * strideA;
    C += (size_t)blockIdx.z * strideC;

    const int n0 = blockIdx.x * 128;
    const int m0 = blockIdx.y * 128;
    const int tid = threadIdx.x;
    const int w = tid >> 5, lane = tid & 31;
    const int grp = lane >> 2, qid = lane & 3;
    const int wm = w & 1, wn = w >> 1;

    const uint32_t smem_base = (uint32_t)__cvta_generic_to_shared(smh);
    const uint32_t aRowOff =
        (uint32_t)((wm * 64 + (lane & 15)) * GH_LDA + (lane >> 4) * 8);

    auto load_tile = [&](int st, int k0) {
        uint32_t aBase = smem_base + (uint32_t)(st * 2 * GH_SA) * 2u;
        uint32_t bBase = aBase + (uint32_t)GH_SA * 2u;
#pragma unroll
        for (int i = tid; i < 512; i += 256) {
            int r = i >> 2, c8 = (i & 3) * 8;
            cp16(aBase + (uint32_t)(r * GH_LDA + c8) * 2u,
                 A + (size_t)(m0 + r) * 128 + k0 + c8);
        }
#pragma unroll
        for (int i = tid; i < 512; i += 256) {
            int r = i >> 2, c8 = (i & 3) * 8;
            cp16(bBase + (uint32_t)(r * GH_LDA + c8) * 2u,
                 B + (size_t)(n0 + r) * 128 + k0 + c8);
        }
        cp_commit();
    };

    float acc[4][4][4];
#pragma unroll
    for (int i = 0; i < 4; i++)
#pragma unroll
        for (int j = 0; j < 4; j++)
#pragma unroll
            for (int q = 0; q < 4; q++) acc[i][j][q] = 0.0f;

    load_tile(0, 0);
    for (int kt = 0; kt < 4; kt++) {
        if (kt + 1 < 4) {
            load_tile((kt + 1) & 1, (kt + 1) * 32);
            cp_wait<1>();
        } else {
            cp_wait<0>();
        }
        __syncthreads();

        const uint32_t aStage = smem_base + (uint32_t)((kt & 1) * 2 * GH_SA) * 2u;
        const __half* sB = smh + (kt & 1) * 2 * GH_SA + GH_SA;

#pragma unroll
        for (int ks = 0; ks < 2; ks++) {
            const int kk = ks * 16;
            uint32_t af[4][4], bf[4][2];
#pragma unroll
            for (int mi = 0; mi < 4; mi++) {
                uint32_t saddr = aStage +
                    (aRowOff + (uint32_t)(mi * 16 * GH_LDA + kk)) * 2u;
                ldsm_x4(af[mi][0], af[mi][1], af[mi][2], af[mi][3], saddr);
            }
#pragma unroll
            for (int ni = 0; ni < 4; ni++) {
                int c = wn * 32 + ni * 8 + grp;
                bf[ni][0] = *reinterpret_cast<const uint32_t*>(
                    sB + c * GH_LDA + kk + 2 * qid);
                bf[ni][1] = *reinterpret_cast<const uint32_t*>(
                    sB + c * GH_LDA + kk + 2 * qid + 8);
            }
#pragma unroll
            for (int mi = 0; mi < 4; mi++)
#pragma unroll
                for (int ni = 0; ni < 4; ni++)
                    mma_f16(acc[mi][ni], af[mi][0], af[mi][1], af[mi][2], af[mi][3],
                            bf[ni][0], bf[ni][1]);
        }
        __syncthreads();
    }

#pragma unroll
    for (int mi = 0; mi < 4; mi++) {
#pragma unroll
        for (int ni = 0; ni < 4; ni++) {
            int r = m0 + wm * 64 + mi * 16 + grp;
            int c = n0 + wn * 32 + ni * 8 + qid * 2;
            float b0 = bias[c], b1 = bias[c + 1];
            *reinterpret_cast<uint32_t*>(C + (size_t)r * 384 + c) =
                pack_h2(acc[mi][ni][0] + b0, acc[mi][ni][1] + b1);
            *reinterpret_cast<uint32_t*>(C + (size_t)(r + 8) * 384 + c) =
                pack_h2(acc[mi][ni][2] + b0, acc[mi][ni][3] + b1);
        }
    }
}

// ---------------------------------------------------------------------------
// k_convA v6 (fp16, validated)
// ---------------------------------------------------------------------------
static constexpr int LDWH = 88;
static constexpr int LDCH = 136;
static constexpr int CONVA_SMEM = (64 * LDWH + KN * LDCH) * 2 + 256;

__global__ __launch_bounds__(256, 3)
void k_convA(const __half* __restrict__ fH,
             const float* __restrict__ pos, const int* __restrict__ idx,
             __half* __restrict__ Ah) {
    extern __shared__ __half dsmh[];
    __half* sWc = dsmh;
    __half* sF  = sWc + 64 * LDWH;

    const int n = blockIdx.x;
    const int s = blockIdx.y;
    const __half* feat = fH + (size_t)s * SZ_ND;
    const int tid = threadIdx.x;
    const int w = tid >> 5, lane = tid & 31;
    const int grp = lane >> 2, qid = lane & 3;

    const uint32_t smem_base = (uint32_t)__cvta_generic_to_shared(dsmh);
    const uint32_t sFbase = smem_base + (uint32_t)(64 * LDWH) * 2u;

#pragma unroll
    for (int t = tid; t < KN * 16; t += 256) {
        int row = t >> 4, chunk = t & 15;
        int nb = idx[n * KN + row];
        cp16(sFbase + (uint32_t)(row * LDCH + chunk * 8) * 2u,
             feat + (size_t)nb * DM + chunk * 8);
    }
    cp_commit();

    {
        uint4* z = reinterpret_cast<uint4*>(sWc);
        for (int i = tid; i < 64 * LDWH / 8; i += 256)
            z[i] = make_uint4(0u, 0u, 0u, 0u);
    }
    __syncthreads();

    if (tid < KN) {
        const float RAD  = 0.22499999403953552f * 0.5f;
        const float invR = 1.0f / RAD;
        float p0 = pos[3 * n], p1 = pos[3 * n + 1], p2 = pos[3 * n + 2];
        int nb = idx[n * KN + tid];
        if (nb != n) {
            float rx = (pos[3 * nb]     - p0) * invR;
            float ry = (pos[3 * nb + 1] - p1) * invR;
            float rz = (pos[3 * nb + 2] - p2) * invR;
            float r2 = rx * rx + ry * ry + rz * rz;
            float w1 = 1.0f - r2;
            float win = fminf(fmaxf(w1 * w1 * w1, 0.0f), 1.0f);
            if (win > 0.0f) {
                float nrm  = sqrtf(fmaxf(r2, 1e-12f));
                float linf = fmaxf(fmaxf(fabsf(rx), fabsf(ry)), fabsf(rz));
                linf = fmaxf(linf, 1e-9f);
                float sc = nrm / linf;
                float gx = fminf(fmaxf((rx * sc + 1.0f) * 1.5f, 0.0f), 3.0f);
                float gy = fminf(fmaxf((ry * sc + 1.0f) * 1.5f, 0.0f), 3.0f);
                float gz = fminf(fmaxf((rz * sc + 1.0f) * 1.5f, 0.0f), 3.0f);
                float f0x = fminf(floorf(gx), 2.0f);
                float f0y = fminf(floorf(gy), 2.0f);
                float f0z = fminf(floorf(gz), 2.0f);
                float tx = gx - f0x, ty = gy - f0y, tz = gz - f0z;
                int base = (int)f0x * 16 + (int)f0y * 4 + (int)f0z;
                float wx[2] = {1.0f - tx, tx};
                float wy[2] = {1.0f - ty, ty};
                float wz[2] = {1.0f - tz, tz};
#pragma unroll
                for (int dx = 0; dx < 2; dx++)
#pragma unroll
                    for (int dy = 0; dy < 2; dy++)
#pragma unroll
                        for (int dz = 0; dz < 2; dz++) {
                            int cell = base + dx * 16 + dy * 4 + dz;
                            sWc[cell * LDWH + tid] =
                                __float2half_rn(win * wx[dx] * wy[dy] * wz[dz]);
                        }
            }
        }
    }
    cp_wait<0>();
    __syncthreads();

    const int wm = w & 1, wn = w >> 1;
    const uint32_t aRowOff =
        (uint32_t)((wm * 32 + (lane & 15)) * LDWH + (lane >> 4) * 8);
    const uint32_t bRowOff =
        (uint32_t)((lane & 15) * LDCH + (lane >> 4) * 8);
    float acc[2][4][4];
#pragma unroll
    for (int mi = 0; mi < 2; mi++)
#pragma unroll
        for (int ni = 0; ni < 4; ni++)
#pragma unroll
            for (int q = 0; q < 4; q++) acc[mi][ni][q] = 0.0f;

#pragma unroll
    for (int ks = 0; ks < 5; ks++) {
        const int kk = ks * 16;
        uint32_t af[2][4], bf[4][2];
#pragma unroll
        for (int mi = 0; mi < 2; mi++) {
            uint32_t saddr = smem_base +
                (aRowOff + (uint32_t)(mi * 16 * LDWH + kk)) * 2u;
            ldsm_x4(af[mi][0], af[mi][1], af[mi][2], af[mi][3], saddr);
        }
#pragma unroll
        for (int p = 0; p < 2; p++) {
            uint32_t saddr = sFbase +
                (bRowOff + (uint32_t)(kk * LDCH + wn * 32 + p * 16)) * 2u;
            ldsm_x4_t(bf[2 * p][0], bf[2 * p][1], bf[2 * p + 1][0], bf[2 * p + 1][1],
                      saddr);
        }
#pragma unroll
        for (int mi = 0; mi < 2; mi++)
#pragma unroll
            for (int ni = 0; ni < 4; ni++)
                mma_f16(acc[mi][ni], af[mi][0], af[mi][1], af[mi][2], af[mi][3],
                        bf[ni][0], bf[ni][1]);
    }

    __half* Aout = Ah + (size_t)s * SZ_A1 + (size_t)n * 8192;
#pragma unroll
    for (int mi = 0; mi < 2; mi++) {
#pragma unroll
        for (int ni = 0; ni < 4; ni++) {
            int g = wm * 32 + mi * 16 + grp;
            int c = wn * 32 + ni * 8 + qid * 2;
            *reinterpret_cast<__half2*>(Aout + (size_t)g * 128 + c) =
                __floats2half2_rn(acc[mi][ni][0], acc[mi][ni][1]);
            *reinterpret_cast<__half2*>(Aout + (size_t)(g + 8) * 128 + c) =
                __floats2half2_rn(acc[mi][ni][2], acc[mi][ni][3]);
        }
    }
}

// ---------------------------------------------------------------------------
// Flash attention v4 (fp16): S accum layout == PV A-frag layout (no shuffles)
// smem: sQ/sK/sV [128][40]h = 30 KB
// ---------------------------------------------------------------------------
static constexpr int FL_LD = 40;
static constexpr int FLASH_SMEM = 3 * 128 * FL_LD * 2;

__global__ __launch_bounds__(256, 2)
void k_flash(const __half* __restrict__ qkvH, float* __restrict__ obuf,
             float alpha2) {
    extern __shared__ __half smfh[];
    __half* sQ = smfh;
    __half* sK = sQ + 128 * FL_LD;
    __half* sV = sK + 128 * FL_LD;

    const int qb = blockIdx.x, head = blockIdx.y, str = blockIdx.z;
    const __half* Qg = qkvH + (size_t)str * SZ_QKV + head * 32;
    const __half* Kg = Qg + 128;
    const __half* Vg = Qg + 256;

    const int tid = threadIdx.x;
    const int w = tid >> 5, lane = tid & 31;
    const int grp = lane >> 2, qid = lane & 3;
    const unsigned FULL = 0xffffffffu;

    const uint32_t smem_base = (uint32_t)__cvta_generic_to_shared(smfh);
    const uint32_t sVbase = smem_base + (uint32_t)(2 * 128 * FL_LD) * 2u;

    // Q tile, scaled by alpha2 (fp32 mul, fp16 store)
    for (int t = tid; t < 512; t += 256) {
        int r = t >> 2, c8 = (t & 3) * 8;
        uint4 v = *reinterpret_cast<const uint4*>(
            Qg + (size_t)(qb * 128 + r) * 384 + c8);
        const __half2* hp = reinterpret_cast<const __half2*>(&v);
        __half2* dst = reinterpret_cast<__half2*>(sQ + r * FL_LD + c8);
#pragma unroll
        for (int j = 0; j < 4; j++) {
            float2 f = __half22float2(hp[j]);
            dst[j] = __floats2half2_rn(f.x * alpha2, f.y * alpha2);
        }
    }

    float acc[4][4];
#pragma unroll
    for (int ni = 0; ni < 4; ni++)
#pragma unroll
        for (int q = 0; q < 4; q++) acc[ni][q] = 0.0f;
    float m0 = -1e30f, m1 = -1e30f, l0 = 0.0f, l1 = 0.0f;

    const uint32_t qRowOff =
        (uint32_t)((w * 16 + (lane & 15)) * FL_LD + (lane >> 4) * 8);
    const uint32_t vRowOff =
        (uint32_t)((lane & 15) * FL_LD + (lane >> 4) * 8);

    for (int kt = 0; kt < 32; kt++) {
        __syncthreads();
        for (int t = tid; t < 512; t += 256) {
            int r = t >> 2, c8 = (t & 3) * 8;
            *reinterpret_cast<uint4*>(sK + r * FL_LD + c8) =
                *reinterpret_cast<const uint4*>(
                    Kg + (size_t)(kt * 128 + r) * 384 + c8);
            *reinterpret_cast<uint4*>(sV + r * FL_LD + c8) =
                *reinterpret_cast<const uint4*>(
                    Vg + (size_t)(kt * 128 + r) * 384 + c8);
        }
        __syncthreads();

        // ---- S = Q K^T (K=32, 2 k16 steps) ----
        float s[16][4];
#pragma unroll
        for (int ni = 0; ni < 16; ni++)
#pragma unroll
            for (int q = 0; q < 4; q++) s[ni][q] = 0.0f;

#pragma unroll
        for (int ks = 0; ks < 2; ks++) {
            const int kk = ks * 16;
            uint32_t a0, a1, a2, a3;
            ldsm_x4(a0, a1, a2, a3, smem_base + (qRowOff + (uint32_t)kk) * 2u);
#pragma unroll
            for (int ni = 0; ni < 16; ni++) {
                int key = ni * 8 + grp;
                uint32_t b0 = *reinterpret_cast<const uint32_t*>(
                    sK + key * FL_LD + kk + 2 * qid);
                uint32_t b1 = *reinterpret_cast<const uint32_t*>(
                    sK + key * FL_LD + kk + 2 * qid + 8);
                mma_f16(s[ni], a0, a1, a2, a3, b0, b1);
            }
        }

        // ---- online softmax (log2 domain) ----
        float rm0 = -1e30f, rm1 = -1e30f;
#pragma unroll
        for (int ni = 0; ni < 16; ni++) {
            rm0 = fmaxf(rm0, fmaxf(s[ni][0], s[ni][1]));
            rm1 = fmaxf(rm1, fmaxf(s[ni][2], s[ni][3]));
        }
        rm0 = fmaxf(rm0, __shfl_xor_sync(FULL, rm0, 1));
        rm0 = fmaxf(rm0, __shfl_xor_sync(FULL, rm0, 2));
        rm1 = fmaxf(rm1, __shfl_xor_sync(FULL, rm1, 1));
        rm1 = fmaxf(rm1, __shfl_xor_sync(FULL, rm1, 2));

        float mn0 = fmaxf(m0, rm0), mn1 = fmaxf(m1, rm1);
        float c0 = exp2f(m0 - mn0), c1 = exp2f(m1 - mn1);
        float rs0 = 0.0f, rs1 = 0.0f;
#pragma unroll
        for (int ni = 0; ni < 16; ni++) {
            float p00 = exp2f(s[ni][0] - mn0);
            float p01 = exp2f(s[ni][1] - mn0);
            float p10 = exp2f(s[ni][2] - mn1);
            float p11 = exp2f(s[ni][3] - mn1);
            rs0 += p00 + p01;
            rs1 += p10 + p11;
            s[ni][0] = p00; s[ni][1] = p01;
            s[ni][2] = p10; s[ni][3] = p11;
        }
        rs0 += __shfl_xor_sync(FULL, rs0, 1);
        rs0 += __shfl_xor_sync(FULL, rs0, 2);
        rs1 += __shfl_xor_sync(FULL, rs1, 1);
        rs1 += __shfl_xor_sync(FULL, rs1, 2);

        l0 = l0 * c0 + rs0;
        l1 = l1 * c1 + rs1;
        m0 = mn0; m1 = mn1;
#pragma unroll
        for (int ni = 0; ni < 4; ni++) {
            acc[ni][0] *= c0; acc[ni][1] *= c0;
            acc[ni][2] *= c1; acc[ni][3] *= c1;
        }

        // ---- O += P V: S-accum packs directly into fp16 A-frags ----
#pragma unroll
        for (int ks = 0; ks < 8; ks++) {
            uint32_t a0 = pack_h2(s[2 * ks][0], s[2 * ks][1]);
            uint32_t a1 = pack_h2(s[2 * ks][2], s[2 * ks][3]);
            uint32_t a2 = pack_h2(s[2 * ks + 1][0], s[2 * ks + 1][1]);
            uint32_t a3 = pack_h2(s[2 * ks + 1][2], s[2 * ks + 1][3]);
            const int kk = ks * 16;
            uint32_t bf[4][2];
#pragma unroll
            for (int p = 0; p < 2; p++) {
                uint32_t saddr = sVbase +
                    (vRowOff + (uint32_t)(kk * FL_LD + p * 16)) * 2u;
                ldsm_x4_t(bf[2 * p][0], bf[2 * p][1],
                          bf[2 * p + 1][0], bf[2 * p + 1][1], saddr);
            }
#pragma unroll
            for (int ni = 0; ni < 4; ni++)
                mma_f16(acc[ni], a0, a1, a2, a3, bf[ni][0], bf[ni][1]);
        }
    }

    float i0 = 1.0f / l0, i1 = 1.0f / l1;
    float* O = obuf + (size_t)str * SZ_ND;
    int r0 = qb * 128 + w * 16 + grp;
#pragma unroll
    for (int ni = 0; ni < 4; ni++) {
        int col = head * 32 + ni * 8 + qid * 2;
        *reinterpret_cast<float2*>(O + (size_t)r0 * DM + col) =
            make_float2(qtf32(acc[ni][0] * i0), qtf32(acc[ni][1] * i0));
        *reinterpret_cast<float2*>(O + (size_t)(r0 + 8) * DM + col) =
            make_float2(qtf32(acc[ni][2] * i1), qtf32(acc[ni][3] * i1));
    }
}

// ---------------------------------------------------------------------------
// prep: feats -> fp16; Wqkv -> fp16; Wo/W1/W2 -> tf32; biases
// ---------------------------------------------------------------------------
__global__ void k_prep(const float* __restrict__ x, const float* __restrict__ y,
                       const float* __restrict__ Wo, const float* __restrict__ W1,
                       const float* __restrict__ W2,
                       const float* __restrict__ Wq, const float* __restrict__ Wk,
                       const float* __restrict__ Wv, const float* __restrict__ bq,
                       const float* __restrict__ bk, const float* __restrict__ bv,
                       float* __restrict__ base) {
    __half* fH = reinterpret_cast<__half*>(base + OFF_FH);
    __half* WqkvH = reinterpret_cast<__half*>(base + OFF_WQKV);
    const size_t NF = SZ_ND;
    size_t i = (size_t)blockIdx.x * 256 + threadIdx.x;
    size_t total = 2 * NF + 16384 + 65536 + 65536 + 49152 + 384;
    for (; i < total; i += (size_t)gridDim.x * 256) {
        size_t j = i;
        if (j < NF) { fH[j] = __float2half_rn(x[j]); continue; }
        j -= NF;
        if (j < NF) { fH[NF + j] = __float2half_rn(y[j]); continue; }
        j -= NF;
        if (j < 16384) { base[OFF_WOQ + j] = qtf32(Wo[j]); continue; }
        j -= 16384;
        if (j < 65536) { base[OFF_W1Q + j] = qtf32(W1[j]); continue; }
        j -= 65536;
        if (j < 65536) { base[OFF_W2Q + j] = qtf32(W2[j]); continue; }
        j -= 65536;
        if (j < 49152) {
            float v = (j < 16384) ? Wq[j] : (j < 32768) ? Wk[j - 16384]
                                                        : Wv[j - 32768];
            WqkvH[j] = __float2half_rn(v);
            continue;
        }
        j -= 49152;
        float bvv = (j < 128) ? bq[j] : (j < 256) ? bk[j - 128] : bv[j - 256];
        base[OFF_WQKV + 384 * 128 / 2 + 64 + j] = bvv;  // after half region (pad)
    }
}

// transpose-convert Wx/Wy [8192][128] f32 -> WT [128][8192] fp16
__global__ void k_prepT(const float* __restrict__ Wx, const float* __restrict__ Wy,
                        float* __restrict__ base) {
    __shared__ float t[32][33];
    const float* W = blockIdx.z ? Wy : Wx;
    __half* WT = reinterpret_cast<__half*>(base + (blockIdx.z ? OFF_WYT : OFF_WXT));
    int k0 = blockIdx.x * 32, o0 = blockIdx.y * 32;
    int tx = threadIdx.x, ty = threadIdx.y;
    for (int i = ty; i < 32; i += 8)
        t[i][tx] = W[(size_t)(k0 + i) * 128 + o0 + tx];
    __syncthreads();
    for (int i = ty; i < 32; i += 8)
        WT[(size_t)(o0 + i) * 8192 + k0 + tx] = __float2half_rn(t[tx][i]);
}

// ---------------------------------------------------------------------------
// small kernels
// ---------------------------------------------------------------------------
__global__ void k_pos_stats(const float* __restrict__ pos, float* __restrict__ st) {
    __shared__ double ss[256], sq[256];
    int t = threadIdx.x;
    double a = 0.0, b = 0.0;
    for (int i = t; i < NP; i += 256) {
        double v = (double)pos[3 * i];
        a += v; b += v * v;
    }
    ss[t] = a; sq[t] = b;
    __syncthreads();
    for (int o = 128; o > 0; o >>= 1) {
        if (t < o) { ss[t] += ss[t + o]; sq[t] += sq[t + o]; }
        __syncthreads();
    }
    if (t == 0) {
        double mean = ss[0] / NP;
        double var  = (sq[0] - ss[0] * ss[0] / NP) / (NP - 1);
        st[0] = (float)mean;
        st[1] = (float)(1.0 / (sqrt(var) + 1e-8));
    }
}

__global__ void k_posenc(const float* __restrict__ pos, const float* __restrict__ st,
                         float* __restrict__ pe) {
    int n = blockIdx.x;
    int j = threadIdx.x;
    float px  = (pos[3 * n] - st[0]) * st[1];
    float dv  = expf((float)(2 * j) * (-9.210340371976184f / 128.0f));
    float ang = px * dv;
    float s, c;
    sincosf(ang, &s, &c);
    pe[(size_t)n * DM + 2 * j]     = s;
    pe[(size_t)n * DM + 2 * j + 1] = c;
}

__global__ void k_reduce8(const float* __restrict__ part, const float* __restrict__ bx,
                          const float* __restrict__ by, float* __restrict__ out) {
    size_t i = (size_t)blockIdx.x * 256 + threadIdx.x;
    int str = (int)(i / SZ_ND);
    const float* p = part + (size_t)str * 8 * SZ_ND + (i - (size_t)str * SZ_ND);
    float v = 0.0f;
#pragma unroll
    for (int j = 0; j < 8; j++) v += p[j * SZ_ND];
    const float* bias = str ? by : bx;
    out[i] = v + bias[i & 127];
}

__global__ void k_bn_stats(const float* __restrict__ h, float* __restrict__ st) {
    __shared__ float ss[256], sq[256];
    int c = blockIdx.x, str = blockIdx.y, t = threadIdx.x;
    const float* hs = h + (size_t)str * SZ_ND;
    float a = 0.f, b = 0.f;
    for (int n = t; n < NP; n += 256) {
        float v = hs[(size_t)n * DM + c];
        a += v; b += v * v;
    }
    ss[t] = a; sq[t] = b;
    __syncthreads();
    for (int o = 128; o > 0; o >>= 1) {
        if (t < o) { ss[t] += ss[t + o]; sq[t] += sq[t + o]; }
        __syncthreads();
    }
    if (t == 0) {
        float mean = ss[0] / NP;
        float var  = sq[0] / NP - mean * mean;
        st[str * 256 + c]       = mean;
        st[str * 256 + 128 + c] = rsqrtf(var + 1e-5f);
    }
}

__global__ void k_bn_apply(const float* __restrict__ conv, const float* __restrict__ st,
                           const float* __restrict__ gx, const float* __restrict__ bxp,
                           const float* __restrict__ gy, const float* __restrict__ byp,
                           const float* __restrict__ pe,
                           float* __restrict__ feat0, __half* __restrict__ hH) {
    size_t i = (size_t)blockIdx.x * 256 + threadIdx.x;
    int str = (int)(i / SZ_ND);
    size_t local = i - (size_t)str * SZ_ND;
    int c = (int)(i & 127);
    const float* g = str ? gy : gx;
    const float* b = str ? byp : bxp;
    const float* s = st + str * 256;
    float v = (conv[i] - s[c]) * s[128 + c] * g[c] + b[c];
    v = fmaxf(v, 0.0f);
    feat0[i] = v;
    hH[i] = __float2half_rn(v + pe[local]);
}

__global__ void k_ln(const float* __restrict__ a, const float* __restrict__ b,
                     const float* __restrict__ g, const float* __restrict__ beta,
                     float* __restrict__ out, int quant) {
    int r = blockIdx.x, t = threadIdx.x;
    float v = a[(size_t)r * DM + t] + b[(size_t)r * DM + t];
    float s = v, q = v * v;
#pragma unroll
    for (int o = 16; o > 0; o >>= 1) {
        s += __shfl_xor_sync(0xffffffffu, s, o);
        q += __shfl_xor_sync(0xffffffffu, q, o);
    }
    __shared__ float ws[4], wq[4];
    int w = t >> 5, lane = t & 31;
    if (lane == 0) { ws[w] = s; wq[w] = q; }
    __syncthreads();
    if (t == 0) {
        float S_ = ws[0] + ws[1] + ws[2] + ws[3];
        float Q_ = wq[0] + wq[1] + wq[2] + wq[3];
        float mean = S_ / 128.0f;
        float var  = Q_ / 128.0f - mean * mean;
        ws[0] = mean;
        wq[0] = rsqrtf(var + 1e-5f);
    }
    __syncthreads();
    float o = (v - ws[0]) * wq[0] * g[t] + beta[t];
    out[(size_t)r * DM + t] = quant ? qtf32(o) : o;
}

__global__ void k_combine(const float* __restrict__ x, const float* __restrict__ y,
                          const float* __restrict__ xf, const float* __restrict__ yf,
                          float* __restrict__ out) {
    int i = blockIdx.x * 256 + threadIdx.x;
    float z = xf[i] + yf[i];
    float s = 1.0f / (1.0f + expf(-z));
    out[i] = 2.0f * x[i] * s + 2.0f * y[i] * (1.0f - s);
}

// ---------------------------------------------------------------------------
// Launch
// ---------------------------------------------------------------------------
extern "C" void kernel_launch(void* const* d_in, const int* in_sizes, int n_in,
                              void* d_out, int out_size) {
    const float* x    = (const float*)d_in[0];
    const float* y    = (const float*)d_in[1];
    const float* pos  = (const float*)d_in[2];
    const int*   idx  = (const int*)d_in[3];
    const float* Wx   = (const float*)d_in[5];
    const float* bx   = (const float*)d_in[6];
    const float* bnxg = (const float*)d_in[7];
    const float* bnxb = (const float*)d_in[8];
    const float* Wy   = (const float*)d_in[9];
    const float* by   = (const float*)d_in[10];
    const float* bnyg = (const float*)d_in[11];
    const float* bnyb = (const float*)d_in[12];
    const float* Wq   = (const float*)d_in[13];
    const float* bq   = (const float*)d_in[14];
    const float* Wk   = (const float*)d_in[15];
    const float* bk   = (const float*)d_in[16];
    const float* Wv   = (const float*)d_in[17];
    const float* bv   = (const float*)d_in[18];
    const float* Wo   = (const float*)d_in[19];
    const float* bo   = (const float*)d_in[20];
    const float* ln1g = (const float*)d_in[21];
    const float* ln1b = (const float*)d_in[22];
    const float* W1   = (const float*)d_in[23];
    const float* b1   = (const float*)d_in[24];
    const float* W2   = (const float*)d_in[25];
    const float* b2   = (const float*)d_in[26];
    const float* ln2g = (const float*)d_in[27];
    const float* ln2b = (const float*)d_in[28];
    float* out = (float*)d_out;

    float* base = nullptr;
    cudaGetSymbolAddress((void**)&base, g_scratch);

    __half* Ah    = reinterpret_cast<__half*>(base + OFF_A);
    __half* fH    = reinterpret_cast<__half*>(base + OFF_FH);
    __half* hH    = reinterpret_cast<__half*>(base + OFF_H);
    __half* qkvH  = reinterpret_cast<__half*>(base + OFF_QKV);
    __half* WxT   = reinterpret_cast<__half*>(base + OFF_WXT);
    __half* WyT   = reinterpret_cast<__half*>(base + OFF_WYT);
    __half* WqkvH = reinterpret_cast<__half*>(base + OFF_WQKV);
    float* bqkv = base + OFF_WQKV + 384 * 128 / 2 + 64;
    float* pe   = base + OFF_PE;
    float* conv = base + OFF_CONV;
    float* f0   = base + OFF_F0;
    float* o    = base + OFF_O;
    float* tmp  = base + OFF_T;
    float* f1   = base + OFF_F1;
    float* ff   = base + OFF_FF;
    float* fo   = base + OFF_OUT;
    float* part = base + OFF_PART;
    float* Woq  = base + OFF_WOQ;
    float* W1q  = base + OFF_W1Q;
    float* W2q  = base + OFF_W2Q;
    float* st   = base + OFF_ST;

    constexpr int SMEM_NT = 2 * (128 * 36 + 128 * 36) * 4;
    cudaFuncSetAttribute(k_mma<128, 128, 64, 32, 0, 0>,
                         cudaFuncAttributeMaxDynamicSharedMemorySize, SMEM_NT);
    cudaFuncSetAttribute(k_mma<128, 128, 64, 32, 1, 1>,
                         cudaFuncAttributeMaxDynamicSharedMemorySize, SMEM_NT);
    cudaFuncSetAttribute(k_gemm_h,
                         cudaFuncAttributeMaxDynamicSharedMemorySize, GH_SMEM);
    cudaFuncSetAttribute(k_gh_qkv,
                         cudaFuncAttributeMaxDynamicSharedMemorySize, GH_SMEM);
    cudaFuncSetAttribute(k_convA,
                         cudaFuncAttributeMaxDynamicSharedMemorySize, CONVA_SMEM);
    cudaFuncSetAttribute(k_flash,
                         cudaFuncAttributeMaxDynamicSharedMemorySize, FLASH_SMEM);

    const float alphaS = 0.17677669529663687f;           // 1/sqrt(32)
    const float alpha2 = alphaS * 1.4426950408889634f;   // * log2(e)

    k_prep<<<2048, 256>>>(x, y, Wo, W1, W2, Wq, Wk, Wv, bq, bk, bv, base);
    k_prepT<<<dim3(256, 4, 2), dim3(32, 8)>>>(Wx, Wy, base);
    k_pos_stats<<<1, 256>>>(pos, st + 512);
    k_posenc<<<NP, 64>>>(pos, st + 512, pe);
    k_convA<<<dim3(NP, 2), 256, CONVA_SMEM>>>(fH, pos, idx, Ah);

    const __half* WT[2] = {WxT, WyT};
    for (int s = 0; s < 2; s++) {
        k_gemm_h<<<dim3(1, 32, 8), 256, GH_SMEM>>>(
            Ah + (size_t)s * SZ_A1, 8192, 1024,
            WT[s], 8192, 1024,
            part + (size_t)s * 8 * SZ_ND, 128, (long long)SZ_ND,
            NP, 1024);
    }
    k_reduce8<<<(2 * SZ_ND) / 256, 256>>>(part, bx, by, conv);
    k_bn_stats<<<dim3(128, 2), 256>>>(conv, st);
    k_bn_apply<<<(2 * SZ_ND) / 256, 256>>>(conv, st, bnxg, bnxb, bnyg, bnyb,
                                           pe, f0, hH);

    // fused QKV (fp16 in/out), both streams
    k_gh_qkv<<<dim3(3, 32, 2), 256, GH_SMEM>>>(
        hH, (long long)SZ_ND, WqkvH, qkvH, (long long)SZ_QKV, bqkv);

    // flash attention (fp16)
    k_flash<<<dim3(32, 4, 2), 256, FLASH_SMEM>>>(qkvH, o, alpha2);

    k_mma<128, 128, 64, 32, 0, 0><<<dim3(1, 32, 2), 256, SMEM_NT>>>(
        o, 128, (long long)SZ_ND, Woq, 128, 0,
        tmp, 128, (long long)SZ_ND, bo, NP, 128, 128, 1.0f);
    k_ln<<<2 * NP, 128>>>(f0, tmp, ln1g, ln1b, f1, 1);

    k_mma<128, 128, 64, 32, 1, 1><<<dim3(4, 32, 2), 256, SMEM_NT>>>(
        f1, 128, (long long)SZ_ND, W1q, 128, 0,
        ff, FFD, (long long)NP * FFD, b1, NP, FFD, 128, 1.0f);
    k_mma<128, 128, 64, 32, 0, 0><<<dim3(1, 32, 2), 256, SMEM_NT>>>(
        ff, FFD, (long long)NP * FFD, W2q, FFD, 0,
        tmp, 128, (long long)SZ_ND, b2, NP, 128, FFD, 1.0f);
    k_ln<<<2 * NP, 128>>>(f1, tmp, ln2g, ln2b, fo, 0);

    k_combine<<<(NP * DM) / 256, 256>>>(x, y, fo, fo + SZ_ND, out);
}